// round 12
// baseline (speedup 1.0000x reference)
#include <cuda_runtime.h>
#include <cuda_bf16.h>
#include <cuda_fp16.h>
#include <math.h>

#define Bt 16
#define LT 1024
#define LA 2048
#define Dm 256
#define Rr 64
#define NE 3
#define ROWS_T (Bt*LT)   // 16384
#define ROWS_A (Bt*LA)   // 32768

// ---------------- scratch ----------------
__device__ float2 g_stats[ROWS_T + ROWS_A];
__device__ float g_Tp [(size_t)ROWS_T*Dm];
__device__ float g_Ap [(size_t)ROWS_A*Dm];
__device__ __nv_bfloat16 g_Tn [(size_t)ROWS_T*Dm];
__device__ __nv_bfloat16 g_An [(size_t)ROWS_A*Dm];
__device__ __nv_bfloat16 g_ApT[(size_t)Bt*Dm*LA];
__device__ __half g_logK[(size_t)Bt*LT*LA];
__device__ float g_lu[ROWS_T];
__device__ float g_lv[ROWS_A];
__device__ float g_S[ROWS_T];
__device__ float g_resid[(size_t)ROWS_T*Dm];
__device__ float g_h1[(size_t)ROWS_T*Dm];
__device__ float g_G[ROWS_T*NE];
__device__ float g_h [(size_t)ROWS_T*NE*Rr];
__device__ float g_h2[(size_t)ROWS_T*NE*Rr];
__device__ __nv_bfloat16 g_u [(size_t)NE*ROWS_T*Dm];

// ---------------- helpers ----------------
__device__ __forceinline__ float geluf(float x){
    return 0.5f*x*(1.0f+erff(x*0.7071067811865476f));
}
__device__ __forceinline__ float warpReduceSum(float v){
    #pragma unroll
    for(int o=16;o;o>>=1) v += __shfl_xor_sync(0xffffffffu, v, o);
    return v;
}
__device__ __forceinline__ float warpReduceMax(float v){
    #pragma unroll
    for(int o=16;o;o>>=1) v = fmaxf(v, __shfl_xor_sync(0xffffffffu, v, o));
    return v;
}
__device__ __forceinline__ float blockReduceSum256(float v){
    __shared__ float sh[8];
    int ln = threadIdx.x & 31, w = threadIdx.x >> 5;
    v = warpReduceSum(v);
    __syncthreads();
    if (ln==0) sh[w]=v;
    __syncthreads();
    float t = 0.f;
    #pragma unroll
    for (int i=0;i<8;i++) t += sh[i];
    return t;
}
__device__ __forceinline__ float blockReduceMax256(float v){
    __shared__ float shm[8];
    int ln = threadIdx.x & 31, w = threadIdx.x >> 5;
    v = warpReduceMax(v);
    __syncthreads();
    if (ln==0) shm[w]=v;
    __syncthreads();
    float t = -INFINITY;
    #pragma unroll
    for (int i=0;i<8;i++) t = fmaxf(t, shm[i]);
    return t;
}
__device__ __forceinline__ float clip_nan(float l){
    if (isnan(l)) return 0.f;
    return fminf(fmaxf(l, -1e9f), 1e9f);
}

__device__ __forceinline__ void mma_bf16(float* c, const unsigned* a, const unsigned* b){
    asm volatile("mma.sync.aligned.m16n8k16.row.col.f32.bf16.bf16.f32 "
        "{%0,%1,%2,%3}, {%4,%5,%6,%7}, {%8,%9}, {%0,%1,%2,%3};"
        : "+f"(c[0]), "+f"(c[1]), "+f"(c[2]), "+f"(c[3])
        : "r"(a[0]), "r"(a[1]), "r"(a[2]), "r"(a[3]), "r"(b[0]), "r"(b[1]));
}
__device__ __forceinline__ void mma_tf32(float* c, const unsigned* a, const unsigned* b){
    asm volatile("mma.sync.aligned.m16n8k8.row.col.f32.tf32.tf32.f32 "
        "{%0,%1,%2,%3}, {%4,%5,%6,%7}, {%8,%9}, {%0,%1,%2,%3};"
        : "+f"(c[0]), "+f"(c[1]), "+f"(c[2]), "+f"(c[3])
        : "r"(a[0]), "r"(a[1]), "r"(a[2]), "r"(a[3]), "r"(b[0]), "r"(b[1]));
}
__device__ __forceinline__ unsigned f2tf32(float f){
    unsigned r; asm("cvt.rna.tf32.f32 %0, %1;" : "=r"(r) : "f"(f)); return r;
}
__device__ __forceinline__ unsigned sptr(const void* p){
    return (unsigned)__cvta_generic_to_shared(p);
}
__device__ __forceinline__ void ldmx4(unsigned &r0, unsigned &r1, unsigned &r2, unsigned &r3, unsigned a){
    asm volatile("ldmatrix.sync.aligned.m8n8.x4.shared.b16 {%0,%1,%2,%3}, [%4];"
        : "=r"(r0), "=r"(r1), "=r"(r2), "=r"(r3) : "r"(a));
}

// ---------------- init ----------------
__global__ void zero_lulv(float* lu, float* lv, float* S){
    int i = blockIdx.x*256 + threadIdx.x;
    if (i < ROWS_T){ lu[i] = 0.f; S[i] = 0.f; }
    if (i < ROWS_A) lv[i] = 0.f;
}

// ---------------- LN stats (warp per row) ----------------
__global__ __launch_bounds__(256) void ln_stats(const float* __restrict__ text,
        const float* __restrict__ audio, float2* __restrict__ stats){
    size_t row = (size_t)blockIdx.x*8 + (threadIdx.x >> 5);
    int lane = threadIdx.x & 31;
    const float* x = (row < ROWS_T) ? (text + row*Dm) : (audio + (row-ROWS_T)*Dm);
    float4 v1 = *(const float4*)(x + lane*4);
    float4 v2 = *(const float4*)(x + 128 + lane*4);
    float s = v1.x+v1.y+v1.z+v1.w + v2.x+v2.y+v2.z+v2.w;
    float mean = warpReduceSum(s) * (1.f/Dm);
    float d0=v1.x-mean,d1=v1.y-mean,d2=v1.z-mean,d3=v1.w-mean;
    float e0=v2.x-mean,e1=v2.y-mean,e2=v2.z-mean,e3=v2.w-mean;
    float var = warpReduceSum(d0*d0+d1*d1+d2*d2+d3*d3+e0*e0+e1*e1+e2*e2+e3*e3) * (1.f/Dm);
    if (lane==0) stats[row] = make_float2(mean, rsqrtf(var + 1e-5f));
}

// ---------------- text: unit-norm rows -> bf16 (warp per row) ----------------
__global__ __launch_bounds__(256) void norm_bf16_kernel(const float* __restrict__ x,
        __nv_bfloat16* __restrict__ y){
    size_t row = (size_t)blockIdx.x*8 + (threadIdx.x >> 5);
    int lane = threadIdx.x & 31;
    const float* xr = x + row*Dm;
    float4 v1 = *(const float4*)(xr + lane*4);
    float4 v2 = *(const float4*)(xr + 128 + lane*4);
    float s = v1.x*v1.x+v1.y*v1.y+v1.z*v1.z+v1.w*v1.w
            + v2.x*v2.x+v2.y*v2.y+v2.z*v2.z+v2.w*v2.w;
    float inv = 1.f / fmaxf(sqrtf(warpReduceSum(s)), 1e-12f);
    __nv_bfloat162 p0 = {__float2bfloat16(v1.x*inv), __float2bfloat16(v1.y*inv)};
    __nv_bfloat162 p1 = {__float2bfloat16(v1.z*inv), __float2bfloat16(v1.w*inv)};
    __nv_bfloat162 q0 = {__float2bfloat16(v2.x*inv), __float2bfloat16(v2.y*inv)};
    __nv_bfloat162 q1 = {__float2bfloat16(v2.z*inv), __float2bfloat16(v2.w*inv)};
    *(uint2*)(y + row*Dm + lane*4) = make_uint2(*(unsigned*)&p0, *(unsigned*)&p1);
    *(uint2*)(y + row*Dm + 128 + lane*4) = make_uint2(*(unsigned*)&q0, *(unsigned*)&q1);
}

// ---------------- audio: unit-norm -> An (bf16) + transposed ApT (bf16) ----------------
__global__ __launch_bounds__(256) void audio_norm_T(const float* __restrict__ Ap,
        __nv_bfloat16* __restrict__ An, __nv_bfloat16* __restrict__ ApT){
    __shared__ float tile[32][257];
    __shared__ float invs[32];
    int b = blockIdx.y;
    int n0 = blockIdx.x*32;
    const float* src = Ap + ((size_t)b*LA + n0)*Dm;
    int tid = threadIdx.x;
    for (int i = tid; i < 32*256; i += 256)
        tile[i>>8][i&255] = src[i];
    __syncthreads();
    int w = tid>>5, lane = tid&31;
    for (int rr = 0; rr < 4; rr++){
        int row = w*4 + rr;
        float s = 0.f;
        #pragma unroll
        for (int j=0;j<8;j++){
            float v = tile[row][lane*8 + j];
            s += v*v;
        }
        s = warpReduceSum(s);
        if (lane==0) invs[row] = 1.f / fmaxf(sqrtf(s), 1e-12f);
    }
    __syncthreads();
    __nv_bfloat16* dstA = An + ((size_t)b*LA + n0)*Dm;
    for (int i = tid; i < 32*256; i += 256){
        int row = i>>8;
        dstA[i] = __float2bfloat16(tile[row][i&255] * invs[row]);
    }
    float inv = invs[lane];
    __nv_bfloat16* dstT = ApT + (size_t)b*Dm*LA + n0;
    for (int it = 0; it < 32; it++){
        int d = it*8 + w;
        dstT[(size_t)d*LA + lane] = __float2bfloat16(tile[lane][d] * inv);
    }
}

// ---------------- tf32 tensor-core GEMM (ldmatrix + register prefetch) ----------------
template<int EPI, bool FUSE_LN, bool OUT_BF16>
__global__ __launch_bounds__(256) void gemm_tf32(
        const float* __restrict__ A, int lda, long long bsA,
        const float* __restrict__ B, int ldb, long long bsB,
        void* __restrict__ Cv, int ldc, long long bsC,
        int K,
        const float* __restrict__ bias, long long bsBias,
        const float2* __restrict__ stats,
        const float* __restrict__ lng, const float* __restrict__ lnb,
        const float* __restrict__ rowv, const float* __restrict__ colv, int colvStride)
{
    long long bz = blockIdx.z;
    A += bz*bsA; B += bz*bsB;
    if (bias) bias += bz*bsBias;
    int M0 = blockIdx.x*128, N0 = blockIdx.y*64;

    __shared__ __align__(16) unsigned As[128][36];
    __shared__ __align__(16) unsigned Bs[64][36];
    __shared__ float2 st[128];
    __shared__ float gAll[256], bAll[256];

    int tid = threadIdx.x;
    int warp = tid >> 5, lane = tid & 31;
    int g = lane >> 2, tig = lane & 3;
    int wm = warp >> 1, wn = warp & 1;
    int r8 = lane & 7, grp = lane >> 3;

    if (FUSE_LN){
        if (tid < 128) st[tid] = stats[M0 + tid];
        for (int i = tid; i < K; i += 256){ gAll[i] = lng[i]; bAll[i] = lnb[i]; }
    }

    float acc[2][4][4];
    #pragma unroll
    for(int i=0;i<2;i++) for(int j=0;j<4;j++) for(int q=0;q<4;q++) acc[i][j][q]=0.f;

    int ra = tid >> 1, kh = (tid & 1)*16;
    int rb = tid >> 2, kb = (tid & 3)*8;
    const float* Arow = A + (size_t)(M0+ra)*lda + kh;
    const float* Brow = B + (size_t)(N0+rb)*ldb + kb;

    // prefetch first tile
    float4 va[4];
    float vb[8];
    #pragma unroll
    for (int j=0;j<4;j++) va[j] = *(const float4*)(Arow + 4*j);
    #pragma unroll
    for (int j=0;j<8;j++) vb[j] = Brow[j];

    for (int k0 = 0; k0 < K; k0 += 32){
        __syncthreads();
        {
            float2 ms = FUSE_LN ? st[ra] : make_float2(0.f,0.f);
            #pragma unroll
            for (int j=0;j<4;j++){
                float e[4] = {va[j].x, va[j].y, va[j].z, va[j].w};
                unsigned o[4];
                #pragma unroll
                for (int c=0;c<4;c++){
                    if (FUSE_LN){
                        int kk = k0 + kh + 4*j + c;
                        e[c] = (e[c] - ms.x)*ms.y*gAll[kk] + bAll[kk];
                    }
                    o[c] = f2tf32(e[c]);
                }
                *(uint4*)&As[ra][kh + 4*j] = make_uint4(o[0],o[1],o[2],o[3]);
            }
            unsigned ob[8];
            #pragma unroll
            for (int j=0;j<8;j++) ob[j] = f2tf32(vb[j]);
            *(uint4*)&Bs[rb][kb]   = make_uint4(ob[0],ob[1],ob[2],ob[3]);
            *(uint4*)&Bs[rb][kb+4] = make_uint4(ob[4],ob[5],ob[6],ob[7]);
        }
        __syncthreads();
        if (k0 + 32 < K){
            #pragma unroll
            for (int j=0;j<4;j++) va[j] = *(const float4*)(Arow + k0+32 + 4*j);
            #pragma unroll
            for (int j=0;j<8;j++) vb[j] = Brow[k0+32 + j];
        }
        #pragma unroll
        for (int ks=0; ks<4; ks++){
            int k = ks*8;
            unsigned a[2][4], bf[4][2];
            #pragma unroll
            for (int mt=0; mt<2; mt++){
                unsigned ad = sptr(&As[wm*32 + mt*16 + (grp&1)*8 + r8][k + (grp>>1)*4]);
                ldmx4(a[mt][0], a[mt][1], a[mt][2], a[mt][3], ad);
            }
            #pragma unroll
            for (int p=0; p<2; p++){
                unsigned ad = sptr(&Bs[wn*32 + (p*2 + (grp>>1))*8 + r8][k + (grp&1)*4]);
                ldmx4(bf[p*2][0], bf[p*2][1], bf[p*2+1][0], bf[p*2+1][1], ad);
            }
            #pragma unroll
            for (int mt=0; mt<2; mt++)
                #pragma unroll
                for (int nt=0; nt<4; nt++)
                    mma_tf32(acc[mt][nt], a[mt], bf[nt]);
        }
    }

    #pragma unroll
    for (int mt=0; mt<2; mt++){
        #pragma unroll
        for (int nt=0; nt<4; nt++){
            int m = M0 + wm*32 + mt*16 + g;
            int n = N0 + wn*32 + nt*8 + tig*2;
            #pragma unroll
            for (int hrow=0; hrow<2; hrow++){
                int mm = m + hrow*8;
                float v0 = acc[mt][nt][hrow*2+0];
                float v1 = acc[mt][nt][hrow*2+1];
                if (EPI==0){ v0 += bias[n]; v1 += bias[n+1]; }
                if (EPI==1){
                    float rv = rowv[mm];
                    v0 = geluf(v0 + rv*colv[(size_t)n*colvStride] + bias[n]);
                    v1 = geluf(v1 + rv*colv[(size_t)(n+1)*colvStride] + bias[n+1]);
                }
                if (EPI==2){ v0 = geluf(v0 + bias[n]); v1 = geluf(v1 + bias[n+1]); }
                if (OUT_BF16){
                    __nv_bfloat16* C = (__nv_bfloat16*)Cv + bz*bsC;
                    __nv_bfloat162 pk = {__float2bfloat16(v0), __float2bfloat16(v1)};
                    *(__nv_bfloat162*)(C + (size_t)mm*ldc + n) = pk;
                } else {
                    float* C = (float*)Cv + bz*bsC;
                    *(float2*)(C + (size_t)mm*ldc + n) = make_float2(v0, v1);
                }
            }
        }
    }
}

// ---------------- bf16 cost GEMM (ldmatrix + register-prefetch pipeline) ----------------
__global__ __launch_bounds__(256) void cost_mma(
        const __nv_bfloat16* __restrict__ Tn, const __nv_bfloat16* __restrict__ An,
        __half* __restrict__ logK)
{
    const float IE = (float)(1.0/(0.1+1e-8));
    int b = blockIdx.z;
    const __nv_bfloat16* Ab = Tn + (size_t)b*LT*Dm;
    const __nv_bfloat16* Bb = An + (size_t)b*LA*Dm;
    __half* Cb = logK + (size_t)b*LT*LA;
    int m0 = blockIdx.x*128, n0 = blockIdx.y*128;

    __shared__ __align__(16) __nv_bfloat16 As[128*40];
    __shared__ __align__(16) __nv_bfloat16 Bs[128*40];

    int tid = threadIdx.x;
    int warp = tid >> 5, lane = tid & 31;
    int g = lane >> 2, tig = lane & 3;
    int wm = warp >> 2, wn = warp & 3;
    int r8 = lane & 7, grp = lane >> 3;

    float acc[4][4][4];
    #pragma unroll
    for(int i=0;i<4;i++) for(int j=0;j<4;j++) for(int q=0;q<4;q++) acc[i][j][q]=0.f;

    int lr = tid >> 2, lc = tid & 3;
    const __nv_bfloat16* Ag0 = Ab + (size_t)(m0+lr)*Dm + lc*8;
    const __nv_bfloat16* Ag1 = Ab + (size_t)(m0+lr+64)*Dm + lc*8;
    const __nv_bfloat16* Bg0 = Bb + (size_t)(n0+lr)*Dm + lc*8;
    const __nv_bfloat16* Bg1 = Bb + (size_t)(n0+lr+64)*Dm + lc*8;

    uint4 pa0 = *(const uint4*)(Ag0), pa1 = *(const uint4*)(Ag1);
    uint4 pb0 = *(const uint4*)(Bg0), pb1 = *(const uint4*)(Bg1);

    for (int k0 = 0; k0 < Dm; k0 += 32){
        *(uint4*)(As + lr*40 + lc*8)      = pa0;
        *(uint4*)(As + (lr+64)*40 + lc*8) = pa1;
        *(uint4*)(Bs + lr*40 + lc*8)      = pb0;
        *(uint4*)(Bs + (lr+64)*40 + lc*8) = pb1;
        __syncthreads();
        if (k0 + 32 < Dm){
            pa0 = *(const uint4*)(Ag0 + k0+32);
            pa1 = *(const uint4*)(Ag1 + k0+32);
            pb0 = *(const uint4*)(Bg0 + k0+32);
            pb1 = *(const uint4*)(Bg1 + k0+32);
        }
        #pragma unroll
        for (int kk2=0; kk2<2; kk2++){
            unsigned a[4][4], bf[4][2];
            #pragma unroll
            for (int mt=0; mt<4; mt++){
                int mrow = wm*64 + mt*16 + (grp&1)*8 + r8;
                unsigned ad = sptr(As + mrow*40 + kk2*16 + (grp>>1)*8);
                ldmx4(a[mt][0], a[mt][1], a[mt][2], a[mt][3], ad);
            }
            #pragma unroll
            for (int p=0; p<2; p++){
                int nrow = wn*32 + (p*2 + (grp>>1))*8 + r8;
                unsigned ad = sptr(Bs + nrow*40 + kk2*16 + (grp&1)*8);
                ldmx4(bf[p*2][0], bf[p*2][1], bf[p*2+1][0], bf[p*2+1][1], ad);
            }
            #pragma unroll
            for (int mt=0; mt<4; mt++)
                #pragma unroll
                for (int nt=0; nt<4; nt++)
                    mma_bf16(acc[mt][nt], a[mt], bf[nt]);
        }
        __syncthreads();
    }
    #pragma unroll
    for (int mt=0; mt<4; mt++){
        int r = m0 + wm*64 + mt*16 + g;
        #pragma unroll
        for (int nt=0; nt<4; nt++){
            int c = n0 + wn*32 + nt*8 + tig*2;
            *(__half2*)(Cb + (size_t)r*LA + c) =
                __floats2half2_rn((acc[mt][nt][0]-1.f)*IE, (acc[mt][nt][1]-1.f)*IE);
            *(__half2*)(Cb + (size_t)(r+8)*LA + c) =
                __floats2half2_rn((acc[mt][nt][2]-1.f)*IE, (acc[mt][nt][3]-1.f)*IE);
        }
    }
}

// ---------------- bf16 pi GEMM (exp on the fly) with fused resid/S epilogue ----------------
__global__ __launch_bounds__(256) void pi_mma(
        const __half* __restrict__ logK, const float* __restrict__ lu,
        const float* __restrict__ lv, const __nv_bfloat16* __restrict__ ApT,
        const float* __restrict__ Tp, float* __restrict__ S, float* __restrict__ resid)
{
    int b = blockIdx.z;
    const __half* LKb = logK + (size_t)b*LT*LA;
    const float* lub = lu + (size_t)b*LT;
    const float* lvb = lv + (size_t)b*LA;
    const __nv_bfloat16* Bb = ApT + (size_t)b*Dm*LA;
    const float* Tpb = Tp + (size_t)b*LT*Dm;
    float* Rb = resid + (size_t)b*LT*Dm;
    float* Sb = S + (size_t)b*LT;
    int m0 = blockIdx.x*128, n0 = blockIdx.y*128;

    __shared__ __align__(16) __nv_bfloat16 As[128*40];
    __shared__ __align__(16) __nv_bfloat16 Bs[128*40];

    int tid = threadIdx.x;
    int warp = tid >> 5, lane = tid & 31;
    int g = lane >> 2, tig = lane & 3;
    int wm = warp >> 2, wn = warp & 3;
    int r8 = lane & 7, grp = lane >> 3;

    float acc[4][4][4];
    #pragma unroll
    for(int i=0;i<4;i++) for(int j=0;j<4;j++) for(int q=0;q<4;q++) acc[i][j][q]=0.f;

    int lr = tid >> 2, lc = tid & 3;
    const __half* Lg0 = LKb + (size_t)(m0+lr)*LA + lc*8;
    const __half* Lg1 = LKb + (size_t)(m0+lr+64)*LA + lc*8;
    const __nv_bfloat16* Bg0 = Bb + (size_t)(n0+lr)*LA + lc*8;
    const __nv_bfloat16* Bg1 = Bb + (size_t)(n0+lr+64)*LA + lc*8;
    float lur0 = lub[m0+lr], lur1 = lub[m0+lr+64];

    uint4 ra0 = *(const uint4*)(Lg0), ra1 = *(const uint4*)(Lg1);
    uint4 pb0 = *(const uint4*)(Bg0), pb1 = *(const uint4*)(Bg1);

    for (int k0 = 0; k0 < LA; k0 += 32){
        {
            const __half* hp0 = (const __half*)&ra0;
            const __half* hp1 = (const __half*)&ra1;
            uint4 o0, o1;
            __nv_bfloat16* ob0 = (__nv_bfloat16*)&o0;
            __nv_bfloat16* ob1 = (__nv_bfloat16*)&o1;
            #pragma unroll
            for (int j=0;j<8;j++){
                float lvj = lvb[k0 + lc*8 + j];
                float p0 = __expf(__half2float(hp0[j]) + lur0 + lvj);
                float p1 = __expf(__half2float(hp1[j]) + lur1 + lvj);
                if (isinf(p0)) p0 = 1.f;
                if (isinf(p1)) p1 = 1.f;
                ob0[j] = __float2bfloat16(p0);
                ob1[j] = __float2bfloat16(p1);
            }
            *(uint4*)(As + lr*40 + lc*8)      = o0;
            *(uint4*)(As + (lr+64)*40 + lc*8) = o1;
            *(uint4*)(Bs + lr*40 + lc*8)      = pb0;
            *(uint4*)(Bs + (lr+64)*40 + lc*8) = pb1;
        }
        __syncthreads();
        if (k0 + 32 < LA){
            ra0 = *(const uint4*)(Lg0 + k0+32);
            ra1 = *(const uint4*)(Lg1 + k0+32);
            pb0 = *(const uint4*)(Bg0 + k0+32);
            pb1 = *(const uint4*)(Bg1 + k0+32);
        }
        #pragma unroll
        for (int kk2=0; kk2<2; kk2++){
            unsigned a[4][4], bf[4][2];
            #pragma unroll
            for (int mt=0; mt<4; mt++){
                int mrow = wm*64 + mt*16 + (grp&1)*8 + r8;
                unsigned ad = sptr(As + mrow*40 + kk2*16 + (grp>>1)*8);
                ldmx4(a[mt][0], a[mt][1], a[mt][2], a[mt][3], ad);
            }
            #pragma unroll
            for (int p=0; p<2; p++){
                int nrow = wn*32 + (p*2 + (grp>>1))*8 + r8;
                unsigned ad = sptr(Bs + nrow*40 + kk2*16 + (grp&1)*8);
                ldmx4(bf[p*2][0], bf[p*2][1], bf[p*2+1][0], bf[p*2+1][1], ad);
            }
            #pragma unroll
            for (int mt=0; mt<4; mt++)
                #pragma unroll
                for (int nt=0; nt<4; nt++)
                    mma_bf16(acc[mt][nt], a[mt], bf[nt]);
        }
        __syncthreads();
    }
    // epilogue: resid = |Tp - Aal|, S += <Tp, Aal> partials
    #pragma unroll
    for (int mt=0; mt<4; mt++){
        int r = m0 + wm*64 + mt*16 + g;
        float ps0 = 0.f, ps1 = 0.f;
        #pragma unroll
        for (int nt=0; nt<4; nt++){
            int c = n0 + wn*32 + nt*8 + tig*2;
            float2 t0 = *(const float2*)(Tpb + (size_t)r*Dm + c);
            float2 t1 = *(const float2*)(Tpb + (size_t)(r+8)*Dm + c);
            ps0 += t0.x*acc[mt][nt][0] + t0.y*acc[mt][nt][1];
            ps1 += t1.x*acc[mt][nt][2] + t1.y*acc[mt][nt][3];
            *(float2*)(Rb + (size_t)r*Dm + c) =
                make_float2(fabsf(t0.x-acc[mt][nt][0]), fabsf(t0.y-acc[mt][nt][1]));
            *(float2*)(Rb + (size_t)(r+8)*Dm + c) =
                make_float2(fabsf(t1.x-acc[mt][nt][2]), fabsf(t1.y-acc[mt][nt][3]));
        }
        ps0 += __shfl_xor_sync(0xffffffffu, ps0, 1);
        ps0 += __shfl_xor_sync(0xffffffffu, ps0, 2);
        ps1 += __shfl_xor_sync(0xffffffffu, ps1, 1);
        ps1 += __shfl_xor_sync(0xffffffffu, ps1, 2);
        if (tig == 0){
            atomicAdd(&Sb[r], ps0);
            atomicAdd(&Sb[r+8], ps1);
        }
    }
}

// ---------------- Sinkhorn: row LSE -> lu (one uint4 logK load per thread) ----------------
__global__ __launch_bounds__(256) void sink_row(const __half* __restrict__ logK,
        const float* __restrict__ lv, float* __restrict__ lu){
    int b = blockIdx.y, m = blockIdx.x;
    const uint4* row = (const uint4*)(logK + ((size_t)b*LT + m)*LA);
    int tid = threadIdx.x;
    uint4 raw = row[tid];
    const float4* lv4 = (const float4*)(lv + (size_t)b*LA);
    float4 l0 = lv4[tid*2], l1 = lv4[tid*2+1];
    const __half* hp = (const __half*)&raw;
    float vals[8];
    vals[0]=__half2float(hp[0])+l0.x; vals[1]=__half2float(hp[1])+l0.y;
    vals[2]=__half2float(hp[2])+l0.z; vals[3]=__half2float(hp[3])+l0.w;
    vals[4]=__half2float(hp[4])+l1.x; vals[5]=__half2float(hp[5])+l1.y;
    vals[6]=__half2float(hp[6])+l1.z; vals[7]=__half2float(hp[7])+l1.w;
    float mx = vals[0];
    #pragma unroll
    for (int i=1;i<8;i++) mx = fmaxf(mx, vals[i]);
    mx = blockReduceMax256(mx);
    float s = 0.f;
    #pragma unroll
    for (int i=0;i<8;i++) s += __expf(vals[i]-mx);
    s = blockReduceSum256(s);
    if (tid==0){
        const float LOG_MU = -6.93147180559945f;
        lu[(size_t)b*LT + m] = clip_nan(LOG_MU - (mx + __logf(s)));
    }
}

// ---------------- Sinkhorn: column LSE -> lv (8x row unroll for MLP) ----------------
// grid (LA/64, Bt), block (32,8)
__global__ void sink_col(const __half* __restrict__ logK,
        const float* __restrict__ lu, float* __restrict__ lv){
    int b = blockIdx.y;
    int tx = threadIdx.x, ty = threadIdx.y;
    int c2 = blockIdx.x*32 + tx;
    const __half2* base = (const __half2*)(logK + (size_t)b*LT*LA);
    const float* lub  = lu + (size_t)b*LT;
    float mx0=-INFINITY, s0=0.f, mx1=-INFINITY, s1=0.f;
    for (int m = ty; m < LT; m += 64){
        __half2 h[8];
        float l[8];
        #pragma unroll
        for (int i=0;i<8;i++){
            h[i] = base[(size_t)(m+8*i)*(LA/2) + c2];
            l[i] = lub[m+8*i];
        }
        #pragma unroll
        for (int i=0;i<8;i++){
            float2 f = __half22float2(h[i]);
            float v0 = f.x + l[i], v1 = f.y + l[i];
            if (v0 > mx0){ s0 = s0*__expf(mx0-v0) + 1.f; mx0 = v0; } else s0 += __expf(v0-mx0);
            if (v1 > mx1){ s1 = s1*__expf(mx1-v1) + 1.f; mx1 = v1; } else s1 += __expf(v1-mx1);
        }
    }
    __shared__ float smx[8][64], ss[8][64];
    smx[ty][tx*2]=mx0; ss[ty][tx*2]=s0;
    smx[ty][tx*2+1]=mx1; ss[ty][tx*2+1]=s1;
    __syncthreads();
    for (int off=4; off>=1; off>>=1){
        if (ty < off){
            #pragma unroll
            for (int w=0; w<2; w++){
                int cc = tx*2+w;
                float m1=smx[ty][cc], sa=ss[ty][cc];
                float m2=smx[ty+off][cc], sb=ss[ty+off][cc];
                float M = fmaxf(m1,m2);
                float Sv = sa*__expf(m1-M) + sb*__expf(m2-M);
                smx[ty][cc]=M; ss[ty][cc]=Sv;
            }
        }
        __syncthreads();
    }
    if (ty==0){
        const float LOG_NU = -7.62461898616078f;
        #pragma unroll
        for (int w=0; w<2; w++){
            int cc = tx*2+w;
            lv[(size_t)b*LA + c2*2 + w] = clip_nan(LOG_NU - (smx[0][cc] + __logf(ss[0][cc])));
        }
    }
}

// ---------------- router logits + softmax (warp per row) ----------------
__global__ __launch_bounds__(256) void router_out_kernel(const float* __restrict__ h1,
        const float* __restrict__ Wr2, const float* __restrict__ br2, float* __restrict__ G){
    size_t row = (size_t)blockIdx.x*8 + (threadIdx.x >> 5);
    int lane = threadIdx.x & 31;
    const float* hr = h1 + row*Dm;
    float4 v1 = *(const float4*)(hr + lane*4);
    float4 v2 = *(const float4*)(hr + 128 + lane*4);
    float l[3];
    #pragma unroll
    for (int e=0;e<3;e++){
        const float* w = Wr2 + e*Dm;
        float4 w1 = *(const float4*)(w + lane*4);
        float4 w2 = *(const float4*)(w + 128 + lane*4);
        float s = v1.x*w1.x+v1.y*w1.y+v1.z*w1.z+v1.w*w1.w
                + v2.x*w2.x+v2.y*w2.y+v2.z*w2.z+v2.w*w2.w;
        l[e] = warpReduceSum(s);
    }
    if (lane==0){
        float a0=l[0]+br2[0], a1=l[1]+br2[1], a2=l[2]+br2[2];
        float m = fmaxf(a0, fmaxf(a1,a2));
        float e0=__expf(a0-m), e1=__expf(a1-m), e2=__expf(a2-m);
        float inv = 1.f/(e0+e1+e2);
        G[row*3+0]=e0*inv; G[row*3+1]=e1*inv; G[row*3+2]=e2*inv;
    }
}

// ---------------- multi-scale conv (compile-time kernel size) ----------------
template<int KSZ>
__global__ __launch_bounds__(256) void conv_kernel(const float* __restrict__ h,
        const float* __restrict__ w, const float* __restrict__ conv_b,
        float* __restrict__ h2, int e)
{
    const int pad = (KSZ-1)/2;
    int tile = blockIdx.x*64;
    int l0 = tile & (LT-1);
    __shared__ float hs[68][64];
    __shared__ float ws[16*KSZ*64];
    int tid = threadIdx.x;
    for (int idx = tid; idx < 68*64; idx += 256){
        int lr = idx >> 6; int i = idx & 63;
        int l = l0 + lr - 2;
        float v = 0.f;
        if (l >= 0 && l < LT) v = h[(size_t)(tile - l0 + l)*(NE*Rr) + e*Rr + i];
        hs[lr][i] = v;
    }
    float acc[16];
    #pragma unroll
    for (int j=0;j<16;j++) acc[j]=0.f;
    int o = tid & 63;
    int lg = tid >> 6;
    for (int ic = 0; ic < Rr; ic += 16){
        __syncthreads();
        for (int idx = tid; idx < 16*KSZ*64; idx += 256){
            int oo = idx & 63; int r = idx >> 6;
            int t = r % KSZ; int ii = r / KSZ;
            ws[idx] = w[(size_t)oo*Rr*KSZ + (ic+ii)*KSZ + t];
        }
        __syncthreads();
        #pragma unroll
        for (int ii = 0; ii < 16; ii++){
            #pragma unroll
            for (int t = 0; t < KSZ; t++){
                float wv = ws[(ii*KSZ + t)*64 + o];
                int roff = 2 + t - pad;
                #pragma unroll
                for (int j = 0; j < 16; j++){
                    acc[j] += hs[lg*16 + j + roff][ic + ii] * wv;
                }
            }
        }
    }
    float bo = conv_b[e*Rr + o];
    #pragma unroll
    for (int j=0;j<16;j++){
        int l = lg*16 + j;
        h2[(size_t)(tile + l)*(NE*Rr) + e*Rr + o] = geluf(acc[j] + bo);
    }
}

// ---------------- final (warp per row): gated sum of per-expert LN (u in bf16) ----------------
__global__ __launch_bounds__(256) void final_kernel(const __nv_bfloat16* __restrict__ u,
        const float* __restrict__ resid, const float* __restrict__ G,
        const float* __restrict__ en_g, const float* __restrict__ en_b,
        float* __restrict__ out)
{
    size_t row = (size_t)blockIdx.x*8 + (threadIdx.x >> 5);
    int lane = threadIdx.x & 31;
    const float* rr = resid + row*Dm;
    float4 r1 = *(const float4*)(rr + lane*4);
    float4 r2 = *(const float4*)(rr + 128 + lane*4);
    float4 o1 = make_float4(0,0,0,0), o2 = make_float4(0,0,0,0);
    #pragma unroll
    for (int e=0;e<3;e++){
        const __nv_bfloat16* ur = u + ((size_t)e*ROWS_T + row)*Dm;
        uint2 up1 = *(const uint2*)(ur + lane*4);
        uint2 up2 = *(const uint2*)(ur + 128 + lane*4);
        float2 ua = __bfloat1622float2(*(__nv_bfloat162*)&up1.x);
        float2 ub = __bfloat1622float2(*(__nv_bfloat162*)&up1.y);
        float2 uc = __bfloat1622float2(*(__nv_bfloat162*)&up2.x);
        float2 ud = __bfloat1622float2(*(__nv_bfloat162*)&up2.y);
        float y0=ua.x+r1.x, y1=ua.y+r1.y, y2=ub.x+r1.z, y3=ub.y+r1.w;
        float z0=uc.x+r2.x, z1=uc.y+r2.y, z2=ud.x+r2.z, z3=ud.y+r2.w;
        float mean = warpReduceSum(y0+y1+y2+y3+z0+z1+z2+z3) * (1.f/Dm);
        y0-=mean;y1-=mean;y2-=mean;y3-=mean;z0-=mean;z1-=mean;z2-=mean;z3-=mean;
        float var = warpReduceSum(y0*y0+y1*y1+y2*y2+y3*y3+z0*z0+z1*z1+z2*z2+z3*z3) * (1.f/Dm);
        float rstd = rsqrtf(var + 1e-5f);
        float gw = G[row*3+e];
        const float* eg = en_g + e*Dm;
        const float* eb = en_b + e*Dm;
        float4 g1 = *(const float4*)(eg + lane*4);
        float4 g2 = *(const float4*)(eg + 128 + lane*4);
        float4 b1 = *(const float4*)(eb + lane*4);
        float4 b2 = *(const float4*)(eb + 128 + lane*4);
        o1.x += gw*(y0*rstd*g1.x + b1.x); o1.y += gw*(y1*rstd*g1.y + b1.y);
        o1.z += gw*(y2*rstd*g1.z + b1.z); o1.w += gw*(y3*rstd*g1.w + b1.w);
        o2.x += gw*(z0*rstd*g2.x + b2.x); o2.y += gw*(z1*rstd*g2.y + b2.y);
        o2.z += gw*(z2*rstd*g2.z + b2.z); o2.w += gw*(z3*rstd*g2.w + b2.w);
    }
    float* orow = out + row*Dm;
    *(float4*)(orow + lane*4) = o1;
    *(float4*)(orow + 128 + lane*4) = o2;
}

// ---------------- host launcher ----------------
extern "C" void kernel_launch(void* const* d_in, const int* in_sizes, int n_in,
                              void* d_out, int out_size)
{
    const float* text   = (const float*)d_in[0];
    const float* audio  = (const float*)d_in[1];
    const float* ln_g   = (const float*)d_in[2];
    const float* ln_b   = (const float*)d_in[3];
    const float* W_sh   = (const float*)d_in[4];
    const float* b_sh   = (const float*)d_in[5];
    const float* Wr1    = (const float*)d_in[6];
    const float* br1    = (const float*)d_in[7];
    const float* Wr2    = (const float*)d_in[8];
    const float* br2    = (const float*)d_in[9];
    const float* down_W = (const float*)d_in[10];
    const float* down_b = (const float*)d_in[11];
    const float* conv_w1= (const float*)d_in[12];
    const float* conv_w3= (const float*)d_in[13];
    const float* conv_w5= (const float*)d_in[14];
    const float* conv_b = (const float*)d_in[15];
    const float* up_W   = (const float*)d_in[16];
    const float* up_b   = (const float*)d_in[17];
    const float* en_g   = (const float*)d_in[18];
    const float* en_b   = (const float*)d_in[19];
    float* out = (float*)d_out;

    void *p;
    cudaGetSymbolAddress(&p, g_stats); float2* stats = (float2*)p;
    cudaGetSymbolAddress(&p, g_Tp);   float* Tp  = (float*)p;
    cudaGetSymbolAddress(&p, g_Ap);   float* Ap  = (float*)p;
    cudaGetSymbolAddress(&p, g_Tn);   __nv_bfloat16* Tn = (__nv_bfloat16*)p;
    cudaGetSymbolAddress(&p, g_An);   __nv_bfloat16* An = (__nv_bfloat16*)p;
    cudaGetSymbolAddress(&p, g_ApT);  __nv_bfloat16* ApT = (__nv_bfloat16*)p;
    cudaGetSymbolAddress(&p, g_logK); __half* logK = (__half*)p;
    cudaGetSymbolAddress(&p, g_lu);   float* lu = (float*)p;
    cudaGetSymbolAddress(&p, g_lv);   float* lv = (float*)p;
    cudaGetSymbolAddress(&p, g_S);    float* S = (float*)p;
    cudaGetSymbolAddress(&p, g_resid);float* resid = (float*)p;
    cudaGetSymbolAddress(&p, g_h1);   float* h1 = (float*)p;
    cudaGetSymbolAddress(&p, g_G);    float* G = (float*)p;
    cudaGetSymbolAddress(&p, g_h);    float* h = (float*)p;
    cudaGetSymbolAddress(&p, g_h2);   float* h2 = (float*)p;
    cudaGetSymbolAddress(&p, g_u);    __nv_bfloat16* u = (__nv_bfloat16*)p;

    zero_lulv<<<128,256>>>(lu, lv, S);

    // LN stats (warp per row)
    ln_stats<<<(ROWS_T + ROWS_A)/8, 256>>>(text, audio, stats);

    // projections with fused LN (tf32 + ldmatrix + prefetch)
    gemm_tf32<0,true,false><<<dim3(ROWS_T/128, Dm/64, 1),256>>>(text, Dm, 0, W_sh, Dm, 0,
            Tp, Dm, 0, Dm, b_sh, 0, stats, ln_g, ln_b, nullptr, nullptr, 0);
    gemm_tf32<0,true,false><<<dim3(ROWS_A/128, Dm/64, 1),256>>>(audio, Dm, 0, W_sh, Dm, 0,
            Ap, Dm, 0, Dm, b_sh, 0, stats + ROWS_T, ln_g, ln_b, nullptr, nullptr, 0);

    norm_bf16_kernel<<<ROWS_T/8,256>>>(Tp, Tn);
    audio_norm_T<<<dim3(LA/32, Bt), 256>>>(Ap, An, ApT);

    // cost -> logK (fp16) via bf16 tensor cores
    cost_mma<<<dim3(LT/128, LA/128, Bt),256>>>(Tn, An, logK);

    // Sinkhorn (fp16 logK, L2-resident)
    for (int it=0; it<10; ++it){
        sink_row<<<dim3(LT, Bt),256>>>(logK, lv, lu);
        sink_col<<<dim3(LA/64, Bt), dim3(32,8)>>>(logK, lu, lv);
    }

    // pi GEMM with fused resid/S epilogue (A_al never materialized)
    pi_mma<<<dim3(LT/128, Dm/128, Bt),256>>>(logK, lu, lv, ApT, Tp, S, resid);

    // router hidden
    gemm_tf32<1,false,false><<<dim3(ROWS_T/128, Dm/64, 1),256>>>(resid, Dm, 0, Wr1+1, Dm+1, 0,
            h1, Dm, 0, Dm, br1, 0, nullptr, nullptr, nullptr, S, Wr1, Dm+1);
    router_out_kernel<<<ROWS_T/8,256>>>(h1, Wr2, br2, G);

    // experts
    gemm_tf32<2,false,false><<<dim3(ROWS_T/128, (NE*Rr)/64, 1),256>>>(resid, Dm, 0, down_W, Dm, 0,
            h, NE*Rr, 0, Dm, down_b, 0, nullptr, nullptr, nullptr, nullptr, nullptr, 0);
    conv_kernel<1><<<ROWS_T/64,256>>>(h, conv_w1, conv_b, h2, 0);
    conv_kernel<3><<<ROWS_T/64,256>>>(h, conv_w3, conv_b, h2, 1);
    conv_kernel<5><<<ROWS_T/64,256>>>(h, conv_w5, conv_b, h2, 2);
    gemm_tf32<0,false,true><<<dim3(ROWS_T/128, Dm/64, NE),256>>>(h2, NE*Rr, (long long)Rr,
            up_W, Rr, (long long)Dm*Rr, u, Dm, (long long)ROWS_T*Dm,
            Rr, up_b, Dm, nullptr, nullptr, nullptr, nullptr, nullptr, 0);

    final_kernel<<<ROWS_T/8,256>>>(u, resid, G, en_g, en_b, out);
}

// round 13
// speedup vs baseline: 1.0143x; 1.0143x over previous
#include <cuda_runtime.h>
#include <cuda_bf16.h>
#include <cuda_fp16.h>
#include <math.h>

#define Bt 16
#define LT 1024
#define LA 2048
#define Dm 256
#define Rr 64
#define NE 3
#define ROWS_T (Bt*LT)   // 16384
#define ROWS_A (Bt*LA)   // 32768

// ---------------- scratch ----------------
__device__ float2 g_stats[ROWS_T + ROWS_A];
__device__ float g_Tp [(size_t)ROWS_T*Dm];
__device__ float g_Ap [(size_t)ROWS_A*Dm];
__device__ __nv_bfloat16 g_Tn [(size_t)ROWS_T*Dm];
__device__ __nv_bfloat16 g_An [(size_t)ROWS_A*Dm];
__device__ __nv_bfloat16 g_ApT[(size_t)Bt*Dm*LA];
__device__ __half g_logK[(size_t)Bt*LT*LA];
__device__ float g_lu[ROWS_T];
__device__ float g_lv[ROWS_A];
__device__ float g_S[ROWS_T];
__device__ float g_resid[(size_t)ROWS_T*Dm];
__device__ float g_h1[(size_t)ROWS_T*Dm];
__device__ float g_G[ROWS_T*NE];
__device__ float g_h [(size_t)ROWS_T*NE*Rr];
__device__ float g_h2[(size_t)ROWS_T*NE*Rr];
__device__ __nv_bfloat16 g_u [(size_t)NE*ROWS_T*Dm];

// ---------------- helpers ----------------
__device__ __forceinline__ float geluf(float x){
    return 0.5f*x*(1.0f+erff(x*0.7071067811865476f));
}
__device__ __forceinline__ float warpReduceSum(float v){
    #pragma unroll
    for(int o=16;o;o>>=1) v += __shfl_xor_sync(0xffffffffu, v, o);
    return v;
}
__device__ __forceinline__ float warpReduceMax(float v){
    #pragma unroll
    for(int o=16;o;o>>=1) v = fmaxf(v, __shfl_xor_sync(0xffffffffu, v, o));
    return v;
}
__device__ __forceinline__ float blockReduceSum256(float v){
    __shared__ float sh[8];
    int ln = threadIdx.x & 31, w = threadIdx.x >> 5;
    v = warpReduceSum(v);
    __syncthreads();
    if (ln==0) sh[w]=v;
    __syncthreads();
    float t = 0.f;
    #pragma unroll
    for (int i=0;i<8;i++) t += sh[i];
    return t;
}
__device__ __forceinline__ float blockReduceMax256(float v){
    __shared__ float shm[8];
    int ln = threadIdx.x & 31, w = threadIdx.x >> 5;
    v = warpReduceMax(v);
    __syncthreads();
    if (ln==0) shm[w]=v;
    __syncthreads();
    float t = -INFINITY;
    #pragma unroll
    for (int i=0;i<8;i++) t = fmaxf(t, shm[i]);
    return t;
}
__device__ __forceinline__ float clip_nan(float l){
    if (isnan(l)) return 0.f;
    return fminf(fmaxf(l, -1e9f), 1e9f);
}

__device__ __forceinline__ void mma_bf16(float* c, const unsigned* a, const unsigned* b){
    asm volatile("mma.sync.aligned.m16n8k16.row.col.f32.bf16.bf16.f32 "
        "{%0,%1,%2,%3}, {%4,%5,%6,%7}, {%8,%9}, {%0,%1,%2,%3};"
        : "+f"(c[0]), "+f"(c[1]), "+f"(c[2]), "+f"(c[3])
        : "r"(a[0]), "r"(a[1]), "r"(a[2]), "r"(a[3]), "r"(b[0]), "r"(b[1]));
}
__device__ __forceinline__ void mma_tf32(float* c, const unsigned* a, const unsigned* b){
    asm volatile("mma.sync.aligned.m16n8k8.row.col.f32.tf32.tf32.f32 "
        "{%0,%1,%2,%3}, {%4,%5,%6,%7}, {%8,%9}, {%0,%1,%2,%3};"
        : "+f"(c[0]), "+f"(c[1]), "+f"(c[2]), "+f"(c[3])
        : "r"(a[0]), "r"(a[1]), "r"(a[2]), "r"(a[3]), "r"(b[0]), "r"(b[1]));
}
__device__ __forceinline__ unsigned f2tf32(float f){
    unsigned r; asm("cvt.rna.tf32.f32 %0, %1;" : "=r"(r) : "f"(f)); return r;
}
__device__ __forceinline__ unsigned sptr(const void* p){
    return (unsigned)__cvta_generic_to_shared(p);
}
__device__ __forceinline__ void ldmx4(unsigned &r0, unsigned &r1, unsigned &r2, unsigned &r3, unsigned a){
    asm volatile("ldmatrix.sync.aligned.m8n8.x4.shared.b16 {%0,%1,%2,%3}, [%4];"
        : "=r"(r0), "=r"(r1), "=r"(r2), "=r"(r3) : "r"(a));
}

// ---------------- init ----------------
__global__ void zero_lulv(float* lu, float* lv, float* S){
    int i = blockIdx.x*256 + threadIdx.x;
    if (i < ROWS_T){ lu[i] = 0.f; S[i] = 0.f; }
    if (i < ROWS_A) lv[i] = 0.f;
}

// ---------------- LN stats (warp per row) ----------------
__global__ __launch_bounds__(256) void ln_stats(const float* __restrict__ text,
        const float* __restrict__ audio, float2* __restrict__ stats){
    size_t row = (size_t)blockIdx.x*8 + (threadIdx.x >> 5);
    int lane = threadIdx.x & 31;
    const float* x = (row < ROWS_T) ? (text + row*Dm) : (audio + (row-ROWS_T)*Dm);
    float4 v1 = *(const float4*)(x + lane*4);
    float4 v2 = *(const float4*)(x + 128 + lane*4);
    float s = v1.x+v1.y+v1.z+v1.w + v2.x+v2.y+v2.z+v2.w;
    float mean = warpReduceSum(s) * (1.f/Dm);
    float d0=v1.x-mean,d1=v1.y-mean,d2=v1.z-mean,d3=v1.w-mean;
    float e0=v2.x-mean,e1=v2.y-mean,e2=v2.z-mean,e3=v2.w-mean;
    float var = warpReduceSum(d0*d0+d1*d1+d2*d2+d3*d3+e0*e0+e1*e1+e2*e2+e3*e3) * (1.f/Dm);
    if (lane==0) stats[row] = make_float2(mean, rsqrtf(var + 1e-5f));
}

// ---------------- text: unit-norm rows -> bf16 (warp per row) ----------------
__global__ __launch_bounds__(256) void norm_bf16_kernel(const float* __restrict__ x,
        __nv_bfloat16* __restrict__ y){
    size_t row = (size_t)blockIdx.x*8 + (threadIdx.x >> 5);
    int lane = threadIdx.x & 31;
    const float* xr = x + row*Dm;
    float4 v1 = *(const float4*)(xr + lane*4);
    float4 v2 = *(const float4*)(xr + 128 + lane*4);
    float s = v1.x*v1.x+v1.y*v1.y+v1.z*v1.z+v1.w*v1.w
            + v2.x*v2.x+v2.y*v2.y+v2.z*v2.z+v2.w*v2.w;
    float inv = 1.f / fmaxf(sqrtf(warpReduceSum(s)), 1e-12f);
    __nv_bfloat162 p0 = {__float2bfloat16(v1.x*inv), __float2bfloat16(v1.y*inv)};
    __nv_bfloat162 p1 = {__float2bfloat16(v1.z*inv), __float2bfloat16(v1.w*inv)};
    __nv_bfloat162 q0 = {__float2bfloat16(v2.x*inv), __float2bfloat16(v2.y*inv)};
    __nv_bfloat162 q1 = {__float2bfloat16(v2.z*inv), __float2bfloat16(v2.w*inv)};
    *(uint2*)(y + row*Dm + lane*4) = make_uint2(*(unsigned*)&p0, *(unsigned*)&p1);
    *(uint2*)(y + row*Dm + 128 + lane*4) = make_uint2(*(unsigned*)&q0, *(unsigned*)&q1);
}

// ---------------- audio: unit-norm -> An (bf16) + transposed ApT (bf16) ----------------
__global__ __launch_bounds__(256) void audio_norm_T(const float* __restrict__ Ap,
        __nv_bfloat16* __restrict__ An, __nv_bfloat16* __restrict__ ApT){
    __shared__ float tile[32][257];
    __shared__ float invs[32];
    int b = blockIdx.y;
    int n0 = blockIdx.x*32;
    const float* src = Ap + ((size_t)b*LA + n0)*Dm;
    int tid = threadIdx.x;
    for (int i = tid; i < 32*256; i += 256)
        tile[i>>8][i&255] = src[i];
    __syncthreads();
    int w = tid>>5, lane = tid&31;
    for (int rr = 0; rr < 4; rr++){
        int row = w*4 + rr;
        float s = 0.f;
        #pragma unroll
        for (int j=0;j<8;j++){
            float v = tile[row][lane*8 + j];
            s += v*v;
        }
        s = warpReduceSum(s);
        if (lane==0) invs[row] = 1.f / fmaxf(sqrtf(s), 1e-12f);
    }
    __syncthreads();
    __nv_bfloat16* dstA = An + ((size_t)b*LA + n0)*Dm;
    for (int i = tid; i < 32*256; i += 256){
        int row = i>>8;
        dstA[i] = __float2bfloat16(tile[row][i&255] * invs[row]);
    }
    float inv = invs[lane];
    __nv_bfloat16* dstT = ApT + (size_t)b*Dm*LA + n0;
    for (int it = 0; it < 32; it++){
        int d = it*8 + w;
        dstT[(size_t)d*LA + lane] = __float2bfloat16(tile[lane][d] * inv);
    }
}

// ---------------- tf32 tensor-core GEMM (ldmatrix + register prefetch) ----------------
template<int EPI, bool FUSE_LN, bool OUT_BF16>
__global__ __launch_bounds__(256) void gemm_tf32(
        const float* __restrict__ A, int lda, long long bsA,
        const float* __restrict__ B, int ldb, long long bsB,
        void* __restrict__ Cv, int ldc, long long bsC,
        int K,
        const float* __restrict__ bias, long long bsBias,
        const float2* __restrict__ stats,
        const float* __restrict__ lng, const float* __restrict__ lnb,
        const float* __restrict__ rowv, const float* __restrict__ colv, int colvStride)
{
    long long bz = blockIdx.z;
    A += bz*bsA; B += bz*bsB;
    if (bias) bias += bz*bsBias;
    int M0 = blockIdx.x*128, N0 = blockIdx.y*64;

    __shared__ __align__(16) unsigned As[128][36];
    __shared__ __align__(16) unsigned Bs[64][36];
    __shared__ float2 st[128];
    __shared__ float gAll[256], bAll[256];

    int tid = threadIdx.x;
    int warp = tid >> 5, lane = tid & 31;
    int g = lane >> 2, tig = lane & 3;
    int wm = warp >> 1, wn = warp & 1;
    int r8 = lane & 7, grp = lane >> 3;

    if (FUSE_LN){
        if (tid < 128) st[tid] = stats[M0 + tid];
        for (int i = tid; i < K; i += 256){ gAll[i] = lng[i]; bAll[i] = lnb[i]; }
    }

    float acc[2][4][4];
    #pragma unroll
    for(int i=0;i<2;i++) for(int j=0;j<4;j++) for(int q=0;q<4;q++) acc[i][j][q]=0.f;

    int ra = tid >> 1, kh = (tid & 1)*16;
    int rb = tid >> 2, kb = (tid & 3)*8;
    const float* Arow = A + (size_t)(M0+ra)*lda + kh;
    const float* Brow = B + (size_t)(N0+rb)*ldb + kb;

    float4 va[4];
    float vb[8];
    #pragma unroll
    for (int j=0;j<4;j++) va[j] = *(const float4*)(Arow + 4*j);
    #pragma unroll
    for (int j=0;j<8;j++) vb[j] = Brow[j];

    for (int k0 = 0; k0 < K; k0 += 32){
        __syncthreads();
        {
            float2 ms = FUSE_LN ? st[ra] : make_float2(0.f,0.f);
            #pragma unroll
            for (int j=0;j<4;j++){
                float e[4] = {va[j].x, va[j].y, va[j].z, va[j].w};
                unsigned o[4];
                #pragma unroll
                for (int c=0;c<4;c++){
                    if (FUSE_LN){
                        int kk = k0 + kh + 4*j + c;
                        e[c] = (e[c] - ms.x)*ms.y*gAll[kk] + bAll[kk];
                    }
                    o[c] = f2tf32(e[c]);
                }
                *(uint4*)&As[ra][kh + 4*j] = make_uint4(o[0],o[1],o[2],o[3]);
            }
            unsigned ob[8];
            #pragma unroll
            for (int j=0;j<8;j++) ob[j] = f2tf32(vb[j]);
            *(uint4*)&Bs[rb][kb]   = make_uint4(ob[0],ob[1],ob[2],ob[3]);
            *(uint4*)&Bs[rb][kb+4] = make_uint4(ob[4],ob[5],ob[6],ob[7]);
        }
        __syncthreads();
        if (k0 + 32 < K){
            #pragma unroll
            for (int j=0;j<4;j++) va[j] = *(const float4*)(Arow + k0+32 + 4*j);
            #pragma unroll
            for (int j=0;j<8;j++) vb[j] = Brow[k0+32 + j];
        }
        #pragma unroll
        for (int ks=0; ks<4; ks++){
            int k = ks*8;
            unsigned a[2][4], bf[4][2];
            #pragma unroll
            for (int mt=0; mt<2; mt++){
                unsigned ad = sptr(&As[wm*32 + mt*16 + (grp&1)*8 + r8][k + (grp>>1)*4]);
                ldmx4(a[mt][0], a[mt][1], a[mt][2], a[mt][3], ad);
            }
            #pragma unroll
            for (int p=0; p<2; p++){
                unsigned ad = sptr(&Bs[wn*32 + (p*2 + (grp>>1))*8 + r8][k + (grp&1)*4]);
                ldmx4(bf[p*2][0], bf[p*2][1], bf[p*2+1][0], bf[p*2+1][1], ad);
            }
            #pragma unroll
            for (int mt=0; mt<2; mt++)
                #pragma unroll
                for (int nt=0; nt<4; nt++)
                    mma_tf32(acc[mt][nt], a[mt], bf[nt]);
        }
    }

    #pragma unroll
    for (int mt=0; mt<2; mt++){
        #pragma unroll
        for (int nt=0; nt<4; nt++){
            int m = M0 + wm*32 + mt*16 + g;
            int n = N0 + wn*32 + nt*8 + tig*2;
            #pragma unroll
            for (int hrow=0; hrow<2; hrow++){
                int mm = m + hrow*8;
                float v0 = acc[mt][nt][hrow*2+0];
                float v1 = acc[mt][nt][hrow*2+1];
                if (EPI==0){ v0 += bias[n]; v1 += bias[n+1]; }
                if (EPI==1){
                    float rv = rowv[mm];
                    v0 = geluf(v0 + rv*colv[(size_t)n*colvStride] + bias[n]);
                    v1 = geluf(v1 + rv*colv[(size_t)(n+1)*colvStride] + bias[n+1]);
                }
                if (EPI==2){ v0 = geluf(v0 + bias[n]); v1 = geluf(v1 + bias[n+1]); }
                if (OUT_BF16){
                    __nv_bfloat16* C = (__nv_bfloat16*)Cv + bz*bsC;
                    __nv_bfloat162 pk = {__float2bfloat16(v0), __float2bfloat16(v1)};
                    *(__nv_bfloat162*)(C + (size_t)mm*ldc + n) = pk;
                } else {
                    float* C = (float*)Cv + bz*bsC;
                    *(float2*)(C + (size_t)mm*ldc + n) = make_float2(v0, v1);
                }
            }
        }
    }
}

// ---------------- bf16 cost GEMM (double-buffered smem, one sync/iter) ----------------
__global__ __launch_bounds__(256) void cost_mma(
        const __nv_bfloat16* __restrict__ Tn, const __nv_bfloat16* __restrict__ An,
        __half* __restrict__ logK)
{
    const float IE = (float)(1.0/(0.1+1e-8));
    int b = blockIdx.z;
    const __nv_bfloat16* Ab = Tn + (size_t)b*LT*Dm;
    const __nv_bfloat16* Bb = An + (size_t)b*LA*Dm;
    __half* Cb = logK + (size_t)b*LT*LA;
    int m0 = blockIdx.x*128, n0 = blockIdx.y*128;

    __shared__ __align__(16) __nv_bfloat16 As[2][128*40];
    __shared__ __align__(16) __nv_bfloat16 Bs[2][128*40];

    int tid = threadIdx.x;
    int warp = tid >> 5, lane = tid & 31;
    int g = lane >> 2, tig = lane & 3;
    int wm = warp >> 2, wn = warp & 3;
    int r8 = lane & 7, grp = lane >> 3;

    float acc[4][4][4];
    #pragma unroll
    for(int i=0;i<4;i++) for(int j=0;j<4;j++) for(int q=0;q<4;q++) acc[i][j][q]=0.f;

    int lr = tid >> 2, lc = tid & 3;
    const __nv_bfloat16* Ag0 = Ab + (size_t)(m0+lr)*Dm + lc*8;
    const __nv_bfloat16* Ag1 = Ab + (size_t)(m0+lr+64)*Dm + lc*8;
    const __nv_bfloat16* Bg0 = Bb + (size_t)(n0+lr)*Dm + lc*8;
    const __nv_bfloat16* Bg1 = Bb + (size_t)(n0+lr+64)*Dm + lc*8;

    uint4 pa0 = *(const uint4*)(Ag0), pa1 = *(const uint4*)(Ag1);
    uint4 pb0 = *(const uint4*)(Bg0), pb1 = *(const uint4*)(Bg1);

    // prologue: stage tile 0 into buf 0
    *(uint4*)(As[0] + lr*40 + lc*8)      = pa0;
    *(uint4*)(As[0] + (lr+64)*40 + lc*8) = pa1;
    *(uint4*)(Bs[0] + lr*40 + lc*8)      = pb0;
    *(uint4*)(Bs[0] + (lr+64)*40 + lc*8) = pb1;
    __syncthreads();

    for (int k0 = 0; k0 < Dm; k0 += 32){
        int cur = (k0 >> 5) & 1;
        bool more = (k0 + 32 < Dm);
        if (more){
            pa0 = *(const uint4*)(Ag0 + k0+32);
            pa1 = *(const uint4*)(Ag1 + k0+32);
            pb0 = *(const uint4*)(Bg0 + k0+32);
            pb1 = *(const uint4*)(Bg1 + k0+32);
        }
        #pragma unroll
        for (int kk2=0; kk2<2; kk2++){
            unsigned a[4][4], bf[4][2];
            #pragma unroll
            for (int mt=0; mt<4; mt++){
                int mrow = wm*64 + mt*16 + (grp&1)*8 + r8;
                unsigned ad = sptr(As[cur] + mrow*40 + kk2*16 + (grp>>1)*8);
                ldmx4(a[mt][0], a[mt][1], a[mt][2], a[mt][3], ad);
            }
            #pragma unroll
            for (int p=0; p<2; p++){
                int nrow = wn*32 + (p*2 + (grp>>1))*8 + r8;
                unsigned ad = sptr(Bs[cur] + nrow*40 + kk2*16 + (grp&1)*8);
                ldmx4(bf[p*2][0], bf[p*2][1], bf[p*2+1][0], bf[p*2+1][1], ad);
            }
            #pragma unroll
            for (int mt=0; mt<4; mt++)
                #pragma unroll
                for (int nt=0; nt<4; nt++)
                    mma_bf16(acc[mt][nt], a[mt], bf[nt]);
        }
        if (more){
            int nxt = cur ^ 1;
            *(uint4*)(As[nxt] + lr*40 + lc*8)      = pa0;
            *(uint4*)(As[nxt] + (lr+64)*40 + lc*8) = pa1;
            *(uint4*)(Bs[nxt] + lr*40 + lc*8)      = pb0;
            *(uint4*)(Bs[nxt] + (lr+64)*40 + lc*8) = pb1;
        }
        __syncthreads();
    }
    #pragma unroll
    for (int mt=0; mt<4; mt++){
        int r = m0 + wm*64 + mt*16 + g;
        #pragma unroll
        for (int nt=0; nt<4; nt++){
            int c = n0 + wn*32 + nt*8 + tig*2;
            *(__half2*)(Cb + (size_t)r*LA + c) =
                __floats2half2_rn((acc[mt][nt][0]-1.f)*IE, (acc[mt][nt][1]-1.f)*IE);
            *(__half2*)(Cb + (size_t)(r+8)*LA + c) =
                __floats2half2_rn((acc[mt][nt][2]-1.f)*IE, (acc[mt][nt][3]-1.f)*IE);
        }
    }
}

// ---------------- bf16 pi GEMM (double-buffered, exp on the fly, fused resid/S) ----------------
__global__ __launch_bounds__(256) void pi_mma(
        const __half* __restrict__ logK, const float* __restrict__ lu,
        const float* __restrict__ lv, const __nv_bfloat16* __restrict__ ApT,
        const float* __restrict__ Tp, float* __restrict__ S, float* __restrict__ resid)
{
    int b = blockIdx.z;
    const __half* LKb = logK + (size_t)b*LT*LA;
    const float* lub = lu + (size_t)b*LT;
    const float* lvb = lv + (size_t)b*LA;
    const __nv_bfloat16* Bb = ApT + (size_t)b*Dm*LA;
    const float* Tpb = Tp + (size_t)b*LT*Dm;
    float* Rb = resid + (size_t)b*LT*Dm;
    float* Sb = S + (size_t)b*LT;
    int m0 = blockIdx.x*128, n0 = blockIdx.y*128;

    __shared__ __align__(16) __nv_bfloat16 As[2][128*40];
    __shared__ __align__(16) __nv_bfloat16 Bs[2][128*40];

    int tid = threadIdx.x;
    int warp = tid >> 5, lane = tid & 31;
    int g = lane >> 2, tig = lane & 3;
    int wm = warp >> 2, wn = warp & 3;
    int r8 = lane & 7, grp = lane >> 3;

    float acc[4][4][4];
    #pragma unroll
    for(int i=0;i<4;i++) for(int j=0;j<4;j++) for(int q=0;q<4;q++) acc[i][j][q]=0.f;

    int lr = tid >> 2, lc = tid & 3;
    const __half* Lg0 = LKb + (size_t)(m0+lr)*LA + lc*8;
    const __half* Lg1 = LKb + (size_t)(m0+lr+64)*LA + lc*8;
    const __nv_bfloat16* Bg0 = Bb + (size_t)(n0+lr)*LA + lc*8;
    const __nv_bfloat16* Bg1 = Bb + (size_t)(n0+lr+64)*LA + lc*8;
    float lur0 = lub[m0+lr], lur1 = lub[m0+lr+64];

    uint4 ra0 = *(const uint4*)(Lg0), ra1 = *(const uint4*)(Lg1);
    uint4 pb0 = *(const uint4*)(Bg0), pb1 = *(const uint4*)(Bg1);

    // prologue: transform + stage tile 0 into buf 0
    {
        const __half* hp0 = (const __half*)&ra0;
        const __half* hp1 = (const __half*)&ra1;
        uint4 o0, o1;
        __nv_bfloat16* ob0 = (__nv_bfloat16*)&o0;
        __nv_bfloat16* ob1 = (__nv_bfloat16*)&o1;
        #pragma unroll
        for (int j=0;j<8;j++){
            float lvj = lvb[lc*8 + j];
            float p0 = __expf(__half2float(hp0[j]) + lur0 + lvj);
            float p1 = __expf(__half2float(hp1[j]) + lur1 + lvj);
            if (isinf(p0)) p0 = 1.f;
            if (isinf(p1)) p1 = 1.f;
            ob0[j] = __float2bfloat16(p0);
            ob1[j] = __float2bfloat16(p1);
        }
        *(uint4*)(As[0] + lr*40 + lc*8)      = o0;
        *(uint4*)(As[0] + (lr+64)*40 + lc*8) = o1;
        *(uint4*)(Bs[0] + lr*40 + lc*8)      = pb0;
        *(uint4*)(Bs[0] + (lr+64)*40 + lc*8) = pb1;
    }
    __syncthreads();

    for (int k0 = 0; k0 < LA; k0 += 32){
        int cur = (k0 >> 5) & 1;
        bool more = (k0 + 32 < LA);
        if (more){
            ra0 = *(const uint4*)(Lg0 + k0+32);
            ra1 = *(const uint4*)(Lg1 + k0+32);
            pb0 = *(const uint4*)(Bg0 + k0+32);
            pb1 = *(const uint4*)(Bg1 + k0+32);
        }
        #pragma unroll
        for (int kk2=0; kk2<2; kk2++){
            unsigned a[4][4], bf[4][2];
            #pragma unroll
            for (int mt=0; mt<4; mt++){
                int mrow = wm*64 + mt*16 + (grp&1)*8 + r8;
                unsigned ad = sptr(As[cur] + mrow*40 + kk2*16 + (grp>>1)*8);
                ldmx4(a[mt][0], a[mt][1], a[mt][2], a[mt][3], ad);
            }
            #pragma unroll
            for (int p=0; p<2; p++){
                int nrow = wn*32 + (p*2 + (grp>>1))*8 + r8;
                unsigned ad = sptr(Bs[cur] + nrow*40 + kk2*16 + (grp&1)*8);
                ldmx4(bf[p*2][0], bf[p*2][1], bf[p*2+1][0], bf[p*2+1][1], ad);
            }
            #pragma unroll
            for (int mt=0; mt<4; mt++)
                #pragma unroll
                for (int nt=0; nt<4; nt++)
                    mma_bf16(acc[mt][nt], a[mt], bf[nt]);
        }
        if (more){
            int nxt = cur ^ 1;
            const __half* hp0 = (const __half*)&ra0;
            const __half* hp1 = (const __half*)&ra1;
            uint4 o0, o1;
            __nv_bfloat16* ob0 = (__nv_bfloat16*)&o0;
            __nv_bfloat16* ob1 = (__nv_bfloat16*)&o1;
            #pragma unroll
            for (int j=0;j<8;j++){
                float lvj = lvb[k0+32 + lc*8 + j];
                float p0 = __expf(__half2float(hp0[j]) + lur0 + lvj);
                float p1 = __expf(__half2float(hp1[j]) + lur1 + lvj);
                if (isinf(p0)) p0 = 1.f;
                if (isinf(p1)) p1 = 1.f;
                ob0[j] = __float2bfloat16(p0);
                ob1[j] = __float2bfloat16(p1);
            }
            *(uint4*)(As[nxt] + lr*40 + lc*8)      = o0;
            *(uint4*)(As[nxt] + (lr+64)*40 + lc*8) = o1;
            *(uint4*)(Bs[nxt] + lr*40 + lc*8)      = pb0;
            *(uint4*)(Bs[nxt] + (lr+64)*40 + lc*8) = pb1;
        }
        __syncthreads();
    }
    // epilogue: resid = |Tp - Aal|, S += <Tp, Aal> partials
    #pragma unroll
    for (int mt=0; mt<4; mt++){
        int r = m0 + wm*64 + mt*16 + g;
        float ps0 = 0.f, ps1 = 0.f;
        #pragma unroll
        for (int nt=0; nt<4; nt++){
            int c = n0 + wn*32 + nt*8 + tig*2;
            float2 t0 = *(const float2*)(Tpb + (size_t)r*Dm + c);
            float2 t1 = *(const float2*)(Tpb + (size_t)(r+8)*Dm + c);
            ps0 += t0.x*acc[mt][nt][0] + t0.y*acc[mt][nt][1];
            ps1 += t1.x*acc[mt][nt][2] + t1.y*acc[mt][nt][3];
            *(float2*)(Rb + (size_t)r*Dm + c) =
                make_float2(fabsf(t0.x-acc[mt][nt][0]), fabsf(t0.y-acc[mt][nt][1]));
            *(float2*)(Rb + (size_t)(r+8)*Dm + c) =
                make_float2(fabsf(t1.x-acc[mt][nt][2]), fabsf(t1.y-acc[mt][nt][3]));
        }
        ps0 += __shfl_xor_sync(0xffffffffu, ps0, 1);
        ps0 += __shfl_xor_sync(0xffffffffu, ps0, 2);
        ps1 += __shfl_xor_sync(0xffffffffu, ps1, 1);
        ps1 += __shfl_xor_sync(0xffffffffu, ps1, 2);
        if (tig == 0){
            atomicAdd(&Sb[r], ps0);
            atomicAdd(&Sb[r+8], ps1);
        }
    }
}

// ---------------- Sinkhorn: row LSE -> lu ----------------
__global__ __launch_bounds__(256) void sink_row(const __half* __restrict__ logK,
        const float* __restrict__ lv, float* __restrict__ lu){
    int b = blockIdx.y, m = blockIdx.x;
    const uint4* row = (const uint4*)(logK + ((size_t)b*LT + m)*LA);
    int tid = threadIdx.x;
    uint4 raw = row[tid];
    const float4* lv4 = (const float4*)(lv + (size_t)b*LA);
    float4 l0 = lv4[tid*2], l1 = lv4[tid*2+1];
    const __half* hp = (const __half*)&raw;
    float vals[8];
    vals[0]=__half2float(hp[0])+l0.x; vals[1]=__half2float(hp[1])+l0.y;
    vals[2]=__half2float(hp[2])+l0.z; vals[3]=__half2float(hp[3])+l0.w;
    vals[4]=__half2float(hp[4])+l1.x; vals[5]=__half2float(hp[5])+l1.y;
    vals[6]=__half2float(hp[6])+l1.z; vals[7]=__half2float(hp[7])+l1.w;
    float mx = vals[0];
    #pragma unroll
    for (int i=1;i<8;i++) mx = fmaxf(mx, vals[i]);
    mx = blockReduceMax256(mx);
    float s = 0.f;
    #pragma unroll
    for (int i=0;i<8;i++) s += __expf(vals[i]-mx);
    s = blockReduceSum256(s);
    if (tid==0){
        const float LOG_MU = -6.93147180559945f;
        lu[(size_t)b*LT + m] = clip_nan(LOG_MU - (mx + __logf(s)));
    }
}

// ---------------- Sinkhorn: column LSE -> lv (8x row unroll) ----------------
__global__ void sink_col(const __half* __restrict__ logK,
        const float* __restrict__ lu, float* __restrict__ lv){
    int b = blockIdx.y;
    int tx = threadIdx.x, ty = threadIdx.y;
    int c2 = blockIdx.x*32 + tx;
    const __half2* base = (const __half2*)(logK + (size_t)b*LT*LA);
    const float* lub  = lu + (size_t)b*LT;
    float mx0=-INFINITY, s0=0.f, mx1=-INFINITY, s1=0.f;
    for (int m = ty; m < LT; m += 64){
        __half2 h[8];
        float l[8];
        #pragma unroll
        for (int i=0;i<8;i++){
            h[i] = base[(size_t)(m+8*i)*(LA/2) + c2];
            l[i] = lub[m+8*i];
        }
        #pragma unroll
        for (int i=0;i<8;i++){
            float2 f = __half22float2(h[i]);
            float v0 = f.x + l[i], v1 = f.y + l[i];
            if (v0 > mx0){ s0 = s0*__expf(mx0-v0) + 1.f; mx0 = v0; } else s0 += __expf(v0-mx0);
            if (v1 > mx1){ s1 = s1*__expf(mx1-v1) + 1.f; mx1 = v1; } else s1 += __expf(v1-mx1);
        }
    }
    __shared__ float smx[8][64], ss[8][64];
    smx[ty][tx*2]=mx0; ss[ty][tx*2]=s0;
    smx[ty][tx*2+1]=mx1; ss[ty][tx*2+1]=s1;
    __syncthreads();
    for (int off=4; off>=1; off>>=1){
        if (ty < off){
            #pragma unroll
            for (int w=0; w<2; w++){
                int cc = tx*2+w;
                float m1=smx[ty][cc], sa=ss[ty][cc];
                float m2=smx[ty+off][cc], sb=ss[ty+off][cc];
                float M = fmaxf(m1,m2);
                float Sv = sa*__expf(m1-M) + sb*__expf(m2-M);
                smx[ty][cc]=M; ss[ty][cc]=Sv;
            }
        }
        __syncthreads();
    }
    if (ty==0){
        const float LOG_NU = -7.62461898616078f;
        #pragma unroll
        for (int w=0; w<2; w++){
            int cc = tx*2+w;
            lv[(size_t)b*LA + c2*2 + w] = clip_nan(LOG_NU - (smx[0][cc] + __logf(ss[0][cc])));
        }
    }
}

// ---------------- router logits + softmax (warp per row) ----------------
__global__ __launch_bounds__(256) void router_out_kernel(const float* __restrict__ h1,
        const float* __restrict__ Wr2, const float* __restrict__ br2, float* __restrict__ G){
    size_t row = (size_t)blockIdx.x*8 + (threadIdx.x >> 5);
    int lane = threadIdx.x & 31;
    const float* hr = h1 + row*Dm;
    float4 v1 = *(const float4*)(hr + lane*4);
    float4 v2 = *(const float4*)(hr + 128 + lane*4);
    float l[3];
    #pragma unroll
    for (int e=0;e<3;e++){
        const float* w = Wr2 + e*Dm;
        float4 w1 = *(const float4*)(w + lane*4);
        float4 w2 = *(const float4*)(w + 128 + lane*4);
        float s = v1.x*w1.x+v1.y*w1.y+v1.z*w1.z+v1.w*w1.w
                + v2.x*w2.x+v2.y*w2.y+v2.z*w2.z+v2.w*w2.w;
        l[e] = warpReduceSum(s);
    }
    if (lane==0){
        float a0=l[0]+br2[0], a1=l[1]+br2[1], a2=l[2]+br2[2];
        float m = fmaxf(a0, fmaxf(a1,a2));
        float e0=__expf(a0-m), e1=__expf(a1-m), e2=__expf(a2-m);
        float inv = 1.f/(e0+e1+e2);
        G[row*3+0]=e0*inv; G[row*3+1]=e1*inv; G[row*3+2]=e2*inv;
    }
}

// ---------------- multi-scale conv (one kernel, block-level dispatch) ----------------
template<int KSZ>
__device__ __forceinline__ void conv_body(const float* __restrict__ h,
        const float* __restrict__ w, const float* __restrict__ conv_b,
        float* __restrict__ h2, int e, float (*hs)[64], float* ws)
{
    const int pad = (KSZ-1)/2;
    int tile = blockIdx.x*64;
    int l0 = tile & (LT-1);
    int tid = threadIdx.x;
    for (int idx = tid; idx < 68*64; idx += 256){
        int lr = idx >> 6; int i = idx & 63;
        int l = l0 + lr - 2;
        float v = 0.f;
        if (l >= 0 && l < LT) v = h[(size_t)(tile - l0 + l)*(NE*Rr) + e*Rr + i];
        hs[lr][i] = v;
    }
    float acc[16];
    #pragma unroll
    for (int j=0;j<16;j++) acc[j]=0.f;
    int o = tid & 63;
    int lg = tid >> 6;
    for (int ic = 0; ic < Rr; ic += 16){
        __syncthreads();
        for (int idx = tid; idx < 16*KSZ*64; idx += 256){
            int oo = idx & 63; int r = idx >> 6;
            int t = r % KSZ; int ii = r / KSZ;
            ws[idx] = w[(size_t)oo*Rr*KSZ + (ic+ii)*KSZ + t];
        }
        __syncthreads();
        #pragma unroll
        for (int ii = 0; ii < 16; ii++){
            #pragma unroll
            for (int t = 0; t < KSZ; t++){
                float wv = ws[(ii*KSZ + t)*64 + o];
                int roff = 2 + t - pad;
                #pragma unroll
                for (int j = 0; j < 16; j++){
                    acc[j] += hs[lg*16 + j + roff][ic + ii] * wv;
                }
            }
        }
    }
    float bo = conv_b[e*Rr + o];
    #pragma unroll
    for (int j=0;j<16;j++){
        int l = lg*16 + j;
        h2[(size_t)(tile + l)*(NE*Rr) + e*Rr + o] = geluf(acc[j] + bo);
    }
}

__global__ __launch_bounds__(256) void conv_all(const float* __restrict__ h,
        const float* __restrict__ w1, const float* __restrict__ w3,
        const float* __restrict__ w5, const float* __restrict__ conv_b,
        float* __restrict__ h2)
{
    __shared__ float hs[68][64];
    __shared__ float ws[16*5*64];
    int e = blockIdx.y;
    if (e == 0)      conv_body<1>(h, w1, conv_b, h2, 0, hs, ws);
    else if (e == 1) conv_body<3>(h, w3, conv_b, h2, 1, hs, ws);
    else             conv_body<5>(h, w5, conv_b, h2, 2, hs, ws);
}

// ---------------- final (warp per row): gated sum of per-expert LN (u in bf16) ----------------
__global__ __launch_bounds__(256) void final_kernel(const __nv_bfloat16* __restrict__ u,
        const float* __restrict__ resid, const float* __restrict__ G,
        const float* __restrict__ en_g, const float* __restrict__ en_b,
        float* __restrict__ out)
{
    size_t row = (size_t)blockIdx.x*8 + (threadIdx.x >> 5);
    int lane = threadIdx.x & 31;
    const float* rr = resid + row*Dm;
    float4 r1 = *(const float4*)(rr + lane*4);
    float4 r2 = *(const float4*)(rr + 128 + lane*4);
    float4 o1 = make_float4(0,0,0,0), o2 = make_float4(0,0,0,0);
    #pragma unroll
    for (int e=0;e<3;e++){
        const __nv_bfloat16* ur = u + ((size_t)e*ROWS_T + row)*Dm;
        uint2 up1 = *(const uint2*)(ur + lane*4);
        uint2 up2 = *(const uint2*)(ur + 128 + lane*4);
        float2 ua = __bfloat1622float2(*(__nv_bfloat162*)&up1.x);
        float2 ub = __bfloat1622float2(*(__nv_bfloat162*)&up1.y);
        float2 uc = __bfloat1622float2(*(__nv_bfloat162*)&up2.x);
        float2 ud = __bfloat1622float2(*(__nv_bfloat162*)&up2.y);
        float y0=ua.x+r1.x, y1=ua.y+r1.y, y2=ub.x+r1.z, y3=ub.y+r1.w;
        float z0=uc.x+r2.x, z1=uc.y+r2.y, z2=ud.x+r2.z, z3=ud.y+r2.w;
        float mean = warpReduceSum(y0+y1+y2+y3+z0+z1+z2+z3) * (1.f/Dm);
        y0-=mean;y1-=mean;y2-=mean;y3-=mean;z0-=mean;z1-=mean;z2-=mean;z3-=mean;
        float var = warpReduceSum(y0*y0+y1*y1+y2*y2+y3*y3+z0*z0+z1*z1+z2*z2+z3*z3) * (1.f/Dm);
        float rstd = rsqrtf(var + 1e-5f);
        float gw = G[row*3+e];
        const float* eg = en_g + e*Dm;
        const float* eb = en_b + e*Dm;
        float4 g1 = *(const float4*)(eg + lane*4);
        float4 g2 = *(const float4*)(eg + 128 + lane*4);
        float4 b1 = *(const float4*)(eb + lane*4);
        float4 b2 = *(const float4*)(eb + 128 + lane*4);
        o1.x += gw*(y0*rstd*g1.x + b1.x); o1.y += gw*(y1*rstd*g1.y + b1.y);
        o1.z += gw*(y2*rstd*g1.z + b1.z); o1.w += gw*(y3*rstd*g1.w + b1.w);
        o2.x += gw*(z0*rstd*g2.x + b2.x); o2.y += gw*(z1*rstd*g2.y + b2.y);
        o2.z += gw*(z2*rstd*g2.z + b2.z); o2.w += gw*(z3*rstd*g2.w + b2.w);
    }
    float* orow = out + row*Dm;
    *(float4*)(orow + lane*4) = o1;
    *(float4*)(orow + 128 + lane*4) = o2;
}

// ---------------- host launcher ----------------
extern "C" void kernel_launch(void* const* d_in, const int* in_sizes, int n_in,
                              void* d_out, int out_size)
{
    const float* text   = (const float*)d_in[0];
    const float* audio  = (const float*)d_in[1];
    const float* ln_g   = (const float*)d_in[2];
    const float* ln_b   = (const float*)d_in[3];
    const float* W_sh   = (const float*)d_in[4];
    const float* b_sh   = (const float*)d_in[5];
    const float* Wr1    = (const float*)d_in[6];
    const float* br1    = (const float*)d_in[7];
    const float* Wr2    = (const float*)d_in[8];
    const float* br2    = (const float*)d_in[9];
    const float* down_W = (const float*)d_in[10];
    const float* down_b = (const float*)d_in[11];
    const float* conv_w1= (const float*)d_in[12];
    const float* conv_w3= (const float*)d_in[13];
    const float* conv_w5= (const float*)d_in[14];
    const float* conv_b = (const float*)d_in[15];
    const float* up_W   = (const float*)d_in[16];
    const float* up_b   = (const float*)d_in[17];
    const float* en_g   = (const float*)d_in[18];
    const float* en_b   = (const float*)d_in[19];
    float* out = (float*)d_out;

    void *p;
    cudaGetSymbolAddress(&p, g_stats); float2* stats = (float2*)p;
    cudaGetSymbolAddress(&p, g_Tp);   float* Tp  = (float*)p;
    cudaGetSymbolAddress(&p, g_Ap);   float* Ap  = (float*)p;
    cudaGetSymbolAddress(&p, g_Tn);   __nv_bfloat16* Tn = (__nv_bfloat16*)p;
    cudaGetSymbolAddress(&p, g_An);   __nv_bfloat16* An = (__nv_bfloat16*)p;
    cudaGetSymbolAddress(&p, g_ApT);  __nv_bfloat16* ApT = (__nv_bfloat16*)p;
    cudaGetSymbolAddress(&p, g_logK); __half* logK = (__half*)p;
    cudaGetSymbolAddress(&p, g_lu);   float* lu = (float*)p;
    cudaGetSymbolAddress(&p, g_lv);   float* lv = (float*)p;
    cudaGetSymbolAddress(&p, g_S);    float* S = (float*)p;
    cudaGetSymbolAddress(&p, g_resid);float* resid = (float*)p;
    cudaGetSymbolAddress(&p, g_h1);   float* h1 = (float*)p;
    cudaGetSymbolAddress(&p, g_G);    float* G = (float*)p;
    cudaGetSymbolAddress(&p, g_h);    float* h = (float*)p;
    cudaGetSymbolAddress(&p, g_h2);   float* h2 = (float*)p;
    cudaGetSymbolAddress(&p, g_u);    __nv_bfloat16* u = (__nv_bfloat16*)p;

    zero_lulv<<<128,256>>>(lu, lv, S);

    // LN stats (warp per row)
    ln_stats<<<(ROWS_T + ROWS_A)/8, 256>>>(text, audio, stats);

    // projections with fused LN (tf32 + ldmatrix + prefetch)
    gemm_tf32<0,true,false><<<dim3(ROWS_T/128, Dm/64, 1),256>>>(text, Dm, 0, W_sh, Dm, 0,
            Tp, Dm, 0, Dm, b_sh, 0, stats, ln_g, ln_b, nullptr, nullptr, 0);
    gemm_tf32<0,true,false><<<dim3(ROWS_A/128, Dm/64, 1),256>>>(audio, Dm, 0, W_sh, Dm, 0,
            Ap, Dm, 0, Dm, b_sh, 0, stats + ROWS_T, ln_g, ln_b, nullptr, nullptr, 0);

    norm_bf16_kernel<<<ROWS_T/8,256>>>(Tp, Tn);
    audio_norm_T<<<dim3(LA/32, Bt), 256>>>(Ap, An, ApT);

    // cost -> logK (fp16) via bf16 tensor cores (double-buffered)
    cost_mma<<<dim3(LT/128, LA/128, Bt),256>>>(Tn, An, logK);

    // Sinkhorn (fp16 logK, L2-resident)
    for (int it=0; it<10; ++it){
        sink_row<<<dim3(LT, Bt),256>>>(logK, lv, lu);
        sink_col<<<dim3(LA/64, Bt), dim3(32,8)>>>(logK, lu, lv);
    }

    // pi GEMM with fused resid/S epilogue (double-buffered)
    pi_mma<<<dim3(LT/128, Dm/128, Bt),256>>>(logK, lu, lv, ApT, Tp, S, resid);

    // router hidden
    gemm_tf32<1,false,false><<<dim3(ROWS_T/128, Dm/64, 1),256>>>(resid, Dm, 0, Wr1+1, Dm+1, 0,
            h1, Dm, 0, Dm, br1, 0, nullptr, nullptr, nullptr, S, Wr1, Dm+1);
    router_out_kernel<<<ROWS_T/8,256>>>(h1, Wr2, br2, G);

    // experts
    gemm_tf32<2,false,false><<<dim3(ROWS_T/128, (NE*Rr)/64, 1),256>>>(resid, Dm, 0, down_W, Dm, 0,
            h, NE*Rr, 0, Dm, down_b, 0, nullptr, nullptr, nullptr, nullptr, nullptr, 0);
    conv_all<<<dim3(ROWS_T/64, NE),256>>>(h, conv_w1, conv_w3, conv_w5, conv_b, h2);
    gemm_tf32<0,false,true><<<dim3(ROWS_T/128, Dm/64, NE),256>>>(h2, NE*Rr, (long long)Rr,
            up_W, Rr, (long long)Dm*Rr, u, Dm, (long long)ROWS_T*Dm,
            Rr, up_b, Dm, nullptr, nullptr, nullptr, nullptr, nullptr, 0);

    final_kernel<<<ROWS_T/8,256>>>(u, resid, G, en_g, en_b, out);
}

// round 14
// speedup vs baseline: 1.0528x; 1.0379x over previous
#include <cuda_runtime.h>
#include <cuda_bf16.h>
#include <cuda_fp16.h>
#include <math.h>

#define Bt 16
#define LT 1024
#define LA 2048
#define Dm 256
#define Rr 64
#define NE 3
#define ROWS_T (Bt*LT)   // 16384
#define ROWS_A (Bt*LA)   // 32768

// ---------------- scratch ----------------
__device__ float2 g_stats[ROWS_T + ROWS_A];
__device__ float g_Tp [(size_t)ROWS_T*Dm];
__device__ float g_Ap [(size_t)ROWS_A*Dm];
__device__ __nv_bfloat16 g_Tn [(size_t)ROWS_T*Dm];
__device__ __nv_bfloat16 g_An [(size_t)ROWS_A*Dm];
__device__ __nv_bfloat16 g_ApT[(size_t)Bt*Dm*LA];
__device__ __half g_logK[(size_t)Bt*LT*LA];
__device__ float g_lu[ROWS_T];
__device__ float g_lv[ROWS_A];
__device__ float g_S[ROWS_T];
__device__ float g_resid[(size_t)ROWS_T*Dm];
__device__ float g_h1[(size_t)ROWS_T*Dm];
__device__ float g_G[ROWS_T*NE];
__device__ float g_h [(size_t)ROWS_T*NE*Rr];
__device__ float g_h2[(size_t)ROWS_T*NE*Rr];
__device__ __nv_bfloat16 g_u [(size_t)NE*ROWS_T*Dm];

// ---------------- helpers ----------------
__device__ __forceinline__ float geluf(float x){
    return 0.5f*x*(1.0f+erff(x*0.7071067811865476f));
}
__device__ __forceinline__ float warpReduceSum(float v){
    #pragma unroll
    for(int o=16;o;o>>=1) v += __shfl_xor_sync(0xffffffffu, v, o);
    return v;
}
__device__ __forceinline__ float warpReduceMax(float v){
    #pragma unroll
    for(int o=16;o;o>>=1) v = fmaxf(v, __shfl_xor_sync(0xffffffffu, v, o));
    return v;
}
__device__ __forceinline__ float clip_nan(float l){
    if (isnan(l)) return 0.f;
    return fminf(fmaxf(l, -1e9f), 1e9f);
}

__device__ __forceinline__ void mma_bf16(float* c, const unsigned* a, const unsigned* b){
    asm volatile("mma.sync.aligned.m16n8k16.row.col.f32.bf16.bf16.f32 "
        "{%0,%1,%2,%3}, {%4,%5,%6,%7}, {%8,%9}, {%0,%1,%2,%3};"
        : "+f"(c[0]), "+f"(c[1]), "+f"(c[2]), "+f"(c[3])
        : "r"(a[0]), "r"(a[1]), "r"(a[2]), "r"(a[3]), "r"(b[0]), "r"(b[1]));
}
__device__ __forceinline__ void mma_tf32(float* c, const unsigned* a, const unsigned* b){
    asm volatile("mma.sync.aligned.m16n8k8.row.col.f32.tf32.tf32.f32 "
        "{%0,%1,%2,%3}, {%4,%5,%6,%7}, {%8,%9}, {%0,%1,%2,%3};"
        : "+f"(c[0]), "+f"(c[1]), "+f"(c[2]), "+f"(c[3])
        : "r"(a[0]), "r"(a[1]), "r"(a[2]), "r"(a[3]), "r"(b[0]), "r"(b[1]));
}
__device__ __forceinline__ unsigned f2tf32(float f){
    unsigned r; asm("cvt.rna.tf32.f32 %0, %1;" : "=r"(r) : "f"(f)); return r;
}
__device__ __forceinline__ unsigned sptr(const void* p){
    return (unsigned)__cvta_generic_to_shared(p);
}
__device__ __forceinline__ void ldmx4(unsigned &r0, unsigned &r1, unsigned &r2, unsigned &r3, unsigned a){
    asm volatile("ldmatrix.sync.aligned.m8n8.x4.shared.b16 {%0,%1,%2,%3}, [%4];"
        : "=r"(r0), "=r"(r1), "=r"(r2), "=r"(r3) : "r"(a));
}

// ---------------- init ----------------
__global__ void zero_lulv(float* lu, float* lv, float* S){
    int i = blockIdx.x*256 + threadIdx.x;
    if (i < ROWS_T){ lu[i] = 0.f; S[i] = 0.f; }
    if (i < ROWS_A) lv[i] = 0.f;
}

// ---------------- LN stats (warp per row) ----------------
__global__ __launch_bounds__(256) void ln_stats(const float* __restrict__ text,
        const float* __restrict__ audio, float2* __restrict__ stats){
    size_t row = (size_t)blockIdx.x*8 + (threadIdx.x >> 5);
    int lane = threadIdx.x & 31;
    const float* x = (row < ROWS_T) ? (text + row*Dm) : (audio + (row-ROWS_T)*Dm);
    float4 v1 = *(const float4*)(x + lane*4);
    float4 v2 = *(const float4*)(x + 128 + lane*4);
    float s = v1.x+v1.y+v1.z+v1.w + v2.x+v2.y+v2.z+v2.w;
    float mean = warpReduceSum(s) * (1.f/Dm);
    float d0=v1.x-mean,d1=v1.y-mean,d2=v1.z-mean,d3=v1.w-mean;
    float e0=v2.x-mean,e1=v2.y-mean,e2=v2.z-mean,e3=v2.w-mean;
    float var = warpReduceSum(d0*d0+d1*d1+d2*d2+d3*d3+e0*e0+e1*e1+e2*e2+e3*e3) * (1.f/Dm);
    if (lane==0) stats[row] = make_float2(mean, rsqrtf(var + 1e-5f));
}

// ---------------- text: unit-norm rows -> bf16 (warp per row) ----------------
__global__ __launch_bounds__(256) void norm_bf16_kernel(const float* __restrict__ x,
        __nv_bfloat16* __restrict__ y){
    size_t row = (size_t)blockIdx.x*8 + (threadIdx.x >> 5);
    int lane = threadIdx.x & 31;
    const float* xr = x + row*Dm;
    float4 v1 = *(const float4*)(xr + lane*4);
    float4 v2 = *(const float4*)(xr + 128 + lane*4);
    float s = v1.x*v1.x+v1.y*v1.y+v1.z*v1.z+v1.w*v1.w
            + v2.x*v2.x+v2.y*v2.y+v2.z*v2.z+v2.w*v2.w;
    float inv = 1.f / fmaxf(sqrtf(warpReduceSum(s)), 1e-12f);
    __nv_bfloat162 p0 = {__float2bfloat16(v1.x*inv), __float2bfloat16(v1.y*inv)};
    __nv_bfloat162 p1 = {__float2bfloat16(v1.z*inv), __float2bfloat16(v1.w*inv)};
    __nv_bfloat162 q0 = {__float2bfloat16(v2.x*inv), __float2bfloat16(v2.y*inv)};
    __nv_bfloat162 q1 = {__float2bfloat16(v2.z*inv), __float2bfloat16(v2.w*inv)};
    *(uint2*)(y + row*Dm + lane*4) = make_uint2(*(unsigned*)&p0, *(unsigned*)&p1);
    *(uint2*)(y + row*Dm + 128 + lane*4) = make_uint2(*(unsigned*)&q0, *(unsigned*)&q1);
}

// ---------------- audio: unit-norm -> An (bf16) + transposed ApT (bf16) ----------------
__global__ __launch_bounds__(256) void audio_norm_T(const float* __restrict__ Ap,
        __nv_bfloat16* __restrict__ An, __nv_bfloat16* __restrict__ ApT){
    __shared__ float tile[32][257];
    __shared__ float invs[32];
    int b = blockIdx.y;
    int n0 = blockIdx.x*32;
    const float* src = Ap + ((size_t)b*LA + n0)*Dm;
    int tid = threadIdx.x;
    for (int i = tid; i < 32*256; i += 256)
        tile[i>>8][i&255] = src[i];
    __syncthreads();
    int w = tid>>5, lane = tid&31;
    for (int rr = 0; rr < 4; rr++){
        int row = w*4 + rr;
        float s = 0.f;
        #pragma unroll
        for (int j=0;j<8;j++){
            float v = tile[row][lane*8 + j];
            s += v*v;
        }
        s = warpReduceSum(s);
        if (lane==0) invs[row] = 1.f / fmaxf(sqrtf(s), 1e-12f);
    }
    __syncthreads();
    __nv_bfloat16* dstA = An + ((size_t)b*LA + n0)*Dm;
    for (int i = tid; i < 32*256; i += 256){
        int row = i>>8;
        dstA[i] = __float2bfloat16(tile[row][i&255] * invs[row]);
    }
    float inv = invs[lane];
    __nv_bfloat16* dstT = ApT + (size_t)b*Dm*LA + n0;
    for (int it = 0; it < 32; it++){
        int d = it*8 + w;
        dstT[(size_t)d*LA + lane] = __float2bfloat16(tile[lane][d] * inv);
    }
}

// ---------------- tf32 tensor-core GEMM (ldmatrix + register prefetch, dual-input) ----------------
template<int EPI, bool FUSE_LN, bool OUT_BF16>
__global__ __launch_bounds__(256) void gemm_tf32(
        const float* __restrict__ A, int lda, long long bsA,
        const float* __restrict__ B, int ldb, long long bsB,
        void* __restrict__ Cv, int ldc, long long bsC,
        int K,
        const float* __restrict__ bias, long long bsBias,
        const float2* __restrict__ stats,
        const float* __restrict__ lng, const float* __restrict__ lnb,
        const float* __restrict__ rowv, const float* __restrict__ colv, int colvStride,
        const float* __restrict__ A2, void* __restrict__ Cv2,
        const float2* __restrict__ stats2, int blocksA)
{
    long long bz = blockIdx.z;
    int bx = blockIdx.x;
    if (A2 && bx >= blocksA){
        A = A2; Cv = Cv2; stats = stats2;
        bx -= blocksA;
    }
    A += bz*bsA; B += bz*bsB;
    if (bias) bias += bz*bsBias;
    int M0 = bx*128, N0 = blockIdx.y*64;

    __shared__ __align__(16) unsigned As[128][36];
    __shared__ __align__(16) unsigned Bs[64][36];
    __shared__ float2 st[128];
    __shared__ float gAll[256], bAll[256];

    int tid = threadIdx.x;
    int warp = tid >> 5, lane = tid & 31;
    int g = lane >> 2, tig = lane & 3;
    int wm = warp >> 1, wn = warp & 1;
    int r8 = lane & 7, grp = lane >> 3;

    if (FUSE_LN){
        if (tid < 128) st[tid] = stats[M0 + tid];
        for (int i = tid; i < K; i += 256){ gAll[i] = lng[i]; bAll[i] = lnb[i]; }
    }

    float acc[2][4][4];
    #pragma unroll
    for(int i=0;i<2;i++) for(int j=0;j<4;j++) for(int q=0;q<4;q++) acc[i][j][q]=0.f;

    int ra = tid >> 1, kh = (tid & 1)*16;
    int rb = tid >> 2, kb = (tid & 3)*8;
    const float* Arow = A + (size_t)(M0+ra)*lda + kh;
    const float* Brow = B + (size_t)(N0+rb)*ldb + kb;

    float4 va[4];
    float vb[8];
    #pragma unroll
    for (int j=0;j<4;j++) va[j] = *(const float4*)(Arow + 4*j);
    #pragma unroll
    for (int j=0;j<8;j++) vb[j] = Brow[j];

    for (int k0 = 0; k0 < K; k0 += 32){
        __syncthreads();
        {
            float2 ms = FUSE_LN ? st[ra] : make_float2(0.f,0.f);
            #pragma unroll
            for (int j=0;j<4;j++){
                float e[4] = {va[j].x, va[j].y, va[j].z, va[j].w};
                unsigned o[4];
                #pragma unroll
                for (int c=0;c<4;c++){
                    if (FUSE_LN){
                        int kk = k0 + kh + 4*j + c;
                        e[c] = (e[c] - ms.x)*ms.y*gAll[kk] + bAll[kk];
                    }
                    o[c] = f2tf32(e[c]);
                }
                *(uint4*)&As[ra][kh + 4*j] = make_uint4(o[0],o[1],o[2],o[3]);
            }
            unsigned ob[8];
            #pragma unroll
            for (int j=0;j<8;j++) ob[j] = f2tf32(vb[j]);
            *(uint4*)&Bs[rb][kb]   = make_uint4(ob[0],ob[1],ob[2],ob[3]);
            *(uint4*)&Bs[rb][kb+4] = make_uint4(ob[4],ob[5],ob[6],ob[7]);
        }
        __syncthreads();
        if (k0 + 32 < K){
            #pragma unroll
            for (int j=0;j<4;j++) va[j] = *(const float4*)(Arow + k0+32 + 4*j);
            #pragma unroll
            for (int j=0;j<8;j++) vb[j] = Brow[k0+32 + j];
        }
        #pragma unroll
        for (int ks=0; ks<4; ks++){
            int k = ks*8;
            unsigned a[2][4], bf[4][2];
            #pragma unroll
            for (int mt=0; mt<2; mt++){
                unsigned ad = sptr(&As[wm*32 + mt*16 + (grp&1)*8 + r8][k + (grp>>1)*4]);
                ldmx4(a[mt][0], a[mt][1], a[mt][2], a[mt][3], ad);
            }
            #pragma unroll
            for (int p=0; p<2; p++){
                unsigned ad = sptr(&Bs[wn*32 + (p*2 + (grp>>1))*8 + r8][k + (grp&1)*4]);
                ldmx4(bf[p*2][0], bf[p*2][1], bf[p*2+1][0], bf[p*2+1][1], ad);
            }
            #pragma unroll
            for (int mt=0; mt<2; mt++)
                #pragma unroll
                for (int nt=0; nt<4; nt++)
                    mma_tf32(acc[mt][nt], a[mt], bf[nt]);
        }
    }

    #pragma unroll
    for (int mt=0; mt<2; mt++){
        #pragma unroll
        for (int nt=0; nt<4; nt++){
            int m = M0 + wm*32 + mt*16 + g;
            int n = N0 + wn*32 + nt*8 + tig*2;
            #pragma unroll
            for (int hrow=0; hrow<2; hrow++){
                int mm = m + hrow*8;
                float v0 = acc[mt][nt][hrow*2+0];
                float v1 = acc[mt][nt][hrow*2+1];
                if (EPI==0){ v0 += bias[n]; v1 += bias[n+1]; }
                if (EPI==1){
                    float rv = rowv[mm];
                    v0 = geluf(v0 + rv*colv[(size_t)n*colvStride] + bias[n]);
                    v1 = geluf(v1 + rv*colv[(size_t)(n+1)*colvStride] + bias[n+1]);
                }
                if (EPI==2){ v0 = geluf(v0 + bias[n]); v1 = geluf(v1 + bias[n+1]); }
                if (OUT_BF16){
                    __nv_bfloat16* C = (__nv_bfloat16*)Cv + bz*bsC;
                    __nv_bfloat162 pk = {__float2bfloat16(v0), __float2bfloat16(v1)};
                    *(__nv_bfloat162*)(C + (size_t)mm*ldc + n) = pk;
                } else {
                    float* C = (float*)Cv + bz*bsC;
                    *(float2*)(C + (size_t)mm*ldc + n) = make_float2(v0, v1);
                }
            }
        }
    }
}

// ---------------- bf16 cost GEMM (double-buffered smem, one sync/iter) ----------------
__global__ __launch_bounds__(256) void cost_mma(
        const __nv_bfloat16* __restrict__ Tn, const __nv_bfloat16* __restrict__ An,
        __half* __restrict__ logK)
{
    const float IE = (float)(1.0/(0.1+1e-8));
    int b = blockIdx.z;
    const __nv_bfloat16* Ab = Tn + (size_t)b*LT*Dm;
    const __nv_bfloat16* Bb = An + (size_t)b*LA*Dm;
    __half* Cb = logK + (size_t)b*LT*LA;
    int m0 = blockIdx.x*128, n0 = blockIdx.y*128;

    __shared__ __align__(16) __nv_bfloat16 As[2][128*40];
    __shared__ __align__(16) __nv_bfloat16 Bs[2][128*40];

    int tid = threadIdx.x;
    int warp = tid >> 5, lane = tid & 31;
    int g = lane >> 2, tig = lane & 3;
    int wm = warp >> 2, wn = warp & 3;
    int r8 = lane & 7, grp = lane >> 3;

    float acc[4][4][4];
    #pragma unroll
    for(int i=0;i<4;i++) for(int j=0;j<4;j++) for(int q=0;q<4;q++) acc[i][j][q]=0.f;

    int lr = tid >> 2, lc = tid & 3;
    const __nv_bfloat16* Ag0 = Ab + (size_t)(m0+lr)*Dm + lc*8;
    const __nv_bfloat16* Ag1 = Ab + (size_t)(m0+lr+64)*Dm + lc*8;
    const __nv_bfloat16* Bg0 = Bb + (size_t)(n0+lr)*Dm + lc*8;
    const __nv_bfloat16* Bg1 = Bb + (size_t)(n0+lr+64)*Dm + lc*8;

    uint4 pa0 = *(const uint4*)(Ag0), pa1 = *(const uint4*)(Ag1);
    uint4 pb0 = *(const uint4*)(Bg0), pb1 = *(const uint4*)(Bg1);

    *(uint4*)(As[0] + lr*40 + lc*8)      = pa0;
    *(uint4*)(As[0] + (lr+64)*40 + lc*8) = pa1;
    *(uint4*)(Bs[0] + lr*40 + lc*8)      = pb0;
    *(uint4*)(Bs[0] + (lr+64)*40 + lc*8) = pb1;
    __syncthreads();

    for (int k0 = 0; k0 < Dm; k0 += 32){
        int cur = (k0 >> 5) & 1;
        bool more = (k0 + 32 < Dm);
        if (more){
            pa0 = *(const uint4*)(Ag0 + k0+32);
            pa1 = *(const uint4*)(Ag1 + k0+32);
            pb0 = *(const uint4*)(Bg0 + k0+32);
            pb1 = *(const uint4*)(Bg1 + k0+32);
        }
        #pragma unroll
        for (int kk2=0; kk2<2; kk2++){
            unsigned a[4][4], bf[4][2];
            #pragma unroll
            for (int mt=0; mt<4; mt++){
                int mrow = wm*64 + mt*16 + (grp&1)*8 + r8;
                unsigned ad = sptr(As[cur] + mrow*40 + kk2*16 + (grp>>1)*8);
                ldmx4(a[mt][0], a[mt][1], a[mt][2], a[mt][3], ad);
            }
            #pragma unroll
            for (int p=0; p<2; p++){
                int nrow = wn*32 + (p*2 + (grp>>1))*8 + r8;
                unsigned ad = sptr(Bs[cur] + nrow*40 + kk2*16 + (grp&1)*8);
                ldmx4(bf[p*2][0], bf[p*2][1], bf[p*2+1][0], bf[p*2+1][1], ad);
            }
            #pragma unroll
            for (int mt=0; mt<4; mt++)
                #pragma unroll
                for (int nt=0; nt<4; nt++)
                    mma_bf16(acc[mt][nt], a[mt], bf[nt]);
        }
        if (more){
            int nxt = cur ^ 1;
            *(uint4*)(As[nxt] + lr*40 + lc*8)      = pa0;
            *(uint4*)(As[nxt] + (lr+64)*40 + lc*8) = pa1;
            *(uint4*)(Bs[nxt] + lr*40 + lc*8)      = pb0;
            *(uint4*)(Bs[nxt] + (lr+64)*40 + lc*8) = pb1;
        }
        __syncthreads();
    }
    #pragma unroll
    for (int mt=0; mt<4; mt++){
        int r = m0 + wm*64 + mt*16 + g;
        #pragma unroll
        for (int nt=0; nt<4; nt++){
            int c = n0 + wn*32 + nt*8 + tig*2;
            *(__half2*)(Cb + (size_t)r*LA + c) =
                __floats2half2_rn((acc[mt][nt][0]-1.f)*IE, (acc[mt][nt][1]-1.f)*IE);
            *(__half2*)(Cb + (size_t)(r+8)*LA + c) =
                __floats2half2_rn((acc[mt][nt][2]-1.f)*IE, (acc[mt][nt][3]-1.f)*IE);
        }
    }
}

// ---------------- bf16 pi GEMM (double-buffered, exp on the fly, fused resid/S) ----------------
__global__ __launch_bounds__(256) void pi_mma(
        const __half* __restrict__ logK, const float* __restrict__ lu,
        const float* __restrict__ lv, const __nv_bfloat16* __restrict__ ApT,
        const float* __restrict__ Tp, float* __restrict__ S, float* __restrict__ resid)
{
    int b = blockIdx.z;
    const __half* LKb = logK + (size_t)b*LT*LA;
    const float* lub = lu + (size_t)b*LT;
    const float* lvb = lv + (size_t)b*LA;
    const __nv_bfloat16* Bb = ApT + (size_t)b*Dm*LA;
    const float* Tpb = Tp + (size_t)b*LT*Dm;
    float* Rb = resid + (size_t)b*LT*Dm;
    float* Sb = S + (size_t)b*LT;
    int m0 = blockIdx.x*128, n0 = blockIdx.y*128;

    __shared__ __align__(16) __nv_bfloat16 As[2][128*40];
    __shared__ __align__(16) __nv_bfloat16 Bs[2][128*40];

    int tid = threadIdx.x;
    int warp = tid >> 5, lane = tid & 31;
    int g = lane >> 2, tig = lane & 3;
    int wm = warp >> 2, wn = warp & 3;
    int r8 = lane & 7, grp = lane >> 3;

    float acc[4][4][4];
    #pragma unroll
    for(int i=0;i<4;i++) for(int j=0;j<4;j++) for(int q=0;q<4;q++) acc[i][j][q]=0.f;

    int lr = tid >> 2, lc = tid & 3;
    const __half* Lg0 = LKb + (size_t)(m0+lr)*LA + lc*8;
    const __half* Lg1 = LKb + (size_t)(m0+lr+64)*LA + lc*8;
    const __nv_bfloat16* Bg0 = Bb + (size_t)(n0+lr)*LA + lc*8;
    const __nv_bfloat16* Bg1 = Bb + (size_t)(n0+lr+64)*LA + lc*8;
    float lur0 = lub[m0+lr], lur1 = lub[m0+lr+64];

    uint4 ra0 = *(const uint4*)(Lg0), ra1 = *(const uint4*)(Lg1);
    uint4 pb0 = *(const uint4*)(Bg0), pb1 = *(const uint4*)(Bg1);

    {
        const __half* hp0 = (const __half*)&ra0;
        const __half* hp1 = (const __half*)&ra1;
        uint4 o0, o1;
        __nv_bfloat16* ob0 = (__nv_bfloat16*)&o0;
        __nv_bfloat16* ob1 = (__nv_bfloat16*)&o1;
        #pragma unroll
        for (int j=0;j<8;j++){
            float lvj = lvb[lc*8 + j];
            float p0 = __expf(__half2float(hp0[j]) + lur0 + lvj);
            float p1 = __expf(__half2float(hp1[j]) + lur1 + lvj);
            if (isinf(p0)) p0 = 1.f;
            if (isinf(p1)) p1 = 1.f;
            ob0[j] = __float2bfloat16(p0);
            ob1[j] = __float2bfloat16(p1);
        }
        *(uint4*)(As[0] + lr*40 + lc*8)      = o0;
        *(uint4*)(As[0] + (lr+64)*40 + lc*8) = o1;
        *(uint4*)(Bs[0] + lr*40 + lc*8)      = pb0;
        *(uint4*)(Bs[0] + (lr+64)*40 + lc*8) = pb1;
    }
    __syncthreads();

    for (int k0 = 0; k0 < LA; k0 += 32){
        int cur = (k0 >> 5) & 1;
        bool more = (k0 + 32 < LA);
        if (more){
            ra0 = *(const uint4*)(Lg0 + k0+32);
            ra1 = *(const uint4*)(Lg1 + k0+32);
            pb0 = *(const uint4*)(Bg0 + k0+32);
            pb1 = *(const uint4*)(Bg1 + k0+32);
        }
        #pragma unroll
        for (int kk2=0; kk2<2; kk2++){
            unsigned a[4][4], bf[4][2];
            #pragma unroll
            for (int mt=0; mt<4; mt++){
                int mrow = wm*64 + mt*16 + (grp&1)*8 + r8;
                unsigned ad = sptr(As[cur] + mrow*40 + kk2*16 + (grp>>1)*8);
                ldmx4(a[mt][0], a[mt][1], a[mt][2], a[mt][3], ad);
            }
            #pragma unroll
            for (int p=0; p<2; p++){
                int nrow = wn*32 + (p*2 + (grp>>1))*8 + r8;
                unsigned ad = sptr(Bs[cur] + nrow*40 + kk2*16 + (grp&1)*8);
                ldmx4(bf[p*2][0], bf[p*2][1], bf[p*2+1][0], bf[p*2+1][1], ad);
            }
            #pragma unroll
            for (int mt=0; mt<4; mt++)
                #pragma unroll
                for (int nt=0; nt<4; nt++)
                    mma_bf16(acc[mt][nt], a[mt], bf[nt]);
        }
        if (more){
            int nxt = cur ^ 1;
            const __half* hp0 = (const __half*)&ra0;
            const __half* hp1 = (const __half*)&ra1;
            uint4 o0, o1;
            __nv_bfloat16* ob0 = (__nv_bfloat16*)&o0;
            __nv_bfloat16* ob1 = (__nv_bfloat16*)&o1;
            #pragma unroll
            for (int j=0;j<8;j++){
                float lvj = lvb[k0+32 + lc*8 + j];
                float p0 = __expf(__half2float(hp0[j]) + lur0 + lvj);
                float p1 = __expf(__half2float(hp1[j]) + lur1 + lvj);
                if (isinf(p0)) p0 = 1.f;
                if (isinf(p1)) p1 = 1.f;
                ob0[j] = __float2bfloat16(p0);
                ob1[j] = __float2bfloat16(p1);
            }
            *(uint4*)(As[nxt] + lr*40 + lc*8)      = o0;
            *(uint4*)(As[nxt] + (lr+64)*40 + lc*8) = o1;
            *(uint4*)(Bs[nxt] + lr*40 + lc*8)      = pb0;
            *(uint4*)(Bs[nxt] + (lr+64)*40 + lc*8) = pb1;
        }
        __syncthreads();
    }
    #pragma unroll
    for (int mt=0; mt<4; mt++){
        int r = m0 + wm*64 + mt*16 + g;
        float ps0 = 0.f, ps1 = 0.f;
        #pragma unroll
        for (int nt=0; nt<4; nt++){
            int c = n0 + wn*32 + nt*8 + tig*2;
            float2 t0 = *(const float2*)(Tpb + (size_t)r*Dm + c);
            float2 t1 = *(const float2*)(Tpb + (size_t)(r+8)*Dm + c);
            ps0 += t0.x*acc[mt][nt][0] + t0.y*acc[mt][nt][1];
            ps1 += t1.x*acc[mt][nt][2] + t1.y*acc[mt][nt][3];
            *(float2*)(Rb + (size_t)r*Dm + c) =
                make_float2(fabsf(t0.x-acc[mt][nt][0]), fabsf(t0.y-acc[mt][nt][1]));
            *(float2*)(Rb + (size_t)(r+8)*Dm + c) =
                make_float2(fabsf(t1.x-acc[mt][nt][2]), fabsf(t1.y-acc[mt][nt][3]));
        }
        ps0 += __shfl_xor_sync(0xffffffffu, ps0, 1);
        ps0 += __shfl_xor_sync(0xffffffffu, ps0, 2);
        ps1 += __shfl_xor_sync(0xffffffffu, ps1, 1);
        ps1 += __shfl_xor_sync(0xffffffffu, ps1, 2);
        if (tig == 0){
            atomicAdd(&Sb[r], ps0);
            atomicAdd(&Sb[r+8], ps1);
        }
    }
}

// ---------------- Sinkhorn: row LSE -> lu (warp per row, shuffle-only, MLP=8) ----------------
// grid (LT/8, Bt), block 256
__global__ __launch_bounds__(256) void sink_row(const __half* __restrict__ logK,
        const float* __restrict__ lv, float* __restrict__ lu){
    int b = blockIdx.y;
    int m = blockIdx.x*8 + (threadIdx.x >> 5);
    int lane = threadIdx.x & 31;
    const uint4* row = (const uint4*)(logK + ((size_t)b*LT + m)*LA);
    const float4* lv4 = (const float4*)(lv + (size_t)b*LA);
    uint4 raw[8];
    #pragma unroll
    for (int i=0;i<8;i++) raw[i] = row[lane + 32*i];
    // pass 1: max
    float mx = -INFINITY;
    #pragma unroll
    for (int i=0;i<8;i++){
        const __half* hp = (const __half*)&raw[i];
        float4 l0 = lv4[(lane + 32*i)*2];
        float4 l1 = lv4[(lane + 32*i)*2 + 1];
        mx = fmaxf(mx, __half2float(hp[0])+l0.x);
        mx = fmaxf(mx, __half2float(hp[1])+l0.y);
        mx = fmaxf(mx, __half2float(hp[2])+l0.z);
        mx = fmaxf(mx, __half2float(hp[3])+l0.w);
        mx = fmaxf(mx, __half2float(hp[4])+l1.x);
        mx = fmaxf(mx, __half2float(hp[5])+l1.y);
        mx = fmaxf(mx, __half2float(hp[6])+l1.z);
        mx = fmaxf(mx, __half2float(hp[7])+l1.w);
    }
    mx = warpReduceMax(mx);
    // pass 2: sum of exps (lv re-read from L1)
    float s = 0.f;
    #pragma unroll
    for (int i=0;i<8;i++){
        const __half* hp = (const __half*)&raw[i];
        float4 l0 = lv4[(lane + 32*i)*2];
        float4 l1 = lv4[(lane + 32*i)*2 + 1];
        s += __expf(__half2float(hp[0])+l0.x - mx);
        s += __expf(__half2float(hp[1])+l0.y - mx);
        s += __expf(__half2float(hp[2])+l0.z - mx);
        s += __expf(__half2float(hp[3])+l0.w - mx);
        s += __expf(__half2float(hp[4])+l1.x - mx);
        s += __expf(__half2float(hp[5])+l1.y - mx);
        s += __expf(__half2float(hp[6])+l1.z - mx);
        s += __expf(__half2float(hp[7])+l1.w - mx);
    }
    s = warpReduceSum(s);
    if (lane==0){
        const float LOG_MU = -6.93147180559945f;
        lu[(size_t)b*LT + m] = clip_nan(LOG_MU - (mx + __logf(s)));
    }
}

// ---------------- Sinkhorn: column LSE -> lv (8x row unroll) ----------------
__global__ void sink_col(const __half* __restrict__ logK,
        const float* __restrict__ lu, float* __restrict__ lv){
    int b = blockIdx.y;
    int tx = threadIdx.x, ty = threadIdx.y;
    int c2 = blockIdx.x*32 + tx;
    const __half2* base = (const __half2*)(logK + (size_t)b*LT*LA);
    const float* lub  = lu + (size_t)b*LT;
    float mx0=-INFINITY, s0=0.f, mx1=-INFINITY, s1=0.f;
    for (int m = ty; m < LT; m += 64){
        __half2 h[8];
        float l[8];
        #pragma unroll
        for (int i=0;i<8;i++){
            h[i] = base[(size_t)(m+8*i)*(LA/2) + c2];
            l[i] = lub[m+8*i];
        }
        #pragma unroll
        for (int i=0;i<8;i++){
            float2 f = __half22float2(h[i]);
            float v0 = f.x + l[i], v1 = f.y + l[i];
            if (v0 > mx0){ s0 = s0*__expf(mx0-v0) + 1.f; mx0 = v0; } else s0 += __expf(v0-mx0);
            if (v1 > mx1){ s1 = s1*__expf(mx1-v1) + 1.f; mx1 = v1; } else s1 += __expf(v1-mx1);
        }
    }
    __shared__ float smx[8][64], ss[8][64];
    smx[ty][tx*2]=mx0; ss[ty][tx*2]=s0;
    smx[ty][tx*2+1]=mx1; ss[ty][tx*2+1]=s1;
    __syncthreads();
    for (int off=4; off>=1; off>>=1){
        if (ty < off){
            #pragma unroll
            for (int w=0; w<2; w++){
                int cc = tx*2+w;
                float m1=smx[ty][cc], sa=ss[ty][cc];
                float m2=smx[ty+off][cc], sb=ss[ty+off][cc];
                float M = fmaxf(m1,m2);
                float Sv = sa*__expf(m1-M) + sb*__expf(m2-M);
                smx[ty][cc]=M; ss[ty][cc]=Sv;
            }
        }
        __syncthreads();
    }
    if (ty==0){
        const float LOG_NU = -7.62461898616078f;
        #pragma unroll
        for (int w=0; w<2; w++){
            int cc = tx*2+w;
            lv[(size_t)b*LA + c2*2 + w] = clip_nan(LOG_NU - (smx[0][cc] + __logf(ss[0][cc])));
        }
    }
}

// ---------------- router logits + softmax (warp per row) ----------------
__global__ __launch_bounds__(256) void router_out_kernel(const float* __restrict__ h1,
        const float* __restrict__ Wr2, const float* __restrict__ br2, float* __restrict__ G){
    size_t row = (size_t)blockIdx.x*8 + (threadIdx.x >> 5);
    int lane = threadIdx.x & 31;
    const float* hr = h1 + row*Dm;
    float4 v1 = *(const float4*)(hr + lane*4);
    float4 v2 = *(const float4*)(hr + 128 + lane*4);
    float l[3];
    #pragma unroll
    for (int e=0;e<3;e++){
        const float* w = Wr2 + e*Dm;
        float4 w1 = *(const float4*)(w + lane*4);
        float4 w2 = *(const float4*)(w + 128 + lane*4);
        float s = v1.x*w1.x+v1.y*w1.y+v1.z*w1.z+v1.w*w1.w
                + v2.x*w2.x+v2.y*w2.y+v2.z*w2.z+v2.w*w2.w;
        l[e] = warpReduceSum(s);
    }
    if (lane==0){
        float a0=l[0]+br2[0], a1=l[1]+br2[1], a2=l[2]+br2[2];
        float m = fmaxf(a0, fmaxf(a1,a2));
        float e0=__expf(a0-m), e1=__expf(a1-m), e2=__expf(a2-m);
        float inv = 1.f/(e0+e1+e2);
        G[row*3+0]=e0*inv; G[row*3+1]=e1*inv; G[row*3+2]=e2*inv;
    }
}

// ---------------- multi-scale conv (one kernel, block-level dispatch) ----------------
template<int KSZ>
__device__ __forceinline__ void conv_body(const float* __restrict__ h,
        const float* __restrict__ w, const float* __restrict__ conv_b,
        float* __restrict__ h2, int e, float (*hs)[64], float* ws)
{
    const int pad = (KSZ-1)/2;
    int tile = blockIdx.x*64;
    int l0 = tile & (LT-1);
    int tid = threadIdx.x;
    for (int idx = tid; idx < 68*64; idx += 256){
        int lr = idx >> 6; int i = idx & 63;
        int l = l0 + lr - 2;
        float v = 0.f;
        if (l >= 0 && l < LT) v = h[(size_t)(tile - l0 + l)*(NE*Rr) + e*Rr + i];
        hs[lr][i] = v;
    }
    float acc[16];
    #pragma unroll
    for (int j=0;j<16;j++) acc[j]=0.f;
    int o = tid & 63;
    int lg = tid >> 6;
    for (int ic = 0; ic < Rr; ic += 16){
        __syncthreads();
        for (int idx = tid; idx < 16*KSZ*64; idx += 256){
            int oo = idx & 63; int r = idx >> 6;
            int t = r % KSZ; int ii = r / KSZ;
            ws[idx] = w[(size_t)oo*Rr*KSZ + (ic+ii)*KSZ + t];
        }
        __syncthreads();
        #pragma unroll
        for (int ii = 0; ii < 16; ii++){
            #pragma unroll
            for (int t = 0; t < KSZ; t++){
                float wv = ws[(ii*KSZ + t)*64 + o];
                int roff = 2 + t - pad;
                #pragma unroll
                for (int j = 0; j < 16; j++){
                    acc[j] += hs[lg*16 + j + roff][ic + ii] * wv;
                }
            }
        }
    }
    float bo = conv_b[e*Rr + o];
    #pragma unroll
    for (int j=0;j<16;j++){
        int l = lg*16 + j;
        h2[(size_t)(tile + l)*(NE*Rr) + e*Rr + o] = geluf(acc[j] + bo);
    }
}

__global__ __launch_bounds__(256) void conv_all(const float* __restrict__ h,
        const float* __restrict__ w1, const float* __restrict__ w3,
        const float* __restrict__ w5, const float* __restrict__ conv_b,
        float* __restrict__ h2)
{
    __shared__ float hs[68][64];
    __shared__ float ws[16*5*64];
    int e = blockIdx.y;
    if (e == 0)      conv_body<1>(h, w1, conv_b, h2, 0, hs, ws);
    else if (e == 1) conv_body<3>(h, w3, conv_b, h2, 1, hs, ws);
    else             conv_body<5>(h, w5, conv_b, h2, 2, hs, ws);
}

// ---------------- final (warp per row): gated sum of per-expert LN (u in bf16) ----------------
__global__ __launch_bounds__(256) void final_kernel(const __nv_bfloat16* __restrict__ u,
        const float* __restrict__ resid, const float* __restrict__ G,
        const float* __restrict__ en_g, const float* __restrict__ en_b,
        float* __restrict__ out)
{
    size_t row = (size_t)blockIdx.x*8 + (threadIdx.x >> 5);
    int lane = threadIdx.x & 31;
    const float* rr = resid + row*Dm;
    float4 r1 = *(const float4*)(rr + lane*4);
    float4 r2 = *(const float4*)(rr + 128 + lane*4);
    float4 o1 = make_float4(0,0,0,0), o2 = make_float4(0,0,0,0);
    #pragma unroll
    for (int e=0;e<3;e++){
        const __nv_bfloat16* ur = u + ((size_t)e*ROWS_T + row)*Dm;
        uint2 up1 = *(const uint2*)(ur + lane*4);
        uint2 up2 = *(const uint2*)(ur + 128 + lane*4);
        float2 ua = __bfloat1622float2(*(__nv_bfloat162*)&up1.x);
        float2 ub = __bfloat1622float2(*(__nv_bfloat162*)&up1.y);
        float2 uc = __bfloat1622float2(*(__nv_bfloat162*)&up2.x);
        float2 ud = __bfloat1622float2(*(__nv_bfloat162*)&up2.y);
        float y0=ua.x+r1.x, y1=ua.y+r1.y, y2=ub.x+r1.z, y3=ub.y+r1.w;
        float z0=uc.x+r2.x, z1=uc.y+r2.y, z2=ud.x+r2.z, z3=ud.y+r2.w;
        float mean = warpReduceSum(y0+y1+y2+y3+z0+z1+z2+z3) * (1.f/Dm);
        y0-=mean;y1-=mean;y2-=mean;y3-=mean;z0-=mean;z1-=mean;z2-=mean;z3-=mean;
        float var = warpReduceSum(y0*y0+y1*y1+y2*y2+y3*y3+z0*z0+z1*z1+z2*z2+z3*z3) * (1.f/Dm);
        float rstd = rsqrtf(var + 1e-5f);
        float gw = G[row*3+e];
        const float* eg = en_g + e*Dm;
        const float* eb = en_b + e*Dm;
        float4 g1 = *(const float4*)(eg + lane*4);
        float4 g2 = *(const float4*)(eg + 128 + lane*4);
        float4 b1 = *(const float4*)(eb + lane*4);
        float4 b2 = *(const float4*)(eb + 128 + lane*4);
        o1.x += gw*(y0*rstd*g1.x + b1.x); o1.y += gw*(y1*rstd*g1.y + b1.y);
        o1.z += gw*(y2*rstd*g1.z + b1.z); o1.w += gw*(y3*rstd*g1.w + b1.w);
        o2.x += gw*(z0*rstd*g2.x + b2.x); o2.y += gw*(z1*rstd*g2.y + b2.y);
        o2.z += gw*(z2*rstd*g2.z + b2.z); o2.w += gw*(z3*rstd*g2.w + b2.w);
    }
    float* orow = out + row*Dm;
    *(float4*)(orow + lane*4) = o1;
    *(float4*)(orow + 128 + lane*4) = o2;
}

// ---------------- host launcher ----------------
extern "C" void kernel_launch(void* const* d_in, const int* in_sizes, int n_in,
                              void* d_out, int out_size)
{
    const float* text   = (const float*)d_in[0];
    const float* audio  = (const float*)d_in[1];
    const float* ln_g   = (const float*)d_in[2];
    const float* ln_b   = (const float*)d_in[3];
    const float* W_sh   = (const float*)d_in[4];
    const float* b_sh   = (const float*)d_in[5];
    const float* Wr1    = (const float*)d_in[6];
    const float* br1    = (const float*)d_in[7];
    const float* Wr2    = (const float*)d_in[8];
    const float* br2    = (const float*)d_in[9];
    const float* down_W = (const float*)d_in[10];
    const float* down_b = (const float*)d_in[11];
    const float* conv_w1= (const float*)d_in[12];
    const float* conv_w3= (const float*)d_in[13];
    const float* conv_w5= (const float*)d_in[14];
    const float* conv_b = (const float*)d_in[15];
    const float* up_W   = (const float*)d_in[16];
    const float* up_b   = (const float*)d_in[17];
    const float* en_g   = (const float*)d_in[18];
    const float* en_b   = (const float*)d_in[19];
    float* out = (float*)d_out;

    void *p;
    cudaGetSymbolAddress(&p, g_stats); float2* stats = (float2*)p;
    cudaGetSymbolAddress(&p, g_Tp);   float* Tp  = (float*)p;
    cudaGetSymbolAddress(&p, g_Ap);   float* Ap  = (float*)p;
    cudaGetSymbolAddress(&p, g_Tn);   __nv_bfloat16* Tn = (__nv_bfloat16*)p;
    cudaGetSymbolAddress(&p, g_An);   __nv_bfloat16* An = (__nv_bfloat16*)p;
    cudaGetSymbolAddress(&p, g_ApT);  __nv_bfloat16* ApT = (__nv_bfloat16*)p;
    cudaGetSymbolAddress(&p, g_logK); __half* logK = (__half*)p;
    cudaGetSymbolAddress(&p, g_lu);   float* lu = (float*)p;
    cudaGetSymbolAddress(&p, g_lv);   float* lv = (float*)p;
    cudaGetSymbolAddress(&p, g_S);    float* S = (float*)p;
    cudaGetSymbolAddress(&p, g_resid);float* resid = (float*)p;
    cudaGetSymbolAddress(&p, g_h1);   float* h1 = (float*)p;
    cudaGetSymbolAddress(&p, g_G);    float* G = (float*)p;
    cudaGetSymbolAddress(&p, g_h);    float* h = (float*)p;
    cudaGetSymbolAddress(&p, g_h2);   float* h2 = (float*)p;
    cudaGetSymbolAddress(&p, g_u);    __nv_bfloat16* u = (__nv_bfloat16*)p;

    zero_lulv<<<128,256>>>(lu, lv, S);

    // LN stats (warp per row)
    ln_stats<<<(ROWS_T + ROWS_A)/8, 256>>>(text, audio, stats);

    // text+audio projections with fused LN in ONE launch (tf32 + ldmatrix + prefetch)
    gemm_tf32<0,true,false><<<dim3((ROWS_T+ROWS_A)/128, Dm/64, 1),256>>>(
            text, Dm, 0, W_sh, Dm, 0, Tp, Dm, 0, Dm, b_sh, 0,
            stats, ln_g, ln_b, nullptr, nullptr, 0,
            audio, Ap, stats + ROWS_T, ROWS_T/128);

    norm_bf16_kernel<<<ROWS_T/8,256>>>(Tp, Tn);
    audio_norm_T<<<dim3(LA/32, Bt), 256>>>(Ap, An, ApT);

    // cost -> logK (fp16) via bf16 tensor cores (double-buffered)
    cost_mma<<<dim3(LT/128, LA/128, Bt),256>>>(Tn, An, logK);

    // Sinkhorn (fp16 logK, L2-resident)
    for (int it=0; it<10; ++it){
        sink_row<<<dim3(LT/8, Bt),256>>>(logK, lv, lu);
        sink_col<<<dim3(LA/64, Bt), dim3(32,8)>>>(logK, lu, lv);
    }

    // pi GEMM with fused resid/S epilogue (double-buffered)
    pi_mma<<<dim3(LT/128, Dm/128, Bt),256>>>(logK, lu, lv, ApT, Tp, S, resid);

    // router hidden
    gemm_tf32<1,false,false><<<dim3(ROWS_T/128, Dm/64, 1),256>>>(resid, Dm, 0, Wr1+1, Dm+1, 0,
            h1, Dm, 0, Dm, br1, 0, nullptr, nullptr, nullptr, S, Wr1, Dm+1,
            nullptr, nullptr, nullptr, 1<<30);
    router_out_kernel<<<ROWS_T/8,256>>>(h1, Wr2, br2, G);

    // experts
    gemm_tf32<2,false,false><<<dim3(ROWS_T/128, (NE*Rr)/64, 1),256>>>(resid, Dm, 0, down_W, Dm, 0,
            h, NE*Rr, 0, Dm, down_b, 0, nullptr, nullptr, nullptr, nullptr, nullptr, 0,
            nullptr, nullptr, nullptr, 1<<30);
    conv_all<<<dim3(ROWS_T/64, NE),256>>>(h, conv_w1, conv_w3, conv_w5, conv_b, h2);
    gemm_tf32<0,false,true><<<dim3(ROWS_T/128, Dm/64, NE),256>>>(h2, NE*Rr, (long long)Rr,
            up_W, Rr, (long long)Dm*Rr, u, Dm, (long long)ROWS_T*Dm,
            Rr, up_b, Dm, nullptr, nullptr, nullptr, nullptr, nullptr, 0,
            nullptr, nullptr, nullptr, 1<<30);

    final_kernel<<<ROWS_T/8,256>>>(u, resid, G, en_g, en_b, out);
}

// round 16
// speedup vs baseline: 1.0603x; 1.0071x over previous
#include <cuda_runtime.h>
#include <cuda_bf16.h>
#include <cuda_fp16.h>
#include <math.h>

#define Bt 16
#define LT 1024
#define LA 2048
#define Dm 256
#define Rr 64
#define NE 3
#define ROWS_T (Bt*LT)   // 16384
#define ROWS_A (Bt*LA)   // 32768

// ---------------- scratch ----------------
__device__ float2 g_stats[ROWS_T + ROWS_A];
__device__ float g_Tp [(size_t)ROWS_T*Dm];
__device__ float g_Ap [(size_t)ROWS_A*Dm];
__device__ __nv_bfloat16 g_Tn [(size_t)ROWS_T*Dm];
__device__ __nv_bfloat16 g_An [(size_t)ROWS_A*Dm];
__device__ __nv_bfloat16 g_ApT[(size_t)Bt*Dm*LA];
__device__ __half g_logK[(size_t)Bt*LT*LA];
__device__ float g_lu[ROWS_T];
__device__ float g_lv[ROWS_A];
__device__ float g_S[ROWS_T];
__device__ float g_resid[(size_t)ROWS_T*Dm];
__device__ float g_h1[(size_t)ROWS_T*Dm];
__device__ float g_G[ROWS_T*NE];
__device__ float g_h [(size_t)ROWS_T*NE*Rr];
__device__ float g_h2[(size_t)ROWS_T*NE*Rr];
__device__ __nv_bfloat16 g_u [(size_t)NE*ROWS_T*Dm];

// ---------------- helpers ----------------
__device__ __forceinline__ float geluf(float x){
    return 0.5f*x*(1.0f+erff(x*0.7071067811865476f));
}
__device__ __forceinline__ float warpReduceSum(float v){
    #pragma unroll
    for(int o=16;o;o>>=1) v += __shfl_xor_sync(0xffffffffu, v, o);
    return v;
}
__device__ __forceinline__ float warpReduceMax(float v){
    #pragma unroll
    for(int o=16;o;o>>=1) v = fmaxf(v, __shfl_xor_sync(0xffffffffu, v, o));
    return v;
}
__device__ __forceinline__ float clip_nan(float l){
    if (isnan(l)) return 0.f;
    return fminf(fmaxf(l, -1e9f), 1e9f);
}

__device__ __forceinline__ void mma_bf16(float* c, const unsigned* a, const unsigned* b){
    asm volatile("mma.sync.aligned.m16n8k16.row.col.f32.bf16.bf16.f32 "
        "{%0,%1,%2,%3}, {%4,%5,%6,%7}, {%8,%9}, {%0,%1,%2,%3};"
        : "+f"(c[0]), "+f"(c[1]), "+f"(c[2]), "+f"(c[3])
        : "r"(a[0]), "r"(a[1]), "r"(a[2]), "r"(a[3]), "r"(b[0]), "r"(b[1]));
}
__device__ __forceinline__ void mma_tf32(float* c, const unsigned* a, const unsigned* b){
    asm volatile("mma.sync.aligned.m16n8k8.row.col.f32.tf32.tf32.f32 "
        "{%0,%1,%2,%3}, {%4,%5,%6,%7}, {%8,%9}, {%0,%1,%2,%3};"
        : "+f"(c[0]), "+f"(c[1]), "+f"(c[2]), "+f"(c[3])
        : "r"(a[0]), "r"(a[1]), "r"(a[2]), "r"(a[3]), "r"(b[0]), "r"(b[1]));
}
__device__ __forceinline__ unsigned f2tf32(float f){
    unsigned r; asm("cvt.rna.tf32.f32 %0, %1;" : "=r"(r) : "f"(f)); return r;
}
__device__ __forceinline__ unsigned sptr(const void* p){
    return (unsigned)__cvta_generic_to_shared(p);
}
__device__ __forceinline__ void ldmx4(unsigned &r0, unsigned &r1, unsigned &r2, unsigned &r3, unsigned a){
    asm volatile("ldmatrix.sync.aligned.m8n8.x4.shared.b16 {%0,%1,%2,%3}, [%4];"
        : "=r"(r0), "=r"(r1), "=r"(r2), "=r"(r3) : "r"(a));
}

// ---------------- init ----------------
__global__ void zero_lulv(float* lu, float* lv, float* S){
    int i = blockIdx.x*256 + threadIdx.x;
    if (i < ROWS_T){ lu[i] = 0.f; S[i] = 0.f; }
    if (i < ROWS_A) lv[i] = 0.f;
}

// ---------------- LN stats (warp per row) ----------------
__global__ __launch_bounds__(256) void ln_stats(const float* __restrict__ text,
        const float* __restrict__ audio, float2* __restrict__ stats){
    size_t row = (size_t)blockIdx.x*8 + (threadIdx.x >> 5);
    int lane = threadIdx.x & 31;
    const float* x = (row < ROWS_T) ? (text + row*Dm) : (audio + (row-ROWS_T)*Dm);
    float4 v1 = *(const float4*)(x + lane*4);
    float4 v2 = *(const float4*)(x + 128 + lane*4);
    float s = v1.x+v1.y+v1.z+v1.w + v2.x+v2.y+v2.z+v2.w;
    float mean = warpReduceSum(s) * (1.f/Dm);
    float d0=v1.x-mean,d1=v1.y-mean,d2=v1.z-mean,d3=v1.w-mean;
    float e0=v2.x-mean,e1=v2.y-mean,e2=v2.z-mean,e3=v2.w-mean;
    float var = warpReduceSum(d0*d0+d1*d1+d2*d2+d3*d3+e0*e0+e1*e1+e2*e2+e3*e3) * (1.f/Dm);
    if (lane==0) stats[row] = make_float2(mean, rsqrtf(var + 1e-5f));
}

// ---------------- text: unit-norm rows -> bf16 (warp per row) ----------------
__global__ __launch_bounds__(256) void norm_bf16_kernel(const float* __restrict__ x,
        __nv_bfloat16* __restrict__ y){
    size_t row = (size_t)blockIdx.x*8 + (threadIdx.x >> 5);
    int lane = threadIdx.x & 31;
    const float* xr = x + row*Dm;
    float4 v1 = *(const float4*)(xr + lane*4);
    float4 v2 = *(const float4*)(xr + 128 + lane*4);
    float s = v1.x*v1.x+v1.y*v1.y+v1.z*v1.z+v1.w*v1.w
            + v2.x*v2.x+v2.y*v2.y+v2.z*v2.z+v2.w*v2.w;
    float inv = 1.f / fmaxf(sqrtf(warpReduceSum(s)), 1e-12f);
    __nv_bfloat162 p0 = {__float2bfloat16(v1.x*inv), __float2bfloat16(v1.y*inv)};
    __nv_bfloat162 p1 = {__float2bfloat16(v1.z*inv), __float2bfloat16(v1.w*inv)};
    __nv_bfloat162 q0 = {__float2bfloat16(v2.x*inv), __float2bfloat16(v2.y*inv)};
    __nv_bfloat162 q1 = {__float2bfloat16(v2.z*inv), __float2bfloat16(v2.w*inv)};
    *(uint2*)(y + row*Dm + lane*4) = make_uint2(*(unsigned*)&p0, *(unsigned*)&p1);
    *(uint2*)(y + row*Dm + 128 + lane*4) = make_uint2(*(unsigned*)&q0, *(unsigned*)&q1);
}

// ---------------- audio: unit-norm -> An (bf16) + transposed ApT (bf16) ----------------
__global__ __launch_bounds__(256) void audio_norm_T(const float* __restrict__ Ap,
        __nv_bfloat16* __restrict__ An, __nv_bfloat16* __restrict__ ApT){
    __shared__ float tile[32][257];
    __shared__ float invs[32];
    int b = blockIdx.y;
    int n0 = blockIdx.x*32;
    const float* src = Ap + ((size_t)b*LA + n0)*Dm;
    int tid = threadIdx.x;
    for (int i = tid; i < 32*256; i += 256)
        tile[i>>8][i&255] = src[i];
    __syncthreads();
    int w = tid>>5, lane = tid&31;
    for (int rr = 0; rr < 4; rr++){
        int row = w*4 + rr;
        float s = 0.f;
        #pragma unroll
        for (int j=0;j<8;j++){
            float v = tile[row][lane*8 + j];
            s += v*v;
        }
        s = warpReduceSum(s);
        if (lane==0) invs[row] = 1.f / fmaxf(sqrtf(s), 1e-12f);
    }
    __syncthreads();
    __nv_bfloat16* dstA = An + ((size_t)b*LA + n0)*Dm;
    for (int i = tid; i < 32*256; i += 256){
        int row = i>>8;
        dstA[i] = __float2bfloat16(tile[row][i&255] * invs[row]);
    }
    float inv = invs[lane];
    __nv_bfloat16* dstT = ApT + (size_t)b*Dm*LA + n0;
    for (int it = 0; it < 32; it++){
        int d = it*8 + w;
        dstT[(size_t)d*LA + lane] = __float2bfloat16(tile[lane][d] * inv);
    }
}

// ---------------- tf32 tensor-core GEMM (ldmatrix + register prefetch, dual-input) ----------------
template<int EPI, bool FUSE_LN, bool OUT_BF16>
__global__ __launch_bounds__(256) void gemm_tf32(
        const float* __restrict__ A, int lda, long long bsA,
        const float* __restrict__ B, int ldb, long long bsB,
        void* __restrict__ Cv, int ldc, long long bsC,
        int K,
        const float* __restrict__ bias, long long bsBias,
        const float2* __restrict__ stats,
        const float* __restrict__ lng, const float* __restrict__ lnb,
        const float* __restrict__ rowv, const float* __restrict__ colv, int colvStride,
        const float* __restrict__ A2, void* __restrict__ Cv2,
        const float2* __restrict__ stats2, int blocksA)
{
    long long bz = blockIdx.z;
    int bx = blockIdx.x;
    if (A2 && bx >= blocksA){
        A = A2; Cv = Cv2; stats = stats2;
        bx -= blocksA;
    }
    A += bz*bsA; B += bz*bsB;
    if (bias) bias += bz*bsBias;
    int M0 = bx*128, N0 = blockIdx.y*64;

    __shared__ __align__(16) unsigned As[128][36];
    __shared__ __align__(16) unsigned Bs[64][36];
    __shared__ float2 st[128];
    __shared__ float gAll[256], bAll[256];

    int tid = threadIdx.x;
    int warp = tid >> 5, lane = tid & 31;
    int g = lane >> 2, tig = lane & 3;
    int wm = warp >> 1, wn = warp & 1;
    int r8 = lane & 7, grp = lane >> 3;

    if (FUSE_LN){
        if (tid < 128) st[tid] = stats[M0 + tid];
        for (int i = tid; i < K; i += 256){ gAll[i] = lng[i]; bAll[i] = lnb[i]; }
    }

    float acc[2][4][4];
    #pragma unroll
    for(int i=0;i<2;i++) for(int j=0;j<4;j++) for(int q=0;q<4;q++) acc[i][j][q]=0.f;

    int ra = tid >> 1, kh = (tid & 1)*16;
    int rb = tid >> 2, kb = (tid & 3)*8;
    const float* Arow = A + (size_t)(M0+ra)*lda + kh;
    const float* Brow = B + (size_t)(N0+rb)*ldb + kb;

    float4 va[4];
    float vb[8];
    #pragma unroll
    for (int j=0;j<4;j++) va[j] = *(const float4*)(Arow + 4*j);
    #pragma unroll
    for (int j=0;j<8;j++) vb[j] = Brow[j];

    for (int k0 = 0; k0 < K; k0 += 32){
        __syncthreads();
        {
            float2 ms = FUSE_LN ? st[ra] : make_float2(0.f,0.f);
            #pragma unroll
            for (int j=0;j<4;j++){
                float e[4] = {va[j].x, va[j].y, va[j].z, va[j].w};
                unsigned o[4];
                #pragma unroll
                for (int c=0;c<4;c++){
                    if (FUSE_LN){
                        int kk = k0 + kh + 4*j + c;
                        e[c] = (e[c] - ms.x)*ms.y*gAll[kk] + bAll[kk];
                    }
                    o[c] = f2tf32(e[c]);
                }
                *(uint4*)&As[ra][kh + 4*j] = make_uint4(o[0],o[1],o[2],o[3]);
            }
            unsigned ob[8];
            #pragma unroll
            for (int j=0;j<8;j++) ob[j] = f2tf32(vb[j]);
            *(uint4*)&Bs[rb][kb]   = make_uint4(ob[0],ob[1],ob[2],ob[3]);
            *(uint4*)&Bs[rb][kb+4] = make_uint4(ob[4],ob[5],ob[6],ob[7]);
        }
        __syncthreads();
        if (k0 + 32 < K){
            #pragma unroll
            for (int j=0;j<4;j++) va[j] = *(const float4*)(Arow + k0+32 + 4*j);
            #pragma unroll
            for (int j=0;j<8;j++) vb[j] = Brow[k0+32 + j];
        }
        #pragma unroll
        for (int ks=0; ks<4; ks++){
            int k = ks*8;
            unsigned a[2][4], bf[4][2];
            #pragma unroll
            for (int mt=0; mt<2; mt++){
                unsigned ad = sptr(&As[wm*32 + mt*16 + (grp&1)*8 + r8][k + (grp>>1)*4]);
                ldmx4(a[mt][0], a[mt][1], a[mt][2], a[mt][3], ad);
            }
            #pragma unroll
            for (int p=0; p<2; p++){
                unsigned ad = sptr(&Bs[wn*32 + (p*2 + (grp>>1))*8 + r8][k + (grp&1)*4]);
                ldmx4(bf[p*2][0], bf[p*2][1], bf[p*2+1][0], bf[p*2+1][1], ad);
            }
            #pragma unroll
            for (int mt=0; mt<2; mt++)
                #pragma unroll
                for (int nt=0; nt<4; nt++)
                    mma_tf32(acc[mt][nt], a[mt], bf[nt]);
        }
    }

    #pragma unroll
    for (int mt=0; mt<2; mt++){
        #pragma unroll
        for (int nt=0; nt<4; nt++){
            int m = M0 + wm*32 + mt*16 + g;
            int n = N0 + wn*32 + nt*8 + tig*2;
            #pragma unroll
            for (int hrow=0; hrow<2; hrow++){
                int mm = m + hrow*8;
                float v0 = acc[mt][nt][hrow*2+0];
                float v1 = acc[mt][nt][hrow*2+1];
                if (EPI==0){ v0 += bias[n]; v1 += bias[n+1]; }
                if (EPI==1){
                    float rv = rowv[mm];
                    v0 = geluf(v0 + rv*colv[(size_t)n*colvStride] + bias[n]);
                    v1 = geluf(v1 + rv*colv[(size_t)(n+1)*colvStride] + bias[n+1]);
                }
                if (EPI==2){ v0 = geluf(v0 + bias[n]); v1 = geluf(v1 + bias[n+1]); }
                if (OUT_BF16){
                    __nv_bfloat16* C = (__nv_bfloat16*)Cv + bz*bsC;
                    __nv_bfloat162 pk = {__float2bfloat16(v0), __float2bfloat16(v1)};
                    *(__nv_bfloat162*)(C + (size_t)mm*ldc + n) = pk;
                } else {
                    float* C = (float*)Cv + bz*bsC;
                    *(float2*)(C + (size_t)mm*ldc + n) = make_float2(v0, v1);
                }
            }
        }
    }
}

// ---------------- dual GEMM: router (EPI1, y<4) + down (EPI2, y>=4) in one launch ----------------
__global__ __launch_bounds__(256) void gemm_dual(
        const float* __restrict__ Aresid,
        const float* __restrict__ Wr1p, const float* __restrict__ br1,
        const float* __restrict__ S, const float* __restrict__ Wr1full,
        float* __restrict__ h1,
        const float* __restrict__ downW, const float* __restrict__ downb,
        float* __restrict__ h)
{
    int by = blockIdx.y;
    bool isDown = (by >= 4);
    int yIdx = isDown ? by - 4 : by;
    const float* B = isDown ? downW : Wr1p;
    int ldb = isDown ? Dm : Dm+1;
    const float* bias = isDown ? downb : br1;
    float* C = isDown ? h : h1;
    int ldc = isDown ? NE*Rr : Dm;

    int M0 = blockIdx.x*128, N0 = yIdx*64;

    __shared__ __align__(16) unsigned As[128][36];
    __shared__ __align__(16) unsigned Bs[64][36];

    int tid = threadIdx.x;
    int warp = tid >> 5, lane = tid & 31;
    int g = lane >> 2, tig = lane & 3;
    int wm = warp >> 1, wn = warp & 1;
    int r8 = lane & 7, grp = lane >> 3;

    float acc[2][4][4];
    #pragma unroll
    for(int i=0;i<2;i++) for(int j=0;j<4;j++) for(int q=0;q<4;q++) acc[i][j][q]=0.f;

    int ra = tid >> 1, kh = (tid & 1)*16;
    int rb = tid >> 2, kb = (tid & 3)*8;
    const float* Arow = Aresid + (size_t)(M0+ra)*Dm + kh;
    const float* Brow = B + (size_t)(N0+rb)*ldb + kb;

    float4 va[4];
    float vb[8];
    #pragma unroll
    for (int j=0;j<4;j++) va[j] = *(const float4*)(Arow + 4*j);
    #pragma unroll
    for (int j=0;j<8;j++) vb[j] = Brow[j];

    for (int k0 = 0; k0 < Dm; k0 += 32){
        __syncthreads();
        {
            #pragma unroll
            for (int j=0;j<4;j++){
                unsigned o[4];
                o[0]=f2tf32(va[j].x); o[1]=f2tf32(va[j].y);
                o[2]=f2tf32(va[j].z); o[3]=f2tf32(va[j].w);
                *(uint4*)&As[ra][kh + 4*j] = make_uint4(o[0],o[1],o[2],o[3]);
            }
            unsigned ob[8];
            #pragma unroll
            for (int j=0;j<8;j++) ob[j] = f2tf32(vb[j]);
            *(uint4*)&Bs[rb][kb]   = make_uint4(ob[0],ob[1],ob[2],ob[3]);
            *(uint4*)&Bs[rb][kb+4] = make_uint4(ob[4],ob[5],ob[6],ob[7]);
        }
        __syncthreads();
        if (k0 + 32 < Dm){
            #pragma unroll
            for (int j=0;j<4;j++) va[j] = *(const float4*)(Arow + k0+32 + 4*j);
            #pragma unroll
            for (int j=0;j<8;j++) vb[j] = Brow[k0+32 + j];
        }
        #pragma unroll
        for (int ks=0; ks<4; ks++){
            int k = ks*8;
            unsigned a[2][4], bf[4][2];
            #pragma unroll
            for (int mt=0; mt<2; mt++){
                unsigned ad = sptr(&As[wm*32 + mt*16 + (grp&1)*8 + r8][k + (grp>>1)*4]);
                ldmx4(a[mt][0], a[mt][1], a[mt][2], a[mt][3], ad);
            }
            #pragma unroll
            for (int p=0; p<2; p++){
                unsigned ad = sptr(&Bs[wn*32 + (p*2 + (grp>>1))*8 + r8][k + (grp&1)*4]);
                ldmx4(bf[p*2][0], bf[p*2][1], bf[p*2+1][0], bf[p*2+1][1], ad);
            }
            #pragma unroll
            for (int mt=0; mt<2; mt++)
                #pragma unroll
                for (int nt=0; nt<4; nt++)
                    mma_tf32(acc[mt][nt], a[mt], bf[nt]);
        }
    }

    #pragma unroll
    for (int mt=0; mt<2; mt++){
        #pragma unroll
        for (int nt=0; nt<4; nt++){
            int m = M0 + wm*32 + mt*16 + g;
            int n = N0 + wn*32 + nt*8 + tig*2;
            #pragma unroll
            for (int hrow=0; hrow<2; hrow++){
                int mm = m + hrow*8;
                float v0 = acc[mt][nt][hrow*2+0];
                float v1 = acc[mt][nt][hrow*2+1];
                if (!isDown){
                    float rv = S[mm];
                    v0 = geluf(v0 + rv*Wr1full[(size_t)n*(Dm+1)] + bias[n]);
                    v1 = geluf(v1 + rv*Wr1full[(size_t)(n+1)*(Dm+1)] + bias[n+1]);
                } else {
                    v0 = geluf(v0 + bias[n]);
                    v1 = geluf(v1 + bias[n+1]);
                }
                *(float2*)(C + (size_t)mm*ldc + n) = make_float2(v0, v1);
            }
        }
    }
}

// ---------------- bf16 cost GEMM (double-buffered smem, one sync/iter) ----------------
__global__ __launch_bounds__(256) void cost_mma(
        const __nv_bfloat16* __restrict__ Tn, const __nv_bfloat16* __restrict__ An,
        __half* __restrict__ logK)
{
    const float IE = (float)(1.0/(0.1+1e-8));
    int b = blockIdx.z;
    const __nv_bfloat16* Ab = Tn + (size_t)b*LT*Dm;
    const __nv_bfloat16* Bb = An + (size_t)b*LA*Dm;
    __half* Cb = logK + (size_t)b*LT*LA;
    int m0 = blockIdx.x*128, n0 = blockIdx.y*128;

    __shared__ __align__(16) __nv_bfloat16 As[2][128*40];
    __shared__ __align__(16) __nv_bfloat16 Bs[2][128*40];

    int tid = threadIdx.x;
    int warp = tid >> 5, lane = tid & 31;
    int g = lane >> 2, tig = lane & 3;
    int wm = warp >> 2, wn = warp & 3;
    int r8 = lane & 7, grp = lane >> 3;

    float acc[4][4][4];
    #pragma unroll
    for(int i=0;i<4;i++) for(int j=0;j<4;j++) for(int q=0;q<4;q++) acc[i][j][q]=0.f;

    int lr = tid >> 2, lc = tid & 3;
    const __nv_bfloat16* Ag0 = Ab + (size_t)(m0+lr)*Dm + lc*8;
    const __nv_bfloat16* Ag1 = Ab + (size_t)(m0+lr+64)*Dm + lc*8;
    const __nv_bfloat16* Bg0 = Bb + (size_t)(n0+lr)*Dm + lc*8;
    const __nv_bfloat16* Bg1 = Bb + (size_t)(n0+lr+64)*Dm + lc*8;

    uint4 pa0 = *(const uint4*)(Ag0), pa1 = *(const uint4*)(Ag1);
    uint4 pb0 = *(const uint4*)(Bg0), pb1 = *(const uint4*)(Bg1);

    *(uint4*)(As[0] + lr*40 + lc*8)      = pa0;
    *(uint4*)(As[0] + (lr+64)*40 + lc*8) = pa1;
    *(uint4*)(Bs[0] + lr*40 + lc*8)      = pb0;
    *(uint4*)(Bs[0] + (lr+64)*40 + lc*8) = pb1;
    __syncthreads();

    for (int k0 = 0; k0 < Dm; k0 += 32){
        int cur = (k0 >> 5) & 1;
        bool more = (k0 + 32 < Dm);
        if (more){
            pa0 = *(const uint4*)(Ag0 + k0+32);
            pa1 = *(const uint4*)(Ag1 + k0+32);
            pb0 = *(const uint4*)(Bg0 + k0+32);
            pb1 = *(const uint4*)(Bg1 + k0+32);
        }
        #pragma unroll
        for (int kk2=0; kk2<2; kk2++){
            unsigned a[4][4], bf[4][2];
            #pragma unroll
            for (int mt=0; mt<4; mt++){
                int mrow = wm*64 + mt*16 + (grp&1)*8 + r8;
                unsigned ad = sptr(As[cur] + mrow*40 + kk2*16 + (grp>>1)*8);
                ldmx4(a[mt][0], a[mt][1], a[mt][2], a[mt][3], ad);
            }
            #pragma unroll
            for (int p=0; p<2; p++){
                int nrow = wn*32 + (p*2 + (grp>>1))*8 + r8;
                unsigned ad = sptr(Bs[cur] + nrow*40 + kk2*16 + (grp&1)*8);
                ldmx4(bf[p*2][0], bf[p*2][1], bf[p*2+1][0], bf[p*2+1][1], ad);
            }
            #pragma unroll
            for (int mt=0; mt<4; mt++)
                #pragma unroll
                for (int nt=0; nt<4; nt++)
                    mma_bf16(acc[mt][nt], a[mt], bf[nt]);
        }
        if (more){
            int nxt = cur ^ 1;
            *(uint4*)(As[nxt] + lr*40 + lc*8)      = pa0;
            *(uint4*)(As[nxt] + (lr+64)*40 + lc*8) = pa1;
            *(uint4*)(Bs[nxt] + lr*40 + lc*8)      = pb0;
            *(uint4*)(Bs[nxt] + (lr+64)*40 + lc*8) = pb1;
        }
        __syncthreads();
    }
    #pragma unroll
    for (int mt=0; mt<4; mt++){
        int r = m0 + wm*64 + mt*16 + g;
        #pragma unroll
        for (int nt=0; nt<4; nt++){
            int c = n0 + wn*32 + nt*8 + tig*2;
            *(__half2*)(Cb + (size_t)r*LA + c) =
                __floats2half2_rn((acc[mt][nt][0]-1.f)*IE, (acc[mt][nt][1]-1.f)*IE);
            *(__half2*)(Cb + (size_t)(r+8)*LA + c) =
                __floats2half2_rn((acc[mt][nt][2]-1.f)*IE, (acc[mt][nt][3]-1.f)*IE);
        }
    }
}

// ---------------- bf16 pi GEMM (double-buffered, exp on the fly, fused resid/S) ----------------
__global__ __launch_bounds__(256) void pi_mma(
        const __half* __restrict__ logK, const float* __restrict__ lu,
        const float* __restrict__ lv, const __nv_bfloat16* __restrict__ ApT,
        const float* __restrict__ Tp, float* __restrict__ S, float* __restrict__ resid)
{
    int b = blockIdx.z;
    const __half* LKb = logK + (size_t)b*LT*LA;
    const float* lub = lu + (size_t)b*LT;
    const float* lvb = lv + (size_t)b*LA;
    const __nv_bfloat16* Bb = ApT + (size_t)b*Dm*LA;
    const float* Tpb = Tp + (size_t)b*LT*Dm;
    float* Rb = resid + (size_t)b*LT*Dm;
    float* Sb = S + (size_t)b*LT;
    int m0 = blockIdx.x*128, n0 = blockIdx.y*128;

    __shared__ __align__(16) __nv_bfloat16 As[2][128*40];
    __shared__ __align__(16) __nv_bfloat16 Bs[2][128*40];

    int tid = threadIdx.x;
    int warp = tid >> 5, lane = tid & 31;
    int g = lane >> 2, tig = lane & 3;
    int wm = warp >> 2, wn = warp & 3;
    int r8 = lane & 7, grp = lane >> 3;

    float acc[4][4][4];
    #pragma unroll
    for(int i=0;i<4;i++) for(int j=0;j<4;j++) for(int q=0;q<4;q++) acc[i][j][q]=0.f;

    int lr = tid >> 2, lc = tid & 3;
    const __half* Lg0 = LKb + (size_t)(m0+lr)*LA + lc*8;
    const __half* Lg1 = LKb + (size_t)(m0+lr+64)*LA + lc*8;
    const __nv_bfloat16* Bg0 = Bb + (size_t)(n0+lr)*LA + lc*8;
    const __nv_bfloat16* Bg1 = Bb + (size_t)(n0+lr+64)*LA + lc*8;
    float lur0 = lub[m0+lr], lur1 = lub[m0+lr+64];

    uint4 ra0 = *(const uint4*)(Lg0), ra1 = *(const uint4*)(Lg1);
    uint4 pb0 = *(const uint4*)(Bg0), pb1 = *(const uint4*)(Bg1);

    {
        const __half* hp0 = (const __half*)&ra0;
        const __half* hp1 = (const __half*)&ra1;
        uint4 o0, o1;
        __nv_bfloat16* ob0 = (__nv_bfloat16*)&o0;
        __nv_bfloat16* ob1 = (__nv_bfloat16*)&o1;
        #pragma unroll
        for (int j=0;j<8;j++){
            float lvj = lvb[lc*8 + j];
            float p0 = __expf(__half2float(hp0[j]) + lur0 + lvj);
            float p1 = __expf(__half2float(hp1[j]) + lur1 + lvj);
            if (isinf(p0)) p0 = 1.f;
            if (isinf(p1)) p1 = 1.f;
            ob0[j] = __float2bfloat16(p0);
            ob1[j] = __float2bfloat16(p1);
        }
        *(uint4*)(As[0] + lr*40 + lc*8)      = o0;
        *(uint4*)(As[0] + (lr+64)*40 + lc*8) = o1;
        *(uint4*)(Bs[0] + lr*40 + lc*8)      = pb0;
        *(uint4*)(Bs[0] + (lr+64)*40 + lc*8) = pb1;
    }
    __syncthreads();

    for (int k0 = 0; k0 < LA; k0 += 32){
        int cur = (k0 >> 5) & 1;
        bool more = (k0 + 32 < LA);
        if (more){
            ra0 = *(const uint4*)(Lg0 + k0+32);
            ra1 = *(const uint4*)(Lg1 + k0+32);
            pb0 = *(const uint4*)(Bg0 + k0+32);
            pb1 = *(const uint4*)(Bg1 + k0+32);
        }
        #pragma unroll
        for (int kk2=0; kk2<2; kk2++){
            unsigned a[4][4], bf[4][2];
            #pragma unroll
            for (int mt=0; mt<4; mt++){
                int mrow = wm*64 + mt*16 + (grp&1)*8 + r8;
                unsigned ad = sptr(As[cur] + mrow*40 + kk2*16 + (grp>>1)*8);
                ldmx4(a[mt][0], a[mt][1], a[mt][2], a[mt][3], ad);
            }
            #pragma unroll
            for (int p=0; p<2; p++){
                int nrow = wn*32 + (p*2 + (grp>>1))*8 + r8;
                unsigned ad = sptr(Bs[cur] + nrow*40 + kk2*16 + (grp&1)*8);
                ldmx4(bf[p*2][0], bf[p*2][1], bf[p*2+1][0], bf[p*2+1][1], ad);
            }
            #pragma unroll
            for (int mt=0; mt<4; mt++)
                #pragma unroll
                for (int nt=0; nt<4; nt++)
                    mma_bf16(acc[mt][nt], a[mt], bf[nt]);
        }
        if (more){
            int nxt = cur ^ 1;
            const __half* hp0 = (const __half*)&ra0;
            const __half* hp1 = (const __half*)&ra1;
            uint4 o0, o1;
            __nv_bfloat16* ob0 = (__nv_bfloat16*)&o0;
            __nv_bfloat16* ob1 = (__nv_bfloat16*)&o1;
            #pragma unroll
            for (int j=0;j<8;j++){
                float lvj = lvb[k0+32 + lc*8 + j];
                float p0 = __expf(__half2float(hp0[j]) + lur0 + lvj);
                float p1 = __expf(__half2float(hp1[j]) + lur1 + lvj);
                if (isinf(p0)) p0 = 1.f;
                if (isinf(p1)) p1 = 1.f;
                ob0[j] = __float2bfloat16(p0);
                ob1[j] = __float2bfloat16(p1);
            }
            *(uint4*)(As[nxt] + lr*40 + lc*8)      = o0;
            *(uint4*)(As[nxt] + (lr+64)*40 + lc*8) = o1;
            *(uint4*)(Bs[nxt] + lr*40 + lc*8)      = pb0;
            *(uint4*)(Bs[nxt] + (lr+64)*40 + lc*8) = pb1;
        }
        __syncthreads();
    }
    #pragma unroll
    for (int mt=0; mt<4; mt++){
        int r = m0 + wm*64 + mt*16 + g;
        float ps0 = 0.f, ps1 = 0.f;
        #pragma unroll
        for (int nt=0; nt<4; nt++){
            int c = n0 + wn*32 + nt*8 + tig*2;
            float2 t0 = *(const float2*)(Tpb + (size_t)r*Dm + c);
            float2 t1 = *(const float2*)(Tpb + (size_t)(r+8)*Dm + c);
            ps0 += t0.x*acc[mt][nt][0] + t0.y*acc[mt][nt][1];
            ps1 += t1.x*acc[mt][nt][2] + t1.y*acc[mt][nt][3];
            *(float2*)(Rb + (size_t)r*Dm + c) =
                make_float2(fabsf(t0.x-acc[mt][nt][0]), fabsf(t0.y-acc[mt][nt][1]));
            *(float2*)(Rb + (size_t)(r+8)*Dm + c) =
                make_float2(fabsf(t1.x-acc[mt][nt][2]), fabsf(t1.y-acc[mt][nt][3]));
        }
        ps0 += __shfl_xor_sync(0xffffffffu, ps0, 1);
        ps0 += __shfl_xor_sync(0xffffffffu, ps0, 2);
        ps1 += __shfl_xor_sync(0xffffffffu, ps1, 1);
        ps1 += __shfl_xor_sync(0xffffffffu, ps1, 2);
        if (tig == 0){
            atomicAdd(&Sb[r], ps0);
            atomicAdd(&Sb[r+8], ps1);
        }
    }
}

// ---------------- Sinkhorn: row LSE -> lu (warp per row, shuffle-only, MLP=8) ----------------
__global__ __launch_bounds__(256) void sink_row(const __half* __restrict__ logK,
        const float* __restrict__ lv, float* __restrict__ lu){
    int b = blockIdx.y;
    int m = blockIdx.x*8 + (threadIdx.x >> 5);
    int lane = threadIdx.x & 31;
    const uint4* row = (const uint4*)(logK + ((size_t)b*LT + m)*LA);
    const float4* lv4 = (const float4*)(lv + (size_t)b*LA);
    uint4 raw[8];
    #pragma unroll
    for (int i=0;i<8;i++) raw[i] = row[lane + 32*i];
    float mx = -INFINITY;
    #pragma unroll
    for (int i=0;i<8;i++){
        const __half* hp = (const __half*)&raw[i];
        float4 l0 = lv4[(lane + 32*i)*2];
        float4 l1 = lv4[(lane + 32*i)*2 + 1];
        mx = fmaxf(mx, __half2float(hp[0])+l0.x);
        mx = fmaxf(mx, __half2float(hp[1])+l0.y);
        mx = fmaxf(mx, __half2float(hp[2])+l0.z);
        mx = fmaxf(mx, __half2float(hp[3])+l0.w);
        mx = fmaxf(mx, __half2float(hp[4])+l1.x);
        mx = fmaxf(mx, __half2float(hp[5])+l1.y);
        mx = fmaxf(mx, __half2float(hp[6])+l1.z);
        mx = fmaxf(mx, __half2float(hp[7])+l1.w);
    }
    mx = warpReduceMax(mx);
    float s = 0.f;
    #pragma unroll
    for (int i=0;i<8;i++){
        const __half* hp = (const __half*)&raw[i];
        float4 l0 = lv4[(lane + 32*i)*2];
        float4 l1 = lv4[(lane + 32*i)*2 + 1];
        s += __expf(__half2float(hp[0])+l0.x - mx);
        s += __expf(__half2float(hp[1])+l0.y - mx);
        s += __expf(__half2float(hp[2])+l0.z - mx);
        s += __expf(__half2float(hp[3])+l0.w - mx);
        s += __expf(__half2float(hp[4])+l1.x - mx);
        s += __expf(__half2float(hp[5])+l1.y - mx);
        s += __expf(__half2float(hp[6])+l1.z - mx);
        s += __expf(__half2float(hp[7])+l1.w - mx);
    }
    s = warpReduceSum(s);
    if (lane==0){
        const float LOG_MU = -6.93147180559945f;
        lu[(size_t)b*LT + m] = clip_nan(LOG_MU - (mx + __logf(s)));
    }
}

// ---------------- Sinkhorn: column LSE -> lv (8x row unroll) ----------------
__global__ void sink_col(const __half* __restrict__ logK,
        const float* __restrict__ lu, float* __restrict__ lv){
    int b = blockIdx.y;
    int tx = threadIdx.x, ty = threadIdx.y;
    int c2 = blockIdx.x*32 + tx;
    const __half2* base = (const __half2*)(logK + (size_t)b*LT*LA);
    const float* lub  = lu + (size_t)b*LT;
    float mx0=-INFINITY, s0=0.f, mx1=-INFINITY, s1=0.f;
    for (int m = ty; m < LT; m += 64){
        __half2 h[8];
        float l[8];
        #pragma unroll
        for (int i=0;i<8;i++){
            h[i] = base[(size_t)(m+8*i)*(LA/2) + c2];
            l[i] = lub[m+8*i];
        }
        #pragma unroll
        for (int i=0;i<8;i++){
            float2 f = __half22float2(h[i]);
            float v0 = f.x + l[i], v1 = f.y + l[i];
            if (v0 > mx0){ s0 = s0*__expf(mx0-v0) + 1.f; mx0 = v0; } else s0 += __expf(v0-mx0);
            if (v1 > mx1){ s1 = s1*__expf(mx1-v1) + 1.f; mx1 = v1; } else s1 += __expf(v1-mx1);
        }
    }
    __shared__ float smx[8][64], ss[8][64];
    smx[ty][tx*2]=mx0; ss[ty][tx*2]=s0;
    smx[ty][tx*2+1]=mx1; ss[ty][tx*2+1]=s1;
    __syncthreads();
    for (int off=4; off>=1; off>>=1){
        if (ty < off){
            #pragma unroll
            for (int w=0; w<2; w++){
                int cc = tx*2+w;
                float m1=smx[ty][cc], sa=ss[ty][cc];
                float m2=smx[ty+off][cc], sb=ss[ty+off][cc];
                float M = fmaxf(m1,m2);
                float Sv = sa*__expf(m1-M) + sb*__expf(m2-M);
                smx[ty][cc]=M; ss[ty][cc]=Sv;
            }
        }
        __syncthreads();
    }
    if (ty==0){
        const float LOG_NU = -7.62461898616078f;
        #pragma unroll
        for (int w=0; w<2; w++){
            int cc = tx*2+w;
            lv[(size_t)b*LA + c2*2 + w] = clip_nan(LOG_NU - (smx[0][cc] + __logf(ss[0][cc])));
        }
    }
}

// ---------------- router logits + softmax (warp per row) ----------------
__global__ __launch_bounds__(256) void router_out_kernel(const float* __restrict__ h1,
        const float* __restrict__ Wr2, const float* __restrict__ br2, float* __restrict__ G){
    size_t row = (size_t)blockIdx.x*8 + (threadIdx.x >> 5);
    int lane = threadIdx.x & 31;
    const float* hr = h1 + row*Dm;
    float4 v1 = *(const float4*)(hr + lane*4);
    float4 v2 = *(const float4*)(hr + 128 + lane*4);
    float l[3];
    #pragma unroll
    for (int e=0;e<3;e++){
        const float* w = Wr2 + e*Dm;
        float4 w1 = *(const float4*)(w + lane*4);
        float4 w2 = *(const float4*)(w + 128 + lane*4);
        float s = v1.x*w1.x+v1.y*w1.y+v1.z*w1.z+v1.w*w1.w
                + v2.x*w2.x+v2.y*w2.y+v2.z*w2.z+v2.w*w2.w;
        l[e] = warpReduceSum(s);
    }
    if (lane==0){
        float a0=l[0]+br2[0], a1=l[1]+br2[1], a2=l[2]+br2[2];
        float m = fmaxf(a0, fmaxf(a1,a2));
        float e0=__expf(a0-m), e1=__expf(a1-m), e2=__expf(a2-m);
        float inv = 1.f/(e0+e1+e2);
        G[row*3+0]=e0*inv; G[row*3+1]=e1*inv; G[row*3+2]=e2*inv;
    }
}

// ---------------- multi-scale conv (one kernel, block-level dispatch) ----------------
template<int KSZ>
__device__ __forceinline__ void conv_body(const float* __restrict__ h,
        const float* __restrict__ w, const float* __restrict__ conv_b,
        float* __restrict__ h2, int e, float (*hs)[64], float* ws)
{
    const int pad = (KSZ-1)/2;
    int tile = blockIdx.x*64;
    int l0 = tile & (LT-1);
    int tid = threadIdx.x;
    for (int idx = tid; idx < 68*64; idx += 256){
        int lr = idx >> 6; int i = idx & 63;
        int l = l0 + lr - 2;
        float v = 0.f;
        if (l >= 0 && l < LT) v = h[(size_t)(tile - l0 + l)*(NE*Rr) + e*Rr + i];
        hs[lr][i] = v;
    }
    float acc[16];
    #pragma unroll
    for (int j=0;j<16;j++) acc[j]=0.f;
    int o = tid & 63;
    int lg = tid >> 6;
    for (int ic = 0; ic < Rr; ic += 16){
        __syncthreads();
        for (int idx = tid; idx < 16*KSZ*64; idx += 256){
            int oo = idx & 63; int r = idx >> 6;
            int t = r % KSZ; int ii = r / KSZ;
            ws[idx] = w[(size_t)oo*Rr*KSZ + (ic+ii)*KSZ + t];
        }
        __syncthreads();
        #pragma unroll
        for (int ii = 0; ii < 16; ii++){
            #pragma unroll
            for (int t = 0; t < KSZ; t++){
                float wv = ws[(ii*KSZ + t)*64 + o];
                int roff = 2 + t - pad;
                #pragma unroll
                for (int j = 0; j < 16; j++){
                    acc[j] += hs[lg*16 + j + roff][ic + ii] * wv;
                }
            }
        }
    }
    float bo = conv_b[e*Rr + o];
    #pragma unroll
    for (int j=0;j<16;j++){
        int l = lg*16 + j;
        h2[(size_t)(tile + l)*(NE*Rr) + e*Rr + o] = geluf(acc[j] + bo);
    }
}

__global__ __launch_bounds__(256) void conv_all(const float* __restrict__ h,
        const float* __restrict__ w1, const float* __restrict__ w3,
        const float* __restrict__ w5, const float* __restrict__ conv_b,
        float* __restrict__ h2)
{
    __shared__ float hs[68][64];
    __shared__ float ws[16*5*64];
    int e = blockIdx.y;
    if (e == 0)      conv_body<1>(h, w1, conv_b, h2, 0, hs, ws);
    else if (e == 1) conv_body<3>(h, w3, conv_b, h2, 1, hs, ws);
    else             conv_body<5>(h, w5, conv_b, h2, 2, hs, ws);
}

// ---------------- final (warp per row): gated sum of per-expert LN (u in bf16) ----------------
__global__ __launch_bounds__(256) void final_kernel(const __nv_bfloat16* __restrict__ u,
        const float* __restrict__ resid, const float* __restrict__ G,
        const float* __restrict__ en_g, const float* __restrict__ en_b,
        float* __restrict__ out)
{
    size_t row = (size_t)blockIdx.x*8 + (threadIdx.x >> 5);
    int lane = threadIdx.x & 31;
    const float* rr = resid + row*Dm;
    float4 r1 = *(const float4*)(rr + lane*4);
    float4 r2 = *(const float4*)(rr + 128 + lane*4);
    float4 o1 = make_float4(0,0,0,0), o2 = make_float4(0,0,0,0);
    #pragma unroll
    for (int e=0;e<3;e++){
        const __nv_bfloat16* ur = u + ((size_t)e*ROWS_T + row)*Dm;
        uint2 up1 = *(const uint2*)(ur + lane*4);
        uint2 up2 = *(const uint2*)(ur + 128 + lane*4);
        float2 ua = __bfloat1622float2(*(__nv_bfloat162*)&up1.x);
        float2 ub = __bfloat1622float2(*(__nv_bfloat162*)&up1.y);
        float2 uc = __bfloat1622float2(*(__nv_bfloat162*)&up2.x);
        float2 ud = __bfloat1622float2(*(__nv_bfloat162*)&up2.y);
        float y0=ua.x+r1.x, y1=ua.y+r1.y, y2=ub.x+r1.z, y3=ub.y+r1.w;
        float z0=uc.x+r2.x, z1=uc.y+r2.y, z2=ud.x+r2.z, z3=ud.y+r2.w;
        float mean = warpReduceSum(y0+y1+y2+y3+z0+z1+z2+z3) * (1.f/Dm);
        y0-=mean;y1-=mean;y2-=mean;y3-=mean;z0-=mean;z1-=mean;z2-=mean;z3-=mean;
        float var = warpReduceSum(y0*y0+y1*y1+y2*y2+y3*y3+z0*z0+z1*z1+z2*z2+z3*z3) * (1.f/Dm);
        float rstd = rsqrtf(var + 1e-5f);
        float gw = G[row*3+e];
        const float* eg = en_g + e*Dm;
        const float* eb = en_b + e*Dm;
        float4 g1 = *(const float4*)(eg + lane*4);
        float4 g2 = *(const float4*)(eg + 128 + lane*4);
        float4 b1 = *(const float4*)(eb + lane*4);
        float4 b2 = *(const float4*)(eb + 128 + lane*4);
        o1.x += gw*(y0*rstd*g1.x + b1.x); o1.y += gw*(y1*rstd*g1.y + b1.y);
        o1.z += gw*(y2*rstd*g1.z + b1.z); o1.w += gw*(y3*rstd*g1.w + b1.w);
        o2.x += gw*(z0*rstd*g2.x + b2.x); o2.y += gw*(z1*rstd*g2.y + b2.y);
        o2.z += gw*(z2*rstd*g2.z + b2.z); o2.w += gw*(z3*rstd*g2.w + b2.w);
    }
    float* orow = out + row*Dm;
    *(float4*)(orow + lane*4) = o1;
    *(float4*)(orow + 128 + lane*4) = o2;
}

// ---------------- host launcher ----------------
extern "C" void kernel_launch(void* const* d_in, const int* in_sizes, int n_in,
                              void* d_out, int out_size)
{
    const float* text   = (const float*)d_in[0];
    const float* audio  = (const float*)d_in[1];
    const float* ln_g   = (const float*)d_in[2];
    const float* ln_b   = (const float*)d_in[3];
    const float* W_sh   = (const float*)d_in[4];
    const float* b_sh   = (const float*)d_in[5];
    const float* Wr1    = (const float*)d_in[6];
    const float* br1    = (const float*)d_in[7];
    const float* Wr2    = (const float*)d_in[8];
    const float* br2    = (const float*)d_in[9];
    const float* down_W = (const float*)d_in[10];
    const float* down_b = (const float*)d_in[11];
    const float* conv_w1= (const float*)d_in[12];
    const float* conv_w3= (const float*)d_in[13];
    const float* conv_w5= (const float*)d_in[14];
    const float* conv_b = (const float*)d_in[15];
    const float* up_W   = (const float*)d_in[16];
    const float* up_b   = (const float*)d_in[17];
    const float* en_g   = (const float*)d_in[18];
    const float* en_b   = (const float*)d_in[19];
    float* out = (float*)d_out;

    void *p;
    cudaGetSymbolAddress(&p, g_stats); float2* stats = (float2*)p;
    cudaGetSymbolAddress(&p, g_Tp);   float* Tp  = (float*)p;
    cudaGetSymbolAddress(&p, g_Ap);   float* Ap  = (float*)p;
    cudaGetSymbolAddress(&p, g_Tn);   __nv_bfloat16* Tn = (__nv_bfloat16*)p;
    cudaGetSymbolAddress(&p, g_An);   __nv_bfloat16* An = (__nv_bfloat16*)p;
    cudaGetSymbolAddress(&p, g_ApT);  __nv_bfloat16* ApT = (__nv_bfloat16*)p;
    cudaGetSymbolAddress(&p, g_logK); __half* logK = (__half*)p;
    cudaGetSymbolAddress(&p, g_lu);   float* lu = (float*)p;
    cudaGetSymbolAddress(&p, g_lv);   float* lv = (float*)p;
    cudaGetSymbolAddress(&p, g_S);    float* S = (float*)p;
    cudaGetSymbolAddress(&p, g_resid);float* resid = (float*)p;
    cudaGetSymbolAddress(&p, g_h1);   float* h1 = (float*)p;
    cudaGetSymbolAddress(&p, g_G);    float* G = (float*)p;
    cudaGetSymbolAddress(&p, g_h);    float* h = (float*)p;
    cudaGetSymbolAddress(&p, g_h2);   float* h2 = (float*)p;
    cudaGetSymbolAddress(&p, g_u);    __nv_bfloat16* u = (__nv_bfloat16*)p;

    zero_lulv<<<128,256>>>(lu, lv, S);

    // LN stats (warp per row)
    ln_stats<<<(ROWS_T + ROWS_A)/8, 256>>>(text, audio, stats);

    // text+audio projections with fused LN in ONE launch
    gemm_tf32<0,true,false><<<dim3((ROWS_T+ROWS_A)/128, Dm/64, 1),256>>>(
            text, Dm, 0, W_sh, Dm, 0, Tp, Dm, 0, Dm, b_sh, 0,
            stats, ln_g, ln_b, nullptr, nullptr, 0,
            audio, Ap, stats + ROWS_T, ROWS_T/128);

    norm_bf16_kernel<<<ROWS_T/8,256>>>(Tp, Tn);
    audio_norm_T<<<dim3(LA/32, Bt), 256>>>(Ap, An, ApT);

    // cost -> logK (fp16) via bf16 tensor cores (double-buffered)
    cost_mma<<<dim3(LT/128, LA/128, Bt),256>>>(Tn, An, logK);

    // Sinkhorn (fp16 logK, L2-resident)
    for (int it=0; it<10; ++it){
        sink_row<<<dim3(LT/8, Bt),256>>>(logK, lv, lu);
        sink_col<<<dim3(LA/64, Bt), dim3(32,8)>>>(logK, lu, lv);
    }

    // pi GEMM with fused resid/S epilogue (double-buffered)
    pi_mma<<<dim3(LT/128, Dm/128, Bt),256>>>(logK, lu, lv, ApT, Tp, S, resid);

    // router hidden + down projection in ONE launch (both read resid, independent)
    gemm_dual<<<dim3(ROWS_T/128, 7, 1),256>>>(resid, Wr1+1, br1, S, Wr1, h1,
            down_W, down_b, h);
    router_out_kernel<<<ROWS_T/8,256>>>(h1, Wr2, br2, G);

    // experts
    conv_all<<<dim3(ROWS_T/64, NE),256>>>(h, conv_w1, conv_w3, conv_w5, conv_b, h2);
    gemm_tf32<0,false,true><<<dim3(ROWS_T/128, Dm/64, NE),256>>>(h2, NE*Rr, (long long)Rr,
            up_W, Rr, (long long)Dm*Rr, u, Dm, (long long)ROWS_T*Dm,
            Rr, up_b, Dm, nullptr, nullptr, nullptr, nullptr, nullptr, 0,
            nullptr, nullptr, nullptr, 1<<30);

    final_kernel<<<ROWS_T/8,256>>>(u, resid, G, en_g, en_b, out);
}

// round 17
// speedup vs baseline: 1.0647x; 1.0042x over previous
#include <cuda_runtime.h>
#include <cuda_bf16.h>
#include <cuda_fp16.h>
#include <math.h>

#define Bt 16
#define LT 1024
#define LA 2048
#define Dm 256
#define Rr 64
#define NE 3
#define ROWS_T (Bt*LT)   // 16384
#define ROWS_A (Bt*LA)   // 32768

// ---------------- scratch ----------------
__device__ float2 g_stats[ROWS_T + ROWS_A];
__device__ float g_Tp [(size_t)ROWS_T*Dm];
__device__ float g_Ap [(size_t)ROWS_A*Dm];
__device__ __nv_bfloat16 g_Tn [(size_t)ROWS_T*Dm];
__device__ __nv_bfloat16 g_An [(size_t)ROWS_A*Dm];
__device__ __nv_bfloat16 g_ApT[(size_t)Bt*Dm*LA];
__device__ __half g_logK[(size_t)Bt*LT*LA];
__device__ float g_lu[ROWS_T];
__device__ float g_lv[ROWS_A];
__device__ float g_S[ROWS_T];
__device__ float g_resid[(size_t)ROWS_T*Dm];
__device__ float g_h1[(size_t)ROWS_T*Dm];
__device__ float g_h [(size_t)ROWS_T*NE*Rr];
__device__ float g_h2[(size_t)ROWS_T*NE*Rr];
__device__ __nv_bfloat16 g_u [(size_t)NE*ROWS_T*Dm];

// ---------------- helpers ----------------
__device__ __forceinline__ float geluf(float x){
    return 0.5f*x*(1.0f+erff(x*0.7071067811865476f));
}
__device__ __forceinline__ float warpReduceSum(float v){
    #pragma unroll
    for(int o=16;o;o>>=1) v += __shfl_xor_sync(0xffffffffu, v, o);
    return v;
}
__device__ __forceinline__ float warpReduceMax(float v){
    #pragma unroll
    for(int o=16;o;o>>=1) v = fmaxf(v, __shfl_xor_sync(0xffffffffu, v, o));
    return v;
}
__device__ __forceinline__ float clip_nan(float l){
    if (isnan(l)) return 0.f;
    return fminf(fmaxf(l, -1e9f), 1e9f);
}

__device__ __forceinline__ void mma_bf16(float* c, const unsigned* a, const unsigned* b){
    asm volatile("mma.sync.aligned.m16n8k16.row.col.f32.bf16.bf16.f32 "
        "{%0,%1,%2,%3}, {%4,%5,%6,%7}, {%8,%9}, {%0,%1,%2,%3};"
        : "+f"(c[0]), "+f"(c[1]), "+f"(c[2]), "+f"(c[3])
        : "r"(a[0]), "r"(a[1]), "r"(a[2]), "r"(a[3]), "r"(b[0]), "r"(b[1]));
}
__device__ __forceinline__ void mma_tf32(float* c, const unsigned* a, const unsigned* b){
    asm volatile("mma.sync.aligned.m16n8k8.row.col.f32.tf32.tf32.f32 "
        "{%0,%1,%2,%3}, {%4,%5,%6,%7}, {%8,%9}, {%0,%1,%2,%3};"
        : "+f"(c[0]), "+f"(c[1]), "+f"(c[2]), "+f"(c[3])
        : "r"(a[0]), "r"(a[1]), "r"(a[2]), "r"(a[3]), "r"(b[0]), "r"(b[1]));
}
__device__ __forceinline__ unsigned f2tf32(float f){
    unsigned r; asm("cvt.rna.tf32.f32 %0, %1;" : "=r"(r) : "f"(f)); return r;
}
__device__ __forceinline__ unsigned sptr(const void* p){
    return (unsigned)__cvta_generic_to_shared(p);
}
__device__ __forceinline__ void ldmx4(unsigned &r0, unsigned &r1, unsigned &r2, unsigned &r3, unsigned a){
    asm volatile("ldmatrix.sync.aligned.m8n8.x4.shared.b16 {%0,%1,%2,%3}, [%4];"
        : "=r"(r0), "=r"(r1), "=r"(r2), "=r"(r3) : "r"(a));
}

// ---------------- LN stats (warp per row) + zero lu/lv/S ----------------
__global__ __launch_bounds__(256) void ln_stats(const float* __restrict__ text,
        const float* __restrict__ audio, float2* __restrict__ stats,
        float* __restrict__ lu, float* __restrict__ lv, float* __restrict__ S){
    int gidx = blockIdx.x*256 + threadIdx.x;
    if (gidx < ROWS_T){ lu[gidx] = 0.f; S[gidx] = 0.f; }
    if (gidx < ROWS_A) lv[gidx] = 0.f;
    size_t row = (size_t)blockIdx.x*8 + (threadIdx.x >> 5);
    int lane = threadIdx.x & 31;
    const float* x = (row < ROWS_T) ? (text + row*Dm) : (audio + (row-ROWS_T)*Dm);
    float4 v1 = *(const float4*)(x + lane*4);
    float4 v2 = *(const float4*)(x + 128 + lane*4);
    float s = v1.x+v1.y+v1.z+v1.w + v2.x+v2.y+v2.z+v2.w;
    float mean = warpReduceSum(s) * (1.f/Dm);
    float d0=v1.x-mean,d1=v1.y-mean,d2=v1.z-mean,d3=v1.w-mean;
    float e0=v2.x-mean,e1=v2.y-mean,e2=v2.z-mean,e3=v2.w-mean;
    float var = warpReduceSum(d0*d0+d1*d1+d2*d2+d3*d3+e0*e0+e1*e1+e2*e2+e3*e3) * (1.f/Dm);
    if (lane==0) stats[row] = make_float2(mean, rsqrtf(var + 1e-5f));
}

// ---------------- combined normalization: audio (transpose path) + text (row path) ----------------
// grid.x = 1024 (audio tiles) + 2048 (text warp-row blocks) = 3072
__global__ __launch_bounds__(256) void norm_combined(const float* __restrict__ Ap,
        __nv_bfloat16* __restrict__ An, __nv_bfloat16* __restrict__ ApT,
        const float* __restrict__ Tp, __nv_bfloat16* __restrict__ Tn){
    __shared__ float tile[32][257];
    __shared__ float invs[32];
    int bx = blockIdx.x;
    if (bx < 1024){
        // audio: unit-norm -> An + transposed ApT
        int b = bx >> 6;
        int n0 = (bx & 63)*32;
        const float* src = Ap + ((size_t)b*LA + n0)*Dm;
        int tid = threadIdx.x;
        for (int i = tid; i < 32*256; i += 256)
            tile[i>>8][i&255] = src[i];
        __syncthreads();
        int w = tid>>5, lane = tid&31;
        for (int rr = 0; rr < 4; rr++){
            int row = w*4 + rr;
            float s = 0.f;
            #pragma unroll
            for (int j=0;j<8;j++){
                float v = tile[row][lane*8 + j];
                s += v*v;
            }
            s = warpReduceSum(s);
            if (lane==0) invs[row] = 1.f / fmaxf(sqrtf(s), 1e-12f);
        }
        __syncthreads();
        __nv_bfloat16* dstA = An + ((size_t)b*LA + n0)*Dm;
        for (int i = tid; i < 32*256; i += 256){
            int row = i>>8;
            dstA[i] = __float2bfloat16(tile[row][i&255] * invs[row]);
        }
        float inv = invs[lane];
        __nv_bfloat16* dstT = ApT + (size_t)b*Dm*LA + n0;
        for (int it = 0; it < 32; it++){
            int d = it*8 + w;
            dstT[(size_t)d*LA + lane] = __float2bfloat16(tile[lane][d] * inv);
        }
    } else {
        // text: unit-norm rows -> bf16 (warp per row)
        size_t row = (size_t)(bx - 1024)*8 + (threadIdx.x >> 5);
        int lane = threadIdx.x & 31;
        const float* xr = Tp + row*Dm;
        float4 v1 = *(const float4*)(xr + lane*4);
        float4 v2 = *(const float4*)(xr + 128 + lane*4);
        float s = v1.x*v1.x+v1.y*v1.y+v1.z*v1.z+v1.w*v1.w
                + v2.x*v2.x+v2.y*v2.y+v2.z*v2.z+v2.w*v2.w;
        float inv = 1.f / fmaxf(sqrtf(warpReduceSum(s)), 1e-12f);
        __nv_bfloat162 p0 = {__float2bfloat16(v1.x*inv), __float2bfloat16(v1.y*inv)};
        __nv_bfloat162 p1 = {__float2bfloat16(v1.z*inv), __float2bfloat16(v1.w*inv)};
        __nv_bfloat162 q0 = {__float2bfloat16(v2.x*inv), __float2bfloat16(v2.y*inv)};
        __nv_bfloat162 q1 = {__float2bfloat16(v2.z*inv), __float2bfloat16(v2.w*inv)};
        *(uint2*)(Tn + row*Dm + lane*4) = make_uint2(*(unsigned*)&p0, *(unsigned*)&p1);
        *(uint2*)(Tn + row*Dm + 128 + lane*4) = make_uint2(*(unsigned*)&q0, *(unsigned*)&q1);
    }
}

// ---------------- tf32 tensor-core GEMM (ldmatrix + register prefetch, dual-input) ----------------
template<int EPI, bool FUSE_LN, bool OUT_BF16>
__global__ __launch_bounds__(256) void gemm_tf32(
        const float* __restrict__ A, int lda, long long bsA,
        const float* __restrict__ B, int ldb, long long bsB,
        void* __restrict__ Cv, int ldc, long long bsC,
        int K,
        const float* __restrict__ bias, long long bsBias,
        const float2* __restrict__ stats,
        const float* __restrict__ lng, const float* __restrict__ lnb,
        const float* __restrict__ rowv, const float* __restrict__ colv, int colvStride,
        const float* __restrict__ A2, void* __restrict__ Cv2,
        const float2* __restrict__ stats2, int blocksA)
{
    long long bz = blockIdx.z;
    int bx = blockIdx.x;
    if (A2 && bx >= blocksA){
        A = A2; Cv = Cv2; stats = stats2;
        bx -= blocksA;
    }
    A += bz*bsA; B += bz*bsB;
    if (bias) bias += bz*bsBias;
    int M0 = bx*128, N0 = blockIdx.y*64;

    __shared__ __align__(16) unsigned As[128][36];
    __shared__ __align__(16) unsigned Bs[64][36];
    __shared__ float2 st[128];
    __shared__ float gAll[256], bAll[256];

    int tid = threadIdx.x;
    int warp = tid >> 5, lane = tid & 31;
    int g = lane >> 2, tig = lane & 3;
    int wm = warp >> 1, wn = warp & 1;
    int r8 = lane & 7, grp = lane >> 3;

    if (FUSE_LN){
        if (tid < 128) st[tid] = stats[M0 + tid];
        for (int i = tid; i < K; i += 256){ gAll[i] = lng[i]; bAll[i] = lnb[i]; }
    }

    float acc[2][4][4];
    #pragma unroll
    for(int i=0;i<2;i++) for(int j=0;j<4;j++) for(int q=0;q<4;q++) acc[i][j][q]=0.f;

    int ra = tid >> 1, kh = (tid & 1)*16;
    int rb = tid >> 2, kb = (tid & 3)*8;
    const float* Arow = A + (size_t)(M0+ra)*lda + kh;
    const float* Brow = B + (size_t)(N0+rb)*ldb + kb;

    float4 va[4];
    float vb[8];
    #pragma unroll
    for (int j=0;j<4;j++) va[j] = *(const float4*)(Arow + 4*j);
    #pragma unroll
    for (int j=0;j<8;j++) vb[j] = Brow[j];

    for (int k0 = 0; k0 < K; k0 += 32){
        __syncthreads();
        {
            float2 ms = FUSE_LN ? st[ra] : make_float2(0.f,0.f);
            #pragma unroll
            for (int j=0;j<4;j++){
                float e[4] = {va[j].x, va[j].y, va[j].z, va[j].w};
                unsigned o[4];
                #pragma unroll
                for (int c=0;c<4;c++){
                    if (FUSE_LN){
                        int kk = k0 + kh + 4*j + c;
                        e[c] = (e[c] - ms.x)*ms.y*gAll[kk] + bAll[kk];
                    }
                    o[c] = f2tf32(e[c]);
                }
                *(uint4*)&As[ra][kh + 4*j] = make_uint4(o[0],o[1],o[2],o[3]);
            }
            unsigned ob[8];
            #pragma unroll
            for (int j=0;j<8;j++) ob[j] = f2tf32(vb[j]);
            *(uint4*)&Bs[rb][kb]   = make_uint4(ob[0],ob[1],ob[2],ob[3]);
            *(uint4*)&Bs[rb][kb+4] = make_uint4(ob[4],ob[5],ob[6],ob[7]);
        }
        __syncthreads();
        if (k0 + 32 < K){
            #pragma unroll
            for (int j=0;j<4;j++) va[j] = *(const float4*)(Arow + k0+32 + 4*j);
            #pragma unroll
            for (int j=0;j<8;j++) vb[j] = Brow[k0+32 + j];
        }
        #pragma unroll
        for (int ks=0; ks<4; ks++){
            int k = ks*8;
            unsigned a[2][4], bf[4][2];
            #pragma unroll
            for (int mt=0; mt<2; mt++){
                unsigned ad = sptr(&As[wm*32 + mt*16 + (grp&1)*8 + r8][k + (grp>>1)*4]);
                ldmx4(a[mt][0], a[mt][1], a[mt][2], a[mt][3], ad);
            }
            #pragma unroll
            for (int p=0; p<2; p++){
                unsigned ad = sptr(&Bs[wn*32 + (p*2 + (grp>>1))*8 + r8][k + (grp&1)*4]);
                ldmx4(bf[p*2][0], bf[p*2][1], bf[p*2+1][0], bf[p*2+1][1], ad);
            }
            #pragma unroll
            for (int mt=0; mt<2; mt++)
                #pragma unroll
                for (int nt=0; nt<4; nt++)
                    mma_tf32(acc[mt][nt], a[mt], bf[nt]);
        }
    }

    #pragma unroll
    for (int mt=0; mt<2; mt++){
        #pragma unroll
        for (int nt=0; nt<4; nt++){
            int m = M0 + wm*32 + mt*16 + g;
            int n = N0 + wn*32 + nt*8 + tig*2;
            #pragma unroll
            for (int hrow=0; hrow<2; hrow++){
                int mm = m + hrow*8;
                float v0 = acc[mt][nt][hrow*2+0];
                float v1 = acc[mt][nt][hrow*2+1];
                if (EPI==0){ v0 += bias[n]; v1 += bias[n+1]; }
                if (EPI==2){ v0 = geluf(v0 + bias[n]); v1 = geluf(v1 + bias[n+1]); }
                if (OUT_BF16){
                    __nv_bfloat16* C = (__nv_bfloat16*)Cv + bz*bsC;
                    __nv_bfloat162 pk = {__float2bfloat16(v0), __float2bfloat16(v1)};
                    *(__nv_bfloat162*)(C + (size_t)mm*ldc + n) = pk;
                } else {
                    float* C = (float*)Cv + bz*bsC;
                    *(float2*)(C + (size_t)mm*ldc + n) = make_float2(v0, v1);
                }
            }
        }
    }
}

// ---------------- dual GEMM: router (y<4) + down (y>=4) in one launch ----------------
__global__ __launch_bounds__(256) void gemm_dual(
        const float* __restrict__ Aresid,
        const float* __restrict__ Wr1p, const float* __restrict__ br1,
        const float* __restrict__ S, const float* __restrict__ Wr1full,
        float* __restrict__ h1,
        const float* __restrict__ downW, const float* __restrict__ downb,
        float* __restrict__ h)
{
    int by = blockIdx.y;
    bool isDown = (by >= 4);
    int yIdx = isDown ? by - 4 : by;
    const float* B = isDown ? downW : Wr1p;
    int ldb = isDown ? Dm : Dm+1;
    const float* bias = isDown ? downb : br1;
    float* C = isDown ? h : h1;
    int ldc = isDown ? NE*Rr : Dm;

    int M0 = blockIdx.x*128, N0 = yIdx*64;

    __shared__ __align__(16) unsigned As[128][36];
    __shared__ __align__(16) unsigned Bs[64][36];

    int tid = threadIdx.x;
    int warp = tid >> 5, lane = tid & 31;
    int g = lane >> 2, tig = lane & 3;
    int wm = warp >> 1, wn = warp & 1;
    int r8 = lane & 7, grp = lane >> 3;

    float acc[2][4][4];
    #pragma unroll
    for(int i=0;i<2;i++) for(int j=0;j<4;j++) for(int q=0;q<4;q++) acc[i][j][q]=0.f;

    int ra = tid >> 1, kh = (tid & 1)*16;
    int rb = tid >> 2, kb = (tid & 3)*8;
    const float* Arow = Aresid + (size_t)(M0+ra)*Dm + kh;
    const float* Brow = B + (size_t)(N0+rb)*ldb + kb;

    float4 va[4];
    float vb[8];
    #pragma unroll
    for (int j=0;j<4;j++) va[j] = *(const float4*)(Arow + 4*j);
    #pragma unroll
    for (int j=0;j<8;j++) vb[j] = Brow[j];

    for (int k0 = 0; k0 < Dm; k0 += 32){
        __syncthreads();
        {
            #pragma unroll
            for (int j=0;j<4;j++){
                unsigned o[4];
                o[0]=f2tf32(va[j].x); o[1]=f2tf32(va[j].y);
                o[2]=f2tf32(va[j].z); o[3]=f2tf32(va[j].w);
                *(uint4*)&As[ra][kh + 4*j] = make_uint4(o[0],o[1],o[2],o[3]);
            }
            unsigned ob[8];
            #pragma unroll
            for (int j=0;j<8;j++) ob[j] = f2tf32(vb[j]);
            *(uint4*)&Bs[rb][kb]   = make_uint4(ob[0],ob[1],ob[2],ob[3]);
            *(uint4*)&Bs[rb][kb+4] = make_uint4(ob[4],ob[5],ob[6],ob[7]);
        }
        __syncthreads();
        if (k0 + 32 < Dm){
            #pragma unroll
            for (int j=0;j<4;j++) va[j] = *(const float4*)(Arow + k0+32 + 4*j);
            #pragma unroll
            for (int j=0;j<8;j++) vb[j] = Brow[k0+32 + j];
        }
        #pragma unroll
        for (int ks=0; ks<4; ks++){
            int k = ks*8;
            unsigned a[2][4], bf[4][2];
            #pragma unroll
            for (int mt=0; mt<2; mt++){
                unsigned ad = sptr(&As[wm*32 + mt*16 + (grp&1)*8 + r8][k + (grp>>1)*4]);
                ldmx4(a[mt][0], a[mt][1], a[mt][2], a[mt][3], ad);
            }
            #pragma unroll
            for (int p=0; p<2; p++){
                unsigned ad = sptr(&Bs[wn*32 + (p*2 + (grp>>1))*8 + r8][k + (grp&1)*4]);
                ldmx4(bf[p*2][0], bf[p*2][1], bf[p*2+1][0], bf[p*2+1][1], ad);
            }
            #pragma unroll
            for (int mt=0; mt<2; mt++)
                #pragma unroll
                for (int nt=0; nt<4; nt++)
                    mma_tf32(acc[mt][nt], a[mt], bf[nt]);
        }
    }

    #pragma unroll
    for (int mt=0; mt<2; mt++){
        #pragma unroll
        for (int nt=0; nt<4; nt++){
            int m = M0 + wm*32 + mt*16 + g;
            int n = N0 + wn*32 + nt*8 + tig*2;
            #pragma unroll
            for (int hrow=0; hrow<2; hrow++){
                int mm = m + hrow*8;
                float v0 = acc[mt][nt][hrow*2+0];
                float v1 = acc[mt][nt][hrow*2+1];
                if (!isDown){
                    float rv = S[mm];
                    v0 = geluf(v0 + rv*Wr1full[(size_t)n*(Dm+1)] + bias[n]);
                    v1 = geluf(v1 + rv*Wr1full[(size_t)(n+1)*(Dm+1)] + bias[n+1]);
                } else {
                    v0 = geluf(v0 + bias[n]);
                    v1 = geluf(v1 + bias[n+1]);
                }
                *(float2*)(C + (size_t)mm*ldc + n) = make_float2(v0, v1);
            }
        }
    }
}

// ---------------- bf16 cost GEMM (double-buffered smem, one sync/iter) ----------------
__global__ __launch_bounds__(256) void cost_mma(
        const __nv_bfloat16* __restrict__ Tn, const __nv_bfloat16* __restrict__ An,
        __half* __restrict__ logK)
{
    const float IE = (float)(1.0/(0.1+1e-8));
    int b = blockIdx.z;
    const __nv_bfloat16* Ab = Tn + (size_t)b*LT*Dm;
    const __nv_bfloat16* Bb = An + (size_t)b*LA*Dm;
    __half* Cb = logK + (size_t)b*LT*LA;
    int m0 = blockIdx.x*128, n0 = blockIdx.y*128;

    __shared__ __align__(16) __nv_bfloat16 As[2][128*40];
    __shared__ __align__(16) __nv_bfloat16 Bs[2][128*40];

    int tid = threadIdx.x;
    int warp = tid >> 5, lane = tid & 31;
    int g = lane >> 2, tig = lane & 3;
    int wm = warp >> 2, wn = warp & 3;
    int r8 = lane & 7, grp = lane >> 3;

    float acc[4][4][4];
    #pragma unroll
    for(int i=0;i<4;i++) for(int j=0;j<4;j++) for(int q=0;q<4;q++) acc[i][j][q]=0.f;

    int lr = tid >> 2, lc = tid & 3;
    const __nv_bfloat16* Ag0 = Ab + (size_t)(m0+lr)*Dm + lc*8;
    const __nv_bfloat16* Ag1 = Ab + (size_t)(m0+lr+64)*Dm + lc*8;
    const __nv_bfloat16* Bg0 = Bb + (size_t)(n0+lr)*Dm + lc*8;
    const __nv_bfloat16* Bg1 = Bb + (size_t)(n0+lr+64)*Dm + lc*8;

    uint4 pa0 = *(const uint4*)(Ag0), pa1 = *(const uint4*)(Ag1);
    uint4 pb0 = *(const uint4*)(Bg0), pb1 = *(const uint4*)(Bg1);

    *(uint4*)(As[0] + lr*40 + lc*8)      = pa0;
    *(uint4*)(As[0] + (lr+64)*40 + lc*8) = pa1;
    *(uint4*)(Bs[0] + lr*40 + lc*8)      = pb0;
    *(uint4*)(Bs[0] + (lr+64)*40 + lc*8) = pb1;
    __syncthreads();

    for (int k0 = 0; k0 < Dm; k0 += 32){
        int cur = (k0 >> 5) & 1;
        bool more = (k0 + 32 < Dm);
        if (more){
            pa0 = *(const uint4*)(Ag0 + k0+32);
            pa1 = *(const uint4*)(Ag1 + k0+32);
            pb0 = *(const uint4*)(Bg0 + k0+32);
            pb1 = *(const uint4*)(Bg1 + k0+32);
        }
        #pragma unroll
        for (int kk2=0; kk2<2; kk2++){
            unsigned a[4][4], bf[4][2];
            #pragma unroll
            for (int mt=0; mt<4; mt++){
                int mrow = wm*64 + mt*16 + (grp&1)*8 + r8;
                unsigned ad = sptr(As[cur] + mrow*40 + kk2*16 + (grp>>1)*8);
                ldmx4(a[mt][0], a[mt][1], a[mt][2], a[mt][3], ad);
            }
            #pragma unroll
            for (int p=0; p<2; p++){
                int nrow = wn*32 + (p*2 + (grp>>1))*8 + r8;
                unsigned ad = sptr(Bs[cur] + nrow*40 + kk2*16 + (grp&1)*8);
                ldmx4(bf[p*2][0], bf[p*2][1], bf[p*2+1][0], bf[p*2+1][1], ad);
            }
            #pragma unroll
            for (int mt=0; mt<4; mt++)
                #pragma unroll
                for (int nt=0; nt<4; nt++)
                    mma_bf16(acc[mt][nt], a[mt], bf[nt]);
        }
        if (more){
            int nxt = cur ^ 1;
            *(uint4*)(As[nxt] + lr*40 + lc*8)      = pa0;
            *(uint4*)(As[nxt] + (lr+64)*40 + lc*8) = pa1;
            *(uint4*)(Bs[nxt] + lr*40 + lc*8)      = pb0;
            *(uint4*)(Bs[nxt] + (lr+64)*40 + lc*8) = pb1;
        }
        __syncthreads();
    }
    #pragma unroll
    for (int mt=0; mt<4; mt++){
        int r = m0 + wm*64 + mt*16 + g;
        #pragma unroll
        for (int nt=0; nt<4; nt++){
            int c = n0 + wn*32 + nt*8 + tig*2;
            *(__half2*)(Cb + (size_t)r*LA + c) =
                __floats2half2_rn((acc[mt][nt][0]-1.f)*IE, (acc[mt][nt][1]-1.f)*IE);
            *(__half2*)(Cb + (size_t)(r+8)*LA + c) =
                __floats2half2_rn((acc[mt][nt][2]-1.f)*IE, (acc[mt][nt][3]-1.f)*IE);
        }
    }
}

// ---------------- bf16 pi GEMM (double-buffered, exp on the fly, fused resid/S) ----------------
__global__ __launch_bounds__(256) void pi_mma(
        const __half* __restrict__ logK, const float* __restrict__ lu,
        const float* __restrict__ lv, const __nv_bfloat16* __restrict__ ApT,
        const float* __restrict__ Tp, float* __restrict__ S, float* __restrict__ resid)
{
    int b = blockIdx.z;
    const __half* LKb = logK + (size_t)b*LT*LA;
    const float* lub = lu + (size_t)b*LT;
    const float* lvb = lv + (size_t)b*LA;
    const __nv_bfloat16* Bb = ApT + (size_t)b*Dm*LA;
    const float* Tpb = Tp + (size_t)b*LT*Dm;
    float* Rb = resid + (size_t)b*LT*Dm;
    float* Sb = S + (size_t)b*LT;
    int m0 = blockIdx.x*128, n0 = blockIdx.y*128;

    __shared__ __align__(16) __nv_bfloat16 As[2][128*40];
    __shared__ __align__(16) __nv_bfloat16 Bs[2][128*40];

    int tid = threadIdx.x;
    int warp = tid >> 5, lane = tid & 31;
    int g = lane >> 2, tig = lane & 3;
    int wm = warp >> 2, wn = warp & 3;
    int r8 = lane & 7, grp = lane >> 3;

    float acc[4][4][4];
    #pragma unroll
    for(int i=0;i<4;i++) for(int j=0;j<4;j++) for(int q=0;q<4;q++) acc[i][j][q]=0.f;

    int lr = tid >> 2, lc = tid & 3;
    const __half* Lg0 = LKb + (size_t)(m0+lr)*LA + lc*8;
    const __half* Lg1 = LKb + (size_t)(m0+lr+64)*LA + lc*8;
    const __nv_bfloat16* Bg0 = Bb + (size_t)(n0+lr)*LA + lc*8;
    const __nv_bfloat16* Bg1 = Bb + (size_t)(n0+lr+64)*LA + lc*8;
    float lur0 = lub[m0+lr], lur1 = lub[m0+lr+64];

    uint4 ra0 = *(const uint4*)(Lg0), ra1 = *(const uint4*)(Lg1);
    uint4 pb0 = *(const uint4*)(Bg0), pb1 = *(const uint4*)(Bg1);

    {
        const __half* hp0 = (const __half*)&ra0;
        const __half* hp1 = (const __half*)&ra1;
        uint4 o0, o1;
        __nv_bfloat16* ob0 = (__nv_bfloat16*)&o0;
        __nv_bfloat16* ob1 = (__nv_bfloat16*)&o1;
        #pragma unroll
        for (int j=0;j<8;j++){
            float lvj = lvb[lc*8 + j];
            float p0 = __expf(__half2float(hp0[j]) + lur0 + lvj);
            float p1 = __expf(__half2float(hp1[j]) + lur1 + lvj);
            if (isinf(p0)) p0 = 1.f;
            if (isinf(p1)) p1 = 1.f;
            ob0[j] = __float2bfloat16(p0);
            ob1[j] = __float2bfloat16(p1);
        }
        *(uint4*)(As[0] + lr*40 + lc*8)      = o0;
        *(uint4*)(As[0] + (lr+64)*40 + lc*8) = o1;
        *(uint4*)(Bs[0] + lr*40 + lc*8)      = pb0;
        *(uint4*)(Bs[0] + (lr+64)*40 + lc*8) = pb1;
    }
    __syncthreads();

    for (int k0 = 0; k0 < LA; k0 += 32){
        int cur = (k0 >> 5) & 1;
        bool more = (k0 + 32 < LA);
        if (more){
            ra0 = *(const uint4*)(Lg0 + k0+32);
            ra1 = *(const uint4*)(Lg1 + k0+32);
            pb0 = *(const uint4*)(Bg0 + k0+32);
            pb1 = *(const uint4*)(Bg1 + k0+32);
        }
        #pragma unroll
        for (int kk2=0; kk2<2; kk2++){
            unsigned a[4][4], bf[4][2];
            #pragma unroll
            for (int mt=0; mt<4; mt++){
                int mrow = wm*64 + mt*16 + (grp&1)*8 + r8;
                unsigned ad = sptr(As[cur] + mrow*40 + kk2*16 + (grp>>1)*8);
                ldmx4(a[mt][0], a[mt][1], a[mt][2], a[mt][3], ad);
            }
            #pragma unroll
            for (int p=0; p<2; p++){
                int nrow = wn*32 + (p*2 + (grp>>1))*8 + r8;
                unsigned ad = sptr(Bs[cur] + nrow*40 + kk2*16 + (grp&1)*8);
                ldmx4(bf[p*2][0], bf[p*2][1], bf[p*2+1][0], bf[p*2+1][1], ad);
            }
            #pragma unroll
            for (int mt=0; mt<4; mt++)
                #pragma unroll
                for (int nt=0; nt<4; nt++)
                    mma_bf16(acc[mt][nt], a[mt], bf[nt]);
        }
        if (more){
            int nxt = cur ^ 1;
            const __half* hp0 = (const __half*)&ra0;
            const __half* hp1 = (const __half*)&ra1;
            uint4 o0, o1;
            __nv_bfloat16* ob0 = (__nv_bfloat16*)&o0;
            __nv_bfloat16* ob1 = (__nv_bfloat16*)&o1;
            #pragma unroll
            for (int j=0;j<8;j++){
                float lvj = lvb[k0+32 + lc*8 + j];
                float p0 = __expf(__half2float(hp0[j]) + lur0 + lvj);
                float p1 = __expf(__half2float(hp1[j]) + lur1 + lvj);
                if (isinf(p0)) p0 = 1.f;
                if (isinf(p1)) p1 = 1.f;
                ob0[j] = __float2bfloat16(p0);
                ob1[j] = __float2bfloat16(p1);
            }
            *(uint4*)(As[nxt] + lr*40 + lc*8)      = o0;
            *(uint4*)(As[nxt] + (lr+64)*40 + lc*8) = o1;
            *(uint4*)(Bs[nxt] + lr*40 + lc*8)      = pb0;
            *(uint4*)(Bs[nxt] + (lr+64)*40 + lc*8) = pb1;
        }
        __syncthreads();
    }
    #pragma unroll
    for (int mt=0; mt<4; mt++){
        int r = m0 + wm*64 + mt*16 + g;
        float ps0 = 0.f, ps1 = 0.f;
        #pragma unroll
        for (int nt=0; nt<4; nt++){
            int c = n0 + wn*32 + nt*8 + tig*2;
            float2 t0 = *(const float2*)(Tpb + (size_t)r*Dm + c);
            float2 t1 = *(const float2*)(Tpb + (size_t)(r+8)*Dm + c);
            ps0 += t0.x*acc[mt][nt][0] + t0.y*acc[mt][nt][1];
            ps1 += t1.x*acc[mt][nt][2] + t1.y*acc[mt][nt][3];
            *(float2*)(Rb + (size_t)r*Dm + c) =
                make_float2(fabsf(t0.x-acc[mt][nt][0]), fabsf(t0.y-acc[mt][nt][1]));
            *(float2*)(Rb + (size_t)(r+8)*Dm + c) =
                make_float2(fabsf(t1.x-acc[mt][nt][2]), fabsf(t1.y-acc[mt][nt][3]));
        }
        ps0 += __shfl_xor_sync(0xffffffffu, ps0, 1);
        ps0 += __shfl_xor_sync(0xffffffffu, ps0, 2);
        ps1 += __shfl_xor_sync(0xffffffffu, ps1, 1);
        ps1 += __shfl_xor_sync(0xffffffffu, ps1, 2);
        if (tig == 0){
            atomicAdd(&Sb[r], ps0);
            atomicAdd(&Sb[r+8], ps1);
        }
    }
}

// ---------------- Sinkhorn: row LSE -> lu (warp per row, shuffle-only, MLP=8) ----------------
__global__ __launch_bounds__(256) void sink_row(const __half* __restrict__ logK,
        const float* __restrict__ lv, float* __restrict__ lu){
    int b = blockIdx.y;
    int m = blockIdx.x*8 + (threadIdx.x >> 5);
    int lane = threadIdx.x & 31;
    const uint4* row = (const uint4*)(logK + ((size_t)b*LT + m)*LA);
    const float4* lv4 = (const float4*)(lv + (size_t)b*LA);
    uint4 raw[8];
    #pragma unroll
    for (int i=0;i<8;i++) raw[i] = row[lane + 32*i];
    float mx = -INFINITY;
    #pragma unroll
    for (int i=0;i<8;i++){
        const __half* hp = (const __half*)&raw[i];
        float4 l0 = lv4[(lane + 32*i)*2];
        float4 l1 = lv4[(lane + 32*i)*2 + 1];
        mx = fmaxf(mx, __half2float(hp[0])+l0.x);
        mx = fmaxf(mx, __half2float(hp[1])+l0.y);
        mx = fmaxf(mx, __half2float(hp[2])+l0.z);
        mx = fmaxf(mx, __half2float(hp[3])+l0.w);
        mx = fmaxf(mx, __half2float(hp[4])+l1.x);
        mx = fmaxf(mx, __half2float(hp[5])+l1.y);
        mx = fmaxf(mx, __half2float(hp[6])+l1.z);
        mx = fmaxf(mx, __half2float(hp[7])+l1.w);
    }
    mx = warpReduceMax(mx);
    float s = 0.f;
    #pragma unroll
    for (int i=0;i<8;i++){
        const __half* hp = (const __half*)&raw[i];
        float4 l0 = lv4[(lane + 32*i)*2];
        float4 l1 = lv4[(lane + 32*i)*2 + 1];
        s += __expf(__half2float(hp[0])+l0.x - mx);
        s += __expf(__half2float(hp[1])+l0.y - mx);
        s += __expf(__half2float(hp[2])+l0.z - mx);
        s += __expf(__half2float(hp[3])+l0.w - mx);
        s += __expf(__half2float(hp[4])+l1.x - mx);
        s += __expf(__half2float(hp[5])+l1.y - mx);
        s += __expf(__half2float(hp[6])+l1.z - mx);
        s += __expf(__half2float(hp[7])+l1.w - mx);
    }
    s = warpReduceSum(s);
    if (lane==0){
        const float LOG_MU = -6.93147180559945f;
        lu[(size_t)b*LT + m] = clip_nan(LOG_MU - (mx + __logf(s)));
    }
}

// ---------------- Sinkhorn: column LSE -> lv (8x row unroll) ----------------
__global__ void sink_col(const __half* __restrict__ logK,
        const float* __restrict__ lu, float* __restrict__ lv){
    int b = blockIdx.y;
    int tx = threadIdx.x, ty = threadIdx.y;
    int c2 = blockIdx.x*32 + tx;
    const __half2* base = (const __half2*)(logK + (size_t)b*LT*LA);
    const float* lub  = lu + (size_t)b*LT;
    float mx0=-INFINITY, s0=0.f, mx1=-INFINITY, s1=0.f;
    for (int m = ty; m < LT; m += 64){
        __half2 h[8];
        float l[8];
        #pragma unroll
        for (int i=0;i<8;i++){
            h[i] = base[(size_t)(m+8*i)*(LA/2) + c2];
            l[i] = lub[m+8*i];
        }
        #pragma unroll
        for (int i=0;i<8;i++){
            float2 f = __half22float2(h[i]);
            float v0 = f.x + l[i], v1 = f.y + l[i];
            if (v0 > mx0){ s0 = s0*__expf(mx0-v0) + 1.f; mx0 = v0; } else s0 += __expf(v0-mx0);
            if (v1 > mx1){ s1 = s1*__expf(mx1-v1) + 1.f; mx1 = v1; } else s1 += __expf(v1-mx1);
        }
    }
    __shared__ float smx[8][64], ss[8][64];
    smx[ty][tx*2]=mx0; ss[ty][tx*2]=s0;
    smx[ty][tx*2+1]=mx1; ss[ty][tx*2+1]=s1;
    __syncthreads();
    for (int off=4; off>=1; off>>=1){
        if (ty < off){
            #pragma unroll
            for (int w=0; w<2; w++){
                int cc = tx*2+w;
                float m1=smx[ty][cc], sa=ss[ty][cc];
                float m2=smx[ty+off][cc], sb=ss[ty+off][cc];
                float M = fmaxf(m1,m2);
                float Sv = sa*__expf(m1-M) + sb*__expf(m2-M);
                smx[ty][cc]=M; ss[ty][cc]=Sv;
            }
        }
        __syncthreads();
    }
    if (ty==0){
        const float LOG_NU = -7.62461898616078f;
        #pragma unroll
        for (int w=0; w<2; w++){
            int cc = tx*2+w;
            lv[(size_t)b*LA + c2*2 + w] = clip_nan(LOG_NU - (smx[0][cc] + __logf(ss[0][cc])));
        }
    }
}

// ---------------- multi-scale conv (one kernel, block-level dispatch) ----------------
template<int KSZ>
__device__ __forceinline__ void conv_body(const float* __restrict__ h,
        const float* __restrict__ w, const float* __restrict__ conv_b,
        float* __restrict__ h2, int e, float (*hs)[64], float* ws)
{
    const int pad = (KSZ-1)/2;
    int tile = blockIdx.x*64;
    int l0 = tile & (LT-1);
    int tid = threadIdx.x;
    for (int idx = tid; idx < 68*64; idx += 256){
        int lr = idx >> 6; int i = idx & 63;
        int l = l0 + lr - 2;
        float v = 0.f;
        if (l >= 0 && l < LT) v = h[(size_t)(tile - l0 + l)*(NE*Rr) + e*Rr + i];
        hs[lr][i] = v;
    }
    float acc[16];
    #pragma unroll
    for (int j=0;j<16;j++) acc[j]=0.f;
    int o = tid & 63;
    int lg = tid >> 6;
    for (int ic = 0; ic < Rr; ic += 16){
        __syncthreads();
        for (int idx = tid; idx < 16*KSZ*64; idx += 256){
            int oo = idx & 63; int r = idx >> 6;
            int t = r % KSZ; int ii = r / KSZ;
            ws[idx] = w[(size_t)oo*Rr*KSZ + (ic+ii)*KSZ + t];
        }
        __syncthreads();
        #pragma unroll
        for (int ii = 0; ii < 16; ii++){
            #pragma unroll
            for (int t = 0; t < KSZ; t++){
                float wv = ws[(ii*KSZ + t)*64 + o];
                int roff = 2 + t - pad;
                #pragma unroll
                for (int j = 0; j < 16; j++){
                    acc[j] += hs[lg*16 + j + roff][ic + ii] * wv;
                }
            }
        }
    }
    float bo = conv_b[e*Rr + o];
    #pragma unroll
    for (int j=0;j<16;j++){
        int l = lg*16 + j;
        h2[(size_t)(tile + l)*(NE*Rr) + e*Rr + o] = geluf(acc[j] + bo);
    }
}

__global__ __launch_bounds__(256) void conv_all(const float* __restrict__ h,
        const float* __restrict__ w1, const float* __restrict__ w3,
        const float* __restrict__ w5, const float* __restrict__ conv_b,
        float* __restrict__ h2)
{
    __shared__ float hs[68][64];
    __shared__ float ws[16*5*64];
    int e = blockIdx.y;
    if (e == 0)      conv_body<1>(h, w1, conv_b, h2, 0, hs, ws);
    else if (e == 1) conv_body<3>(h, w3, conv_b, h2, 1, hs, ws);
    else             conv_body<5>(h, w5, conv_b, h2, 2, hs, ws);
}

// ---------------- final (warp per row): router softmax + gated sum of per-expert LN ----------------
__global__ __launch_bounds__(256) void final_kernel(const __nv_bfloat16* __restrict__ u,
        const float* __restrict__ resid, const float* __restrict__ h1,
        const float* __restrict__ Wr2, const float* __restrict__ br2,
        const float* __restrict__ en_g, const float* __restrict__ en_b,
        float* __restrict__ out)
{
    size_t row = (size_t)blockIdx.x*8 + (threadIdx.x >> 5);
    int lane = threadIdx.x & 31;
    // router: logits from h1 row, softmax (all lanes redundantly)
    const float* hr = h1 + row*Dm;
    float4 hv1 = *(const float4*)(hr + lane*4);
    float4 hv2 = *(const float4*)(hr + 128 + lane*4);
    float gwv[3];
    {
        float l[3];
        #pragma unroll
        for (int e=0;e<3;e++){
            const float* w = Wr2 + e*Dm;
            float4 w1 = *(const float4*)(w + lane*4);
            float4 w2 = *(const float4*)(w + 128 + lane*4);
            float s = hv1.x*w1.x+hv1.y*w1.y+hv1.z*w1.z+hv1.w*w1.w
                    + hv2.x*w2.x+hv2.y*w2.y+hv2.z*w2.z+hv2.w*w2.w;
            l[e] = warpReduceSum(s);
        }
        float a0=l[0]+br2[0], a1=l[1]+br2[1], a2=l[2]+br2[2];
        float m = fmaxf(a0, fmaxf(a1,a2));
        float e0=__expf(a0-m), e1=__expf(a1-m), e2=__expf(a2-m);
        float inv = 1.f/(e0+e1+e2);
        gwv[0]=e0*inv; gwv[1]=e1*inv; gwv[2]=e2*inv;
    }
    const float* rr = resid + row*Dm;
    float4 r1 = *(const float4*)(rr + lane*4);
    float4 r2 = *(const float4*)(rr + 128 + lane*4);
    float4 o1 = make_float4(0,0,0,0), o2 = make_float4(0,0,0,0);
    #pragma unroll
    for (int e=0;e<3;e++){
        const __nv_bfloat16* ur = u + ((size_t)e*ROWS_T + row)*Dm;
        uint2 up1 = *(const uint2*)(ur + lane*4);
        uint2 up2 = *(const uint2*)(ur + 128 + lane*4);
        float2 ua = __bfloat1622float2(*(__nv_bfloat162*)&up1.x);
        float2 ub = __bfloat1622float2(*(__nv_bfloat162*)&up1.y);
        float2 uc = __bfloat1622float2(*(__nv_bfloat162*)&up2.x);
        float2 ud = __bfloat1622float2(*(__nv_bfloat162*)&up2.y);
        float y0=ua.x+r1.x, y1=ua.y+r1.y, y2=ub.x+r1.z, y3=ub.y+r1.w;
        float z0=uc.x+r2.x, z1=uc.y+r2.y, z2=ud.x+r2.z, z3=ud.y+r2.w;
        float mean = warpReduceSum(y0+y1+y2+y3+z0+z1+z2+z3) * (1.f/Dm);
        y0-=mean;y1-=mean;y2-=mean;y3-=mean;z0-=mean;z1-=mean;z2-=mean;z3-=mean;
        float var = warpReduceSum(y0*y0+y1*y1+y2*y2+y3*y3+z0*z0+z1*z1+z2*z2+z3*z3) * (1.f/Dm);
        float rstd = rsqrtf(var + 1e-5f);
        float gw = gwv[e];
        const float* eg = en_g + e*Dm;
        const float* eb = en_b + e*Dm;
        float4 g1 = *(const float4*)(eg + lane*4);
        float4 g2 = *(const float4*)(eg + 128 + lane*4);
        float4 b1 = *(const float4*)(eb + lane*4);
        float4 b2 = *(const float4*)(eb + 128 + lane*4);
        o1.x += gw*(y0*rstd*g1.x + b1.x); o1.y += gw*(y1*rstd*g1.y + b1.y);
        o1.z += gw*(y2*rstd*g1.z + b1.z); o1.w += gw*(y3*rstd*g1.w + b1.w);
        o2.x += gw*(z0*rstd*g2.x + b2.x); o2.y += gw*(z1*rstd*g2.y + b2.y);
        o2.z += gw*(z2*rstd*g2.z + b2.z); o2.w += gw*(z3*rstd*g2.w + b2.w);
    }
    float* orow = out + row*Dm;
    *(float4*)(orow + lane*4) = o1;
    *(float4*)(orow + 128 + lane*4) = o2;
}

// ---------------- host launcher ----------------
extern "C" void kernel_launch(void* const* d_in, const int* in_sizes, int n_in,
                              void* d_out, int out_size)
{
    const float* text   = (const float*)d_in[0];
    const float* audio  = (const float*)d_in[1];
    const float* ln_g   = (const float*)d_in[2];
    const float* ln_b   = (const float*)d_in[3];
    const float* W_sh   = (const float*)d_in[4];
    const float* b_sh   = (const float*)d_in[5];
    const float* Wr1    = (const float*)d_in[6];
    const float* br1    = (const float*)d_in[7];
    const float* Wr2    = (const float*)d_in[8];
    const float* br2    = (const float*)d_in[9];
    const float* down_W = (const float*)d_in[10];
    const float* down_b = (const float*)d_in[11];
    const float* conv_w1= (const float*)d_in[12];
    const float* conv_w3= (const float*)d_in[13];
    const float* conv_w5= (const float*)d_in[14];
    const float* conv_b = (const float*)d_in[15];
    const float* up_W   = (const float*)d_in[16];
    const float* up_b   = (const float*)d_in[17];
    const float* en_g   = (const float*)d_in[18];
    const float* en_b   = (const float*)d_in[19];
    float* out = (float*)d_out;

    void *p;
    cudaGetSymbolAddress(&p, g_stats); float2* stats = (float2*)p;
    cudaGetSymbolAddress(&p, g_Tp);   float* Tp  = (float*)p;
    cudaGetSymbolAddress(&p, g_Ap);   float* Ap  = (float*)p;
    cudaGetSymbolAddress(&p, g_Tn);   __nv_bfloat16* Tn = (__nv_bfloat16*)p;
    cudaGetSymbolAddress(&p, g_An);   __nv_bfloat16* An = (__nv_bfloat16*)p;
    cudaGetSymbolAddress(&p, g_ApT);  __nv_bfloat16* ApT = (__nv_bfloat16*)p;
    cudaGetSymbolAddress(&p, g_logK); __half* logK = (__half*)p;
    cudaGetSymbolAddress(&p, g_lu);   float* lu = (float*)p;
    cudaGetSymbolAddress(&p, g_lv);   float* lv = (float*)p;
    cudaGetSymbolAddress(&p, g_S);    float* S = (float*)p;
    cudaGetSymbolAddress(&p, g_resid);float* resid = (float*)p;
    cudaGetSymbolAddress(&p, g_h1);   float* h1 = (float*)p;
    cudaGetSymbolAddress(&p, g_h);    float* h = (float*)p;
    cudaGetSymbolAddress(&p, g_h2);   float* h2 = (float*)p;
    cudaGetSymbolAddress(&p, g_u);    __nv_bfloat16* u = (__nv_bfloat16*)p;

    // LN stats + zero lu/lv/S (fused)
    ln_stats<<<(ROWS_T + ROWS_A)/8, 256>>>(text, audio, stats, lu, lv, S);

    // text+audio projections with fused LN in ONE launch
    gemm_tf32<0,true,false><<<dim3((ROWS_T+ROWS_A)/128, Dm/64, 1),256>>>(
            text, Dm, 0, W_sh, Dm, 0, Tp, Dm, 0, Dm, b_sh, 0,
            stats, ln_g, ln_b, nullptr, nullptr, 0,
            audio, Ap, stats + ROWS_T, ROWS_T/128);

    // normalization: audio transpose + text rows in ONE launch
    norm_combined<<<3072, 256>>>(Ap, An, ApT, Tp, Tn);

    // cost -> logK (fp16) via bf16 tensor cores (double-buffered)
    cost_mma<<<dim3(LT/128, LA/128, Bt),256>>>(Tn, An, logK);

    // Sinkhorn (fp16 logK, L2-resident)
    for (int it=0; it<10; ++it){
        sink_row<<<dim3(LT/8, Bt),256>>>(logK, lv, lu);
        sink_col<<<dim3(LA/64, Bt), dim3(32,8)>>>(logK, lu, lv);
    }

    // pi GEMM with fused resid/S epilogue (double-buffered)
    pi_mma<<<dim3(LT/128, Dm/128, Bt),256>>>(logK, lu, lv, ApT, Tp, S, resid);

    // router hidden + down projection in ONE launch
    gemm_dual<<<dim3(ROWS_T/128, 7, 1),256>>>(resid, Wr1+1, br1, S, Wr1, h1,
            down_W, down_b, h);

    // experts
    conv_all<<<dim3(ROWS_T/64, NE),256>>>(h, conv_w1, conv_w3, conv_w5, conv_b, h2);
    gemm_tf32<0,false,true><<<dim3(ROWS_T/128, Dm/64, NE),256>>>(h2, NE*Rr, (long long)Rr,
            up_W, Rr, (long long)Dm*Rr, u, Dm, (long long)ROWS_T*Dm,
            Rr, up_b, Dm, nullptr, nullptr, nullptr, nullptr, nullptr, 0,
            nullptr, nullptr, nullptr, 1<<30);

    // final: router softmax + gated per-expert LN (fused)
    final_kernel<<<ROWS_T/8,256>>>(u, resid, h1, Wr2, br2, en_g, en_b, out);
}